// round 1
// baseline (speedup 1.0000x reference)
#include <cuda_runtime.h>
#include <math.h>

#define B_  8
#define S_  2048
#define D_  1024
#define H_  16
#define DK_ 64
#define M_  (B_*S_)   // 16384

// ---------------- scratch (device globals: allocation-free) ----------------
__device__ float g_q [M_ * D_];
__device__ float g_k [M_ * D_];
__device__ float g_v [M_ * D_];
__device__ float g_ao[M_ * D_];
__device__ float g_wq[D_ * D_];
__device__ float g_wk[D_ * D_];
__device__ float g_wv[D_ * D_];
__device__ float g_wo[D_ * D_];   // Wo transposed to [K][N]

// ---------------- weight rearrange ----------------
// Wq/Wk/Wv: [H, D, DK] -> W'[d][h*DK+dk]   (so projection is one big GEMM)
// Wo: [out, in] -> WoT[in][out]
__global__ void rearrange_w(const float* __restrict__ Wq,
                            const float* __restrict__ Wk,
                            const float* __restrict__ Wv,
                            const float* __restrict__ Wo) {
    int idx = blockIdx.x * blockDim.x + threadIdx.x;
    if (idx >= D_ * D_) return;
    int d = idx / D_;        // k-dim row
    int n = idx % D_;        // output col
    int h  = n >> 6;
    int dk = n & 63;
    int src = (h * D_ + d) * DK_ + dk;
    g_wq[idx] = Wq[src];
    g_wk[idx] = Wk[src];
    g_wv[idx] = Wv[src];
    g_wo[idx] = Wo[(size_t)n * D_ + d];
}

// ---------------- SGEMM NN: C[M,N] = A[M,K] * B[K,N] ----------------
// 128x128 block tile, BK=8, 256 threads, 8x8 register tile.
__global__ __launch_bounds__(256)
void sgemm_nn(const float* __restrict__ A, const float* __restrict__ Bm,
              float* __restrict__ C, int M, int N, int K) {
    __shared__ float As[8][128];
    __shared__ float Bs[8][128];

    int tid = threadIdx.x;
    int bm = blockIdx.y * 128;
    int bn = blockIdx.x * 128;
    int tm = (tid >> 4) * 8;   // 0..120
    int tn = (tid & 15) * 8;   // 0..120

    float acc[8][8] = {};

    for (int k0 = 0; k0 < K; k0 += 8) {
        // A tile: 128 rows x 8 cols -> transposed store As[k][m]
        {
            int r = tid >> 1;           // 0..127
            int c = (tid & 1) * 4;      // 0 or 4
            const float4 a4 = *(const float4*)(A + (size_t)(bm + r) * K + k0 + c);
            As[c + 0][r] = a4.x;
            As[c + 1][r] = a4.y;
            As[c + 2][r] = a4.z;
            As[c + 3][r] = a4.w;
        }
        // B tile: 8 rows x 128 cols, direct
        {
            int r = tid >> 5;           // 0..7
            int c = (tid & 31) * 4;     // 0..124
            *(float4*)(&Bs[r][c]) = *(const float4*)(Bm + (size_t)(k0 + r) * N + bn + c);
        }
        __syncthreads();

        #pragma unroll
        for (int k = 0; k < 8; ++k) {
            float4 a0 = *(float4*)(&As[k][tm]);
            float4 a1 = *(float4*)(&As[k][tm + 4]);
            float4 b0 = *(float4*)(&Bs[k][tn]);
            float4 b1 = *(float4*)(&Bs[k][tn + 4]);
            float ra[8] = {a0.x, a0.y, a0.z, a0.w, a1.x, a1.y, a1.z, a1.w};
            float rb[8] = {b0.x, b0.y, b0.z, b0.w, b1.x, b1.y, b1.z, b1.w};
            #pragma unroll
            for (int i = 0; i < 8; ++i)
                #pragma unroll
                for (int j = 0; j < 8; ++j)
                    acc[i][j] += ra[i] * rb[j];
        }
        __syncthreads();
    }

    #pragma unroll
    for (int i = 0; i < 8; ++i) {
        #pragma unroll
        for (int j = 0; j < 8; j += 4) {
            float4 v = make_float4(acc[i][j], acc[i][j+1], acc[i][j+2], acc[i][j+3]);
            *(float4*)(C + (size_t)(bm + tm + i) * N + bn + tn + j) = v;
        }
    }
}

// ---------------- flash attention (fp32) ----------------
// grid: (S/64, B*H). block: 256 threads. BM=BN=64, DK=64.
// smem tiles padded to stride 65 to avoid bank conflicts.
#define LDP 65

__global__ __launch_bounds__(256)
void flash_attn(const float* __restrict__ gq, const float* __restrict__ gk,
                const float* __restrict__ gv, float* __restrict__ gao) {
    extern __shared__ float sm[];
    float* Qs = sm;                  // [64][LDP]
    float* Ks = Qs + 64 * LDP;
    float* Vs = Ks + 64 * LDP;
    float* Ps = Vs + 64 * LDP;       // [64][LDP]
    float* rowm = Ps + 64 * LDP;     // [64]
    float* rowl = rowm + 64;
    float* rowc = rowl + 64;

    int tid = threadIdx.x;
    int bh  = blockIdx.y;
    int b = bh / H_, h = bh % H_;
    int s0 = blockIdx.x * 64;

    const float* qb = gq + (size_t)(b * S_) * D_ + h * DK_;
    const float* kb = gk + (size_t)(b * S_) * D_ + h * DK_;
    const float* vb = gv + (size_t)(b * S_) * D_ + h * DK_;

    // load Q tile
    for (int idx = tid; idx < 64 * 64; idx += 256) {
        int r = idx >> 6, c = idx & 63;
        Qs[r * LDP + c] = qb[(size_t)(s0 + r) * D_ + c];
    }
    if (tid < 64) { rowm[tid] = -1e30f; rowl[tid] = 0.0f; }

    int ty = tid >> 4;   // 0..15
    int tx = tid & 15;   // 0..15
    float Oacc[4][4] = {};
    const float scale = 0.03125f;  // d_model^-0.5 = 1/32

    for (int t0 = 0; t0 < S_; t0 += 64) {
        __syncthreads();  // protect Ks/Vs from previous iter's PV reads
        for (int idx = tid; idx < 64 * 64; idx += 256) {
            int r = idx >> 6, c = idx & 63;
            Ks[r * LDP + c] = kb[(size_t)(t0 + r) * D_ + c];
            Vs[r * LDP + c] = vb[(size_t)(t0 + r) * D_ + c];
        }
        __syncthreads();

        // S = Q K^T * scale  (64x64x64)
        float sacc[4][4] = {};
        #pragma unroll 8
        for (int k = 0; k < 64; ++k) {
            float ra[4], rb[4];
            #pragma unroll
            for (int i = 0; i < 4; ++i) ra[i] = Qs[(ty * 4 + i) * LDP + k];
            #pragma unroll
            for (int j = 0; j < 4; ++j) rb[j] = Ks[(tx * 4 + j) * LDP + k];
            #pragma unroll
            for (int i = 0; i < 4; ++i)
                #pragma unroll
                for (int j = 0; j < 4; ++j)
                    sacc[i][j] += ra[i] * rb[j];
        }
        #pragma unroll
        for (int i = 0; i < 4; ++i)
            #pragma unroll
            for (int j = 0; j < 4; ++j)
                Ps[(ty * 4 + i) * LDP + tx * 4 + j] = sacc[i][j] * scale;
        __syncthreads();

        // online softmax: 4 threads per row (16 cols each)
        {
            int row = tid >> 2;
            int q4  = tid & 3;
            float mx = -1e30f;
            #pragma unroll
            for (int j = q4 * 16; j < q4 * 16 + 16; ++j)
                mx = fmaxf(mx, Ps[row * LDP + j]);
            mx = fmaxf(mx, __shfl_xor_sync(0xffffffffu, mx, 1));
            mx = fmaxf(mx, __shfl_xor_sync(0xffffffffu, mx, 2));
            float mold = rowm[row];
            float mnew = fmaxf(mold, mx);
            float s = 0.0f;
            #pragma unroll
            for (int j = q4 * 16; j < q4 * 16 + 16; ++j) {
                float e = __expf(Ps[row * LDP + j] - mnew);
                Ps[row * LDP + j] = e;
                s += e;
            }
            s += __shfl_xor_sync(0xffffffffu, s, 1);
            s += __shfl_xor_sync(0xffffffffu, s, 2);
            if (q4 == 0) {
                float c = __expf(mold - mnew);
                rowc[row] = c;
                rowm[row] = mnew;
                rowl[row] = rowl[row] * c + s;
            }
        }
        __syncthreads();

        // rescale O, then O += P V   (64x64x64)
        float cs[4];
        #pragma unroll
        for (int i = 0; i < 4; ++i) cs[i] = rowc[ty * 4 + i];
        #pragma unroll
        for (int i = 0; i < 4; ++i)
            #pragma unroll
            for (int k = 0; k < 4; ++k)
                Oacc[i][k] *= cs[i];

        #pragma unroll 8
        for (int j = 0; j < 64; ++j) {
            float rp[4], rv[4];
            #pragma unroll
            for (int i = 0; i < 4; ++i) rp[i] = Ps[(ty * 4 + i) * LDP + j];
            #pragma unroll
            for (int k = 0; k < 4; ++k) rv[k] = Vs[j * LDP + tx * 4 + k];
            #pragma unroll
            for (int i = 0; i < 4; ++i)
                #pragma unroll
                for (int k = 0; k < 4; ++k)
                    Oacc[i][k] += rp[i] * rv[k];
        }
    }
    __syncthreads();

    float invl[4];
    #pragma unroll
    for (int i = 0; i < 4; ++i) invl[i] = 1.0f / rowl[ty * 4 + i];
    float* aob = gao + (size_t)(b * S_) * D_ + h * DK_;
    #pragma unroll
    for (int i = 0; i < 4; ++i)
        #pragma unroll
        for (int k = 0; k < 4; ++k)
            aob[(size_t)(s0 + ty * 4 + i) * D_ + tx * 4 + k] = Oacc[i][k] * invl[i];
}

// ---------------- launch ----------------
extern "C" void kernel_launch(void* const* d_in, const int* in_sizes, int n_in,
                              void* d_out, int out_size) {
    const float* query = (const float*)d_in[0];
    const float* key   = (const float*)d_in[1];
    const float* value = (const float*)d_in[2];
    const float* Wq    = (const float*)d_in[3];
    const float* Wk    = (const float*)d_in[4];
    const float* Wv    = (const float*)d_in[5];
    const float* Wo    = (const float*)d_in[6];
    float* out = (float*)d_out;

    float *gq, *gk, *gv, *gao, *wq, *wk, *wv, *wo;
    cudaGetSymbolAddress((void**)&gq,  g_q);
    cudaGetSymbolAddress((void**)&gk,  g_k);
    cudaGetSymbolAddress((void**)&gv,  g_v);
    cudaGetSymbolAddress((void**)&gao, g_ao);
    cudaGetSymbolAddress((void**)&wq,  g_wq);
    cudaGetSymbolAddress((void**)&wk,  g_wk);
    cudaGetSymbolAddress((void**)&wv,  g_wv);
    cudaGetSymbolAddress((void**)&wo,  g_wo);

    // 1) weight rearrange
    rearrange_w<<<(D_ * D_ + 255) / 256, 256>>>(Wq, Wk, Wv, Wo);

    // 2) projections: [16384,1024] @ [1024,1024]
    dim3 ggrid(D_ / 128, M_ / 128);
    sgemm_nn<<<ggrid, 256>>>(query, wq, gq, M_, D_, D_);
    sgemm_nn<<<ggrid, 256>>>(key,   wk, gk, M_, D_, D_);
    sgemm_nn<<<ggrid, 256>>>(value, wv, gv, M_, D_, D_);

    // 3) flash attention
    size_t smem = (size_t)(4 * 64 * LDP + 3 * 64) * sizeof(float);
    cudaFuncSetAttribute(flash_attn, cudaFuncAttributeMaxDynamicSharedMemorySize, (int)smem);
    dim3 fgrid(S_ / 64, B_ * H_);
    flash_attn<<<fgrid, 256, smem>>>(gq, gk, gv, gao);

    // 4) output projection: ao @ Wo^T  (via pre-transposed WoT, NN GEMM)
    sgemm_nn<<<ggrid, 256>>>(gao, wo, out, M_, D_, D_);
}

// round 3
// speedup vs baseline: 1.3748x; 1.3748x over previous
#include <cuda_runtime.h>
#include <cuda_bf16.h>
#include <stdint.h>
#include <math.h>

#define B_  8
#define S_  2048
#define D_  1024
#define H_  16
#define DK_ 64
#define M_  (B_*S_)   // 16384

// ---------------- scratch (device globals: allocation-free) ----------------
__device__ float g_q [M_ * D_];
__device__ float g_k [M_ * D_];
__device__ float g_v [M_ * D_];
__device__ float g_ao[M_ * D_];
__device__ __nv_bfloat16 g_ah[M_ * D_];      // activation hi (reused across GEMMs)
__device__ __nv_bfloat16 g_al[M_ * D_];      // activation lo
__device__ __nv_bfloat16 g_wh[4 * D_ * D_];  // weights hi, [N][K] layout: q,k,v,o
__device__ __nv_bfloat16 g_wl[4 * D_ * D_];  // weights lo

// ---------------- helpers ----------------
__device__ __forceinline__ uint32_t smem_u32(const void* p) {
    return (uint32_t)__cvta_generic_to_shared(p);
}
__device__ __forceinline__ void cpasync16(uint32_t s, const void* g) {
    asm volatile("cp.async.cg.shared.global [%0], [%1], 16;" :: "r"(s), "l"(g));
}
__device__ __forceinline__ void cp_commit() {
    asm volatile("cp.async.commit_group;" ::: "memory");
}
template<int N> __device__ __forceinline__ void cp_wait() {
    asm volatile("cp.async.wait_group %0;" :: "n"(N) : "memory");
}
__device__ __forceinline__ void ldsm_x4(uint32_t* r, uint32_t a) {
    asm volatile("ldmatrix.sync.aligned.m8n8.x4.shared.b16 {%0,%1,%2,%3}, [%4];"
                 : "=r"(r[0]), "=r"(r[1]), "=r"(r[2]), "=r"(r[3]) : "r"(a));
}
__device__ __forceinline__ void ldsm_x2(uint32_t* r, uint32_t a) {
    asm volatile("ldmatrix.sync.aligned.m8n8.x2.shared.b16 {%0,%1}, [%2];"
                 : "=r"(r[0]), "=r"(r[1]) : "r"(a));
}
__device__ __forceinline__ void mma16816(float* d, const uint32_t* a, const uint32_t* b) {
    asm volatile(
        "mma.sync.aligned.m16n8k16.row.col.f32.bf16.bf16.f32 "
        "{%0,%1,%2,%3}, {%4,%5,%6,%7}, {%8,%9}, {%0,%1,%2,%3};"
        : "+f"(d[0]), "+f"(d[1]), "+f"(d[2]), "+f"(d[3])
        : "r"(a[0]), "r"(a[1]), "r"(a[2]), "r"(a[3]), "r"(b[0]), "r"(b[1]));
}
__device__ __forceinline__ uint32_t pk2(__nv_bfloat16 a, __nv_bfloat16 b) {
    return (uint32_t)__bfloat16_as_ushort(a) | ((uint32_t)__bfloat16_as_ushort(b) << 16);
}

// ---------------- weight rearrange + bf16 split ----------------
// Wq/Wk/Wv [H,D,DK] -> W'[n][k] (n = h*64+dk), Wo [out,in] -> direct [n][k].
__global__ void rearrange_w(const float* __restrict__ Wq, const float* __restrict__ Wk,
                            const float* __restrict__ Wv, const float* __restrict__ Wo) {
    int idx = blockIdx.x * blockDim.x + threadIdx.x;
    if (idx >= D_ * D_) return;
    int n = idx / D_;
    int k = idx % D_;
    int h = n >> 6, dk = n & 63;
    float w[4];
    w[0] = Wq[((size_t)h * D_ + k) * DK_ + dk];
    w[1] = Wk[((size_t)h * D_ + k) * DK_ + dk];
    w[2] = Wv[((size_t)h * D_ + k) * DK_ + dk];
    w[3] = Wo[(size_t)n * D_ + k];
    #pragma unroll
    for (int j = 0; j < 4; ++j) {
        __nv_bfloat16 hi = __float2bfloat16(w[j]);
        float lo = w[j] - __bfloat162float(hi);
        g_wh[j * D_ * D_ + idx] = hi;
        g_wl[j * D_ * D_ + idx] = __float2bfloat16(lo);
    }
}

// ---------------- activation bf16 split ----------------
__global__ void split_bf16(const float* __restrict__ x,
                           __nv_bfloat16* __restrict__ hi, __nv_bfloat16* __restrict__ lo) {
    int i = blockIdx.x * blockDim.x + threadIdx.x;   // float4 index
    float4 v = ((const float4*)x)[i];
    __nv_bfloat16 h0 = __float2bfloat16(v.x), h1 = __float2bfloat16(v.y),
                  h2 = __float2bfloat16(v.z), h3 = __float2bfloat16(v.w);
    __nv_bfloat16 l0 = __float2bfloat16(v.x - __bfloat162float(h0));
    __nv_bfloat16 l1 = __float2bfloat16(v.y - __bfloat162float(h1));
    __nv_bfloat16 l2 = __float2bfloat16(v.z - __bfloat162float(h2));
    __nv_bfloat16 l3 = __float2bfloat16(v.w - __bfloat162float(h3));
    ((uint2*)hi)[i] = make_uint2(pk2(h0, h1), pk2(h2, h3));
    ((uint2*)lo)[i] = make_uint2(pk2(l0, l1), pk2(l2, l3));
}

// ---------------- mma.sync split-bf16 GEMM ----------------
// C[M,1024] = A[M,1024] * B^T, B stored [N][K] K-major (bf16 hi/lo).
// CTA 128x128, BK=32, 8 warps (warp tile 64x32), cp.async double buffer.
// Smem tile: 128 rows x 64B, XOR-swizzled 16B chunks: chunk' = chunk ^ ((row>>1)&3).
#define GBM 128
#define GBN 128
#define GBK 32
#define TILE8K 8192
#define STAGE (4 * TILE8K)   // Ah, Al, Bh, Bl
#define GEMM_SMEM (2 * STAGE)

__global__ __launch_bounds__(256, 1)
void gemm_mma(const __nv_bfloat16* __restrict__ Ah, const __nv_bfloat16* __restrict__ Al,
              const __nv_bfloat16* __restrict__ Bh, const __nv_bfloat16* __restrict__ Bl,
              float* __restrict__ C) {
    extern __shared__ char smraw[];
    const uint32_t sb = smem_u32(smraw);
    const int tid = threadIdx.x;
    const int wid = tid >> 5, lane = tid & 31;
    const int bm = blockIdx.y * GBM;
    const int bn = blockIdx.x * GBN;
    const int warp_m = (wid & 1) * 64;
    const int warp_n = (wid >> 1) * 32;

    // per-thread cp.async targets (2 chunks of the 512 per tile)
    // lin = i*256+tid: row = lin>>2 (0..127), kc = lin&3 (16B chunk)
    uint32_t soff[2];
    const __nv_bfloat16 *gA[2], *gAl[2], *gB[2], *gBl[2];
    #pragma unroll
    for (int i = 0; i < 2; ++i) {
        int lin = i * 256 + tid;
        int row = lin >> 2, kc = lin & 3;
        soff[i] = row * 64 + (((uint32_t)kc ^ ((row >> 1) & 3)) << 4);
        gA[i]  = Ah + (size_t)(bm + row) * D_ + kc * 8;
        gAl[i] = Al + (size_t)(bm + row) * D_ + kc * 8;
        gB[i]  = Bh + (size_t)(bn + row) * D_ + kc * 8;
        gBl[i] = Bl + (size_t)(bn + row) * D_ + kc * 8;
    }

    // ldmatrix source offsets (relative, swizzled)
    const int arow = warp_m + (lane & 15);
    const uint32_t aoff = arow * 64 + ((((uint32_t)lane >> 4) ^ ((arow >> 1) & 3)) << 4);
    const int brow = warp_n + (lane & 7);
    const uint32_t boff = brow * 64 + (((((uint32_t)lane >> 3) & 1) ^ ((brow >> 1) & 3)) << 4);

    float acc[4][4][4] = {};

    auto prefetch = [&](int t) {
        uint32_t stg = sb + (t & 1) * STAGE;
        int kofs = t * GBK;
        #pragma unroll
        for (int i = 0; i < 2; ++i) {
            cpasync16(stg + soff[i],              gA[i]  + kofs);
            cpasync16(stg + TILE8K + soff[i],     gAl[i] + kofs);
            cpasync16(stg + 2 * TILE8K + soff[i], gB[i]  + kofs);
            cpasync16(stg + 3 * TILE8K + soff[i], gBl[i] + kofs);
        }
    };

    prefetch(0);
    cp_commit();

    const int NT = D_ / GBK;   // 32
    for (int t = 0; t < NT; ++t) {
        uint32_t stg = sb + (t & 1) * STAGE;
        if (t + 1 < NT) { prefetch(t + 1); cp_commit(); cp_wait<1>(); }
        else           { cp_wait<0>(); }
        __syncthreads();

        #pragma unroll
        for (int kh = 0; kh < 2; ++kh) {
            uint32_t ao = aoff ^ (kh << 5);
            uint32_t bo = boff ^ (kh << 5);
            uint32_t ah4[4][4], al4[4][4], bh2[4][2], bl2[4][2];
            #pragma unroll
            for (int mb = 0; mb < 4; ++mb) {
                ldsm_x4(ah4[mb], stg + ao + mb * 1024);
                ldsm_x4(al4[mb], stg + TILE8K + ao + mb * 1024);
            }
            #pragma unroll
            for (int nb = 0; nb < 4; ++nb) {
                ldsm_x2(bh2[nb], stg + 2 * TILE8K + bo + nb * 512);
                ldsm_x2(bl2[nb], stg + 3 * TILE8K + bo + nb * 512);
            }
            #pragma unroll
            for (int mb = 0; mb < 4; ++mb)
                #pragma unroll
                for (int nb = 0; nb < 4; ++nb)
                    mma16816(acc[mb][nb], ah4[mb], bh2[nb]);
            #pragma unroll
            for (int mb = 0; mb < 4; ++mb)
                #pragma unroll
                for (int nb = 0; nb < 4; ++nb)
                    mma16816(acc[mb][nb], al4[mb], bh2[nb]);
            #pragma unroll
            for (int mb = 0; mb < 4; ++mb)
                #pragma unroll
                for (int nb = 0; nb < 4; ++nb)
                    mma16816(acc[mb][nb], ah4[mb], bl2[nb]);
        }
        __syncthreads();
    }

    // epilogue: d0,d1 -> (row lane>>2, col 2*(lane&3)); d2,d3 -> row+8
    const int tm = bm + warp_m + (lane >> 2);
    const int tn = bn + warp_n + (lane & 3) * 2;
    #pragma unroll
    for (int mb = 0; mb < 4; ++mb)
        #pragma unroll
        for (int nb = 0; nb < 4; ++nb) {
            float* c0 = C + (size_t)(tm + mb * 16) * D_ + tn + nb * 8;
            *(float2*)c0 = make_float2(acc[mb][nb][0], acc[mb][nb][1]);
            float* c1 = c0 + 8 * D_;
            *(float2*)c1 = make_float2(acc[mb][nb][2], acc[mb][nb][3]);
        }
}

// ---------------- flash attention (fp32, unchanged from R1) ----------------
#define LDP 65

__global__ __launch_bounds__(256)
void flash_attn(const float* __restrict__ gq, const float* __restrict__ gk,
                const float* __restrict__ gv, float* __restrict__ gao) {
    extern __shared__ float sm[];
    float* Qs = sm;
    float* Ks = Qs + 64 * LDP;
    float* Vs = Ks + 64 * LDP;
    float* Ps = Vs + 64 * LDP;
    float* rowm = Ps + 64 * LDP;
    float* rowl = rowm + 64;
    float* rowc = rowl + 64;

    int tid = threadIdx.x;
    int bh  = blockIdx.y;
    int b = bh / H_, h = bh % H_;
    int s0 = blockIdx.x * 64;

    const float* qb = gq + (size_t)(b * S_) * D_ + h * DK_;
    const float* kb = gk + (size_t)(b * S_) * D_ + h * DK_;
    const float* vb = gv + (size_t)(b * S_) * D_ + h * DK_;

    for (int idx = tid; idx < 64 * 64; idx += 256) {
        int r = idx >> 6, c = idx & 63;
        Qs[r * LDP + c] = qb[(size_t)(s0 + r) * D_ + c];
    }
    if (tid < 64) { rowm[tid] = -1e30f; rowl[tid] = 0.0f; }

    int ty = tid >> 4;
    int tx = tid & 15;
    float Oacc[4][4] = {};
    const float scale = 0.03125f;

    for (int t0 = 0; t0 < S_; t0 += 64) {
        __syncthreads();
        for (int idx = tid; idx < 64 * 64; idx += 256) {
            int r = idx >> 6, c = idx & 63;
            Ks[r * LDP + c] = kb[(size_t)(t0 + r) * D_ + c];
            Vs[r * LDP + c] = vb[(size_t)(t0 + r) * D_ + c];
        }
        __syncthreads();

        float sacc[4][4] = {};
        #pragma unroll 8
        for (int k = 0; k < 64; ++k) {
            float ra[4], rb[4];
            #pragma unroll
            for (int i = 0; i < 4; ++i) ra[i] = Qs[(ty * 4 + i) * LDP + k];
            #pragma unroll
            for (int j = 0; j < 4; ++j) rb[j] = Ks[(tx * 4 + j) * LDP + k];
            #pragma unroll
            for (int i = 0; i < 4; ++i)
                #pragma unroll
                for (int j = 0; j < 4; ++j)
                    sacc[i][j] += ra[i] * rb[j];
        }
        #pragma unroll
        for (int i = 0; i < 4; ++i)
            #pragma unroll
            for (int j = 0; j < 4; ++j)
                Ps[(ty * 4 + i) * LDP + tx * 4 + j] = sacc[i][j] * scale;
        __syncthreads();

        {
            int row = tid >> 2;
            int q4  = tid & 3;
            float mx = -1e30f;
            #pragma unroll
            for (int j = q4 * 16; j < q4 * 16 + 16; ++j)
                mx = fmaxf(mx, Ps[row * LDP + j]);
            mx = fmaxf(mx, __shfl_xor_sync(0xffffffffu, mx, 1));
            mx = fmaxf(mx, __shfl_xor_sync(0xffffffffu, mx, 2));
            float mold = rowm[row];
            float mnew = fmaxf(mold, mx);
            float s = 0.0f;
            #pragma unroll
            for (int j = q4 * 16; j < q4 * 16 + 16; ++j) {
                float e = __expf(Ps[row * LDP + j] - mnew);
                Ps[row * LDP + j] = e;
                s += e;
            }
            s += __shfl_xor_sync(0xffffffffu, s, 1);
            s += __shfl_xor_sync(0xffffffffu, s, 2);
            if (q4 == 0) {
                float c = __expf(mold - mnew);
                rowc[row] = c;
                rowm[row] = mnew;
                rowl[row] = rowl[row] * c + s;
            }
        }
        __syncthreads();

        float cs[4];
        #pragma unroll
        for (int i = 0; i < 4; ++i) cs[i] = rowc[ty * 4 + i];
        #pragma unroll
        for (int i = 0; i < 4; ++i)
            #pragma unroll
            for (int k = 0; k < 4; ++k)
                Oacc[i][k] *= cs[i];

        #pragma unroll 8
        for (int j = 0; j < 64; ++j) {
            float rp[4], rv[4];
            #pragma unroll
            for (int i = 0; i < 4; ++i) rp[i] = Ps[(ty * 4 + i) * LDP + j];
            #pragma unroll
            for (int k = 0; k < 4; ++k) rv[k] = Vs[j * LDP + tx * 4 + k];
            #pragma unroll
            for (int i = 0; i < 4; ++i)
                #pragma unroll
                for (int k = 0; k < 4; ++k)
                    Oacc[i][k] += rp[i] * rv[k];
        }
    }
    __syncthreads();

    float invl[4];
    #pragma unroll
    for (int i = 0; i < 4; ++i) invl[i] = 1.0f / rowl[ty * 4 + i];
    float* aob = gao + (size_t)(b * S_) * D_ + h * DK_;
    #pragma unroll
    for (int i = 0; i < 4; ++i)
        #pragma unroll
        for (int k = 0; k < 4; ++k)
            aob[(size_t)(s0 + ty * 4 + i) * D_ + tx * 4 + k] = Oacc[i][k] * invl[i];
}

// ---------------- launch ----------------
extern "C" void kernel_launch(void* const* d_in, const int* in_sizes, int n_in,
                              void* d_out, int out_size) {
    const float* query = (const float*)d_in[0];
    const float* key   = (const float*)d_in[1];
    const float* value = (const float*)d_in[2];
    const float* Wq    = (const float*)d_in[3];
    const float* Wk    = (const float*)d_in[4];
    const float* Wv    = (const float*)d_in[5];
    const float* Wo    = (const float*)d_in[6];
    float* out = (float*)d_out;

    float *gq, *gk, *gv, *gao;
    __nv_bfloat16 *ah, *al, *wh, *wl;
    cudaGetSymbolAddress((void**)&gq,  g_q);
    cudaGetSymbolAddress((void**)&gk,  g_k);
    cudaGetSymbolAddress((void**)&gv,  g_v);
    cudaGetSymbolAddress((void**)&gao, g_ao);
    cudaGetSymbolAddress((void**)&ah,  g_ah);
    cudaGetSymbolAddress((void**)&al,  g_al);
    cudaGetSymbolAddress((void**)&wh,  g_wh);
    cudaGetSymbolAddress((void**)&wl,  g_wl);

    cudaFuncSetAttribute(gemm_mma, cudaFuncAttributeMaxDynamicSharedMemorySize, GEMM_SMEM);
    size_t fsmem = (size_t)(4 * 64 * LDP + 3 * 64) * sizeof(float);
    cudaFuncSetAttribute(flash_attn, cudaFuncAttributeMaxDynamicSharedMemorySize, (int)fsmem);

    // 1) weight rearrange + split
    rearrange_w<<<(D_ * D_ + 255) / 256, 256>>>(Wq, Wk, Wv, Wo);

    dim3 ggrid(D_ / GBN, M_ / GBM);   // (8, 128)
    int splitBlocks = (M_ * D_ / 4) / 256;

    // 2) projections via tensor cores (split bf16)
    split_bf16<<<splitBlocks, 256>>>(query, ah, al);
    gemm_mma<<<ggrid, 256, GEMM_SMEM>>>(ah, al, wh + 0 * D_ * D_, wl + 0 * D_ * D_, gq);
    split_bf16<<<splitBlocks, 256>>>(key, ah, al);
    gemm_mma<<<ggrid, 256, GEMM_SMEM>>>(ah, al, wh + 1 * D_ * D_, wl + 1 * D_ * D_, gk);
    split_bf16<<<splitBlocks, 256>>>(value, ah, al);
    gemm_mma<<<ggrid, 256, GEMM_SMEM>>>(ah, al, wh + 2 * D_ * D_, wl + 2 * D_ * D_, gv);

    // 3) flash attention (fp32)
    dim3 fgrid(S_ / 64, B_ * H_);
    flash_attn<<<fgrid, 256, fsmem>>>(gq, gk, gv, gao);

    // 4) output projection
    split_bf16<<<splitBlocks, 256>>>(gao, ah, al);
    gemm_mma<<<ggrid, 256, GEMM_SMEM>>>(ah, al, wh + 3 * D_ * D_, wl + 3 * D_ * D_, out);
}

// round 4
// speedup vs baseline: 3.2637x; 2.3739x over previous
#include <cuda_runtime.h>
#include <cuda_bf16.h>
#include <stdint.h>
#include <math.h>

#define B_  8
#define S_  2048
#define D_  1024
#define H_  16
#define DK_ 64
#define M_  (B_*S_)   // 16384

// ---------------- scratch (device globals: allocation-free) ----------------
__device__ __nv_bfloat16 g_ah[M_ * D_];      // activation split hi (input to projections)
__device__ __nv_bfloat16 g_al[M_ * D_];
__device__ __nv_bfloat16 g_wh[4 * D_ * D_];  // weights hi, [N][K]: q,k,v,o
__device__ __nv_bfloat16 g_wl[4 * D_ * D_];
// head-major [b*H+h][s][dk] split activations for attention
__device__ __nv_bfloat16 g_qh[M_ * D_];
__device__ __nv_bfloat16 g_ql[M_ * D_];
__device__ __nv_bfloat16 g_kh[M_ * D_];
__device__ __nv_bfloat16 g_kl[M_ * D_];
__device__ __nv_bfloat16 g_vh[M_ * D_];
__device__ __nv_bfloat16 g_vl[M_ * D_];
// attention output, [b*S+s][D] split (feeds Wo GEMM)
__device__ __nv_bfloat16 g_aoh[M_ * D_];
__device__ __nv_bfloat16 g_aol[M_ * D_];

// ---------------- helpers ----------------
__device__ __forceinline__ uint32_t smem_u32(const void* p) {
    return (uint32_t)__cvta_generic_to_shared(p);
}
__device__ __forceinline__ void cpasync16(uint32_t s, const void* g) {
    asm volatile("cp.async.cg.shared.global [%0], [%1], 16;" :: "r"(s), "l"(g));
}
__device__ __forceinline__ void cp_commit() {
    asm volatile("cp.async.commit_group;" ::: "memory");
}
template<int N> __device__ __forceinline__ void cp_wait() {
    asm volatile("cp.async.wait_group %0;" :: "n"(N) : "memory");
}
__device__ __forceinline__ void ldsm_x4(uint32_t* r, uint32_t a) {
    asm volatile("ldmatrix.sync.aligned.m8n8.x4.shared.b16 {%0,%1,%2,%3}, [%4];"
                 : "=r"(r[0]), "=r"(r[1]), "=r"(r[2]), "=r"(r[3]) : "r"(a));
}
__device__ __forceinline__ void ldsm_x4_t(uint32_t* r, uint32_t a) {
    asm volatile("ldmatrix.sync.aligned.m8n8.x4.trans.shared.b16 {%0,%1,%2,%3}, [%4];"
                 : "=r"(r[0]), "=r"(r[1]), "=r"(r[2]), "=r"(r[3]) : "r"(a));
}
__device__ __forceinline__ void ldsm_x2(uint32_t* r, uint32_t a) {
    asm volatile("ldmatrix.sync.aligned.m8n8.x2.shared.b16 {%0,%1}, [%2];"
                 : "=r"(r[0]), "=r"(r[1]) : "r"(a));
}
__device__ __forceinline__ void mma16816(float* d, const uint32_t* a, const uint32_t* b) {
    asm volatile(
        "mma.sync.aligned.m16n8k16.row.col.f32.bf16.bf16.f32 "
        "{%0,%1,%2,%3}, {%4,%5,%6,%7}, {%8,%9}, {%0,%1,%2,%3};"
        : "+f"(d[0]), "+f"(d[1]), "+f"(d[2]), "+f"(d[3])
        : "r"(a[0]), "r"(a[1]), "r"(a[2]), "r"(a[3]), "r"(b[0]), "r"(b[1]));
}
__device__ __forceinline__ uint32_t pk2(__nv_bfloat16 a, __nv_bfloat16 b) {
    return (uint32_t)__bfloat16_as_ushort(a) | ((uint32_t)__bfloat16_as_ushort(b) << 16);
}
// split (x,y) fp32 -> packed bf16x2 hi + lo
__device__ __forceinline__ void split2(float x, float y, uint32_t& hi, uint32_t& lo) {
    __nv_bfloat162 h2 = __floats2bfloat162_rn(x, y);
    float lx = x - __bfloat162float(h2.x);
    float ly = y - __bfloat162float(h2.y);
    __nv_bfloat162 l2 = __floats2bfloat162_rn(lx, ly);
    hi = *reinterpret_cast<uint32_t*>(&h2);
    lo = *reinterpret_cast<uint32_t*>(&l2);
}

// ---------------- weight rearrange + bf16 split ----------------
__global__ void rearrange_w(const float* __restrict__ Wq, const float* __restrict__ Wk,
                            const float* __restrict__ Wv, const float* __restrict__ Wo) {
    int idx = blockIdx.x * blockDim.x + threadIdx.x;
    if (idx >= D_ * D_) return;
    int n = idx / D_;
    int k = idx % D_;
    int h = n >> 6, dk = n & 63;
    float w[4];
    w[0] = Wq[((size_t)h * D_ + k) * DK_ + dk];
    w[1] = Wk[((size_t)h * D_ + k) * DK_ + dk];
    w[2] = Wv[((size_t)h * D_ + k) * DK_ + dk];
    w[3] = Wo[(size_t)n * D_ + k];
    #pragma unroll
    for (int j = 0; j < 4; ++j) {
        __nv_bfloat16 hi = __float2bfloat16(w[j]);
        float lo = w[j] - __bfloat162float(hi);
        g_wh[j * D_ * D_ + idx] = hi;
        g_wl[j * D_ * D_ + idx] = __float2bfloat16(lo);
    }
}

// ---------------- activation bf16 split ----------------
__global__ void split_bf16(const float* __restrict__ x,
                           __nv_bfloat16* __restrict__ hi, __nv_bfloat16* __restrict__ lo) {
    int i = blockIdx.x * blockDim.x + threadIdx.x;
    float4 v = ((const float4*)x)[i];
    __nv_bfloat16 h0 = __float2bfloat16(v.x), h1 = __float2bfloat16(v.y),
                  h2 = __float2bfloat16(v.z), h3 = __float2bfloat16(v.w);
    __nv_bfloat16 l0 = __float2bfloat16(v.x - __bfloat162float(h0));
    __nv_bfloat16 l1 = __float2bfloat16(v.y - __bfloat162float(h1));
    __nv_bfloat16 l2 = __float2bfloat16(v.z - __bfloat162float(h2));
    __nv_bfloat16 l3 = __float2bfloat16(v.w - __bfloat162float(h3));
    ((uint2*)hi)[i] = make_uint2(pk2(h0, h1), pk2(h2, h3));
    ((uint2*)lo)[i] = make_uint2(pk2(l0, l1), pk2(l2, l3));
}

// ---------------- mma.sync split-bf16 GEMM ----------------
// MODE 0: plain fp32 C[row][n].  MODE 1: head-major split bf16 out with scale:
//   dst[((b*16+h)*2048+s)*64+dk], b=row>>11, s=row&2047, h=n>>6, dk=n&63.
#define GBM 128
#define GBN 128
#define GBK 32
#define TILE8K 8192
#define STAGE (4 * TILE8K)
#define GEMM_SMEM (2 * STAGE)

template<int MODE>
__global__ __launch_bounds__(256, 1)
void gemm_mma(const __nv_bfloat16* __restrict__ Ah, const __nv_bfloat16* __restrict__ Al,
              const __nv_bfloat16* __restrict__ Bh, const __nv_bfloat16* __restrict__ Bl,
              float* __restrict__ Cf,
              __nv_bfloat16* __restrict__ Chi, __nv_bfloat16* __restrict__ Clo,
              float scale) {
    extern __shared__ char smraw[];
    const uint32_t sb = smem_u32(smraw);
    const int tid = threadIdx.x;
    const int wid = tid >> 5, lane = tid & 31;
    const int bm = blockIdx.y * GBM;
    const int bn = blockIdx.x * GBN;
    const int warp_m = (wid & 1) * 64;
    const int warp_n = (wid >> 1) * 32;

    uint32_t soff[2];
    const __nv_bfloat16 *gA[2], *gAl[2], *gB[2], *gBl[2];
    #pragma unroll
    for (int i = 0; i < 2; ++i) {
        int lin = i * 256 + tid;
        int row = lin >> 2, kc = lin & 3;
        soff[i] = row * 64 + (((uint32_t)kc ^ ((row >> 1) & 3)) << 4);
        gA[i]  = Ah + (size_t)(bm + row) * D_ + kc * 8;
        gAl[i] = Al + (size_t)(bm + row) * D_ + kc * 8;
        gB[i]  = Bh + (size_t)(bn + row) * D_ + kc * 8;
        gBl[i] = Bl + (size_t)(bn + row) * D_ + kc * 8;
    }

    const int arow = warp_m + (lane & 15);
    const uint32_t aoff = arow * 64 + ((((uint32_t)lane >> 4) ^ ((arow >> 1) & 3)) << 4);
    const int brow = warp_n + (lane & 7);
    const uint32_t boff = brow * 64 + (((((uint32_t)lane >> 3) & 1) ^ ((brow >> 1) & 3)) << 4);

    float acc[4][4][4] = {};

    auto prefetch = [&](int t) {
        uint32_t stg = sb + (t & 1) * STAGE;
        int kofs = t * GBK;
        #pragma unroll
        for (int i = 0; i < 2; ++i) {
            cpasync16(stg + soff[i],              gA[i]  + kofs);
            cpasync16(stg + TILE8K + soff[i],     gAl[i] + kofs);
            cpasync16(stg + 2 * TILE8K + soff[i], gB[i]  + kofs);
            cpasync16(stg + 3 * TILE8K + soff[i], gBl[i] + kofs);
        }
    };

    prefetch(0);
    cp_commit();

    const int NT = D_ / GBK;
    for (int t = 0; t < NT; ++t) {
        uint32_t stg = sb + (t & 1) * STAGE;
        if (t + 1 < NT) { prefetch(t + 1); cp_commit(); cp_wait<1>(); }
        else           { cp_wait<0>(); }
        __syncthreads();

        #pragma unroll
        for (int kh = 0; kh < 2; ++kh) {
            uint32_t ao = aoff ^ (kh << 5);
            uint32_t bo = boff ^ (kh << 5);
            uint32_t ah4[4][4], al4[4][4], bh2[4][2], bl2[4][2];
            #pragma unroll
            for (int mb = 0; mb < 4; ++mb) {
                ldsm_x4(ah4[mb], stg + ao + mb * 1024);
                ldsm_x4(al4[mb], stg + TILE8K + ao + mb * 1024);
            }
            #pragma unroll
            for (int nb = 0; nb < 4; ++nb) {
                ldsm_x2(bh2[nb], stg + 2 * TILE8K + bo + nb * 512);
                ldsm_x2(bl2[nb], stg + 3 * TILE8K + bo + nb * 512);
            }
            #pragma unroll
            for (int mb = 0; mb < 4; ++mb)
                #pragma unroll
                for (int nb = 0; nb < 4; ++nb)
                    mma16816(acc[mb][nb], ah4[mb], bh2[nb]);
            #pragma unroll
            for (int mb = 0; mb < 4; ++mb)
                #pragma unroll
                for (int nb = 0; nb < 4; ++nb)
                    mma16816(acc[mb][nb], al4[mb], bh2[nb]);
            #pragma unroll
            for (int mb = 0; mb < 4; ++mb)
                #pragma unroll
                for (int nb = 0; nb < 4; ++nb)
                    mma16816(acc[mb][nb], ah4[mb], bl2[nb]);
        }
        __syncthreads();
    }

    const int tm = bm + warp_m + (lane >> 2);
    const int tn = bn + warp_n + (lane & 3) * 2;
    if (MODE == 0) {
        #pragma unroll
        for (int mb = 0; mb < 4; ++mb)
            #pragma unroll
            for (int nb = 0; nb < 4; ++nb) {
                float* c0 = Cf + (size_t)(tm + mb * 16) * D_ + tn + nb * 8;
                *(float2*)c0 = make_float2(acc[mb][nb][0], acc[mb][nb][1]);
                float* c1 = c0 + 8 * D_;
                *(float2*)c1 = make_float2(acc[mb][nb][2], acc[mb][nb][3]);
            }
    } else {
        #pragma unroll
        for (int mb = 0; mb < 4; ++mb)
            #pragma unroll
            for (int nb = 0; nb < 4; ++nb) {
                int n = tn + nb * 8;
                int h = n >> 6, dk = n & 63;
                #pragma unroll
                for (int hh = 0; hh < 2; ++hh) {
                    int row = tm + mb * 16 + hh * 8;
                    int b = row >> 11, s = row & 2047;
                    size_t idx = (((size_t)b * H_ + h) * S_ + s) * 64 + dk;
                    uint32_t hi, lo;
                    split2(acc[mb][nb][hh * 2] * scale, acc[mb][nb][hh * 2 + 1] * scale, hi, lo);
                    *(uint32_t*)(Chi + idx) = hi;
                    *(uint32_t*)(Clo + idx) = lo;
                }
            }
    }
}

// ---------------- flash attention via mma.sync (split bf16) ----------------
// grid (S/128, B*H), 256 threads / 8 warps; warp w owns q-rows [w*16, w*16+16).
// Smem rows 128B, swizzle: chunk' = chunk ^ (row & 7).
#define FOFF(r, c) ((uint32_t)((r) * 128 + ((((c) ^ ((r) & 7))) << 4)))
#define FLASH_SMEM (32768 + 2 * 32768)   // Q hi/lo 32K + 2 KV stages of 32K

__global__ __launch_bounds__(256, 1)
void flash_mma(const __nv_bfloat16* __restrict__ qh, const __nv_bfloat16* __restrict__ ql,
               const __nv_bfloat16* __restrict__ kh, const __nv_bfloat16* __restrict__ kl,
               const __nv_bfloat16* __restrict__ vh, const __nv_bfloat16* __restrict__ vl,
               __nv_bfloat16* __restrict__ aoh, __nv_bfloat16* __restrict__ aol) {
    extern __shared__ char smraw[];
    const uint32_t sb = smem_u32(smraw);
    const int tid = threadIdx.x;
    const int wid = tid >> 5, lane = tid & 31;
    const int bh = blockIdx.y;
    const int s0 = blockIdx.x * 128;

    const size_t hb = (size_t)bh * S_ * 64;
    const __nv_bfloat16* qhp = qh + hb + (size_t)s0 * 64;
    const __nv_bfloat16* qlp = ql + hb + (size_t)s0 * 64;
    const __nv_bfloat16* khp = kh + hb;
    const __nv_bfloat16* klp = kl + hb;
    const __nv_bfloat16* vhp = vh + hb;
    const __nv_bfloat16* vlp = vl + hb;

    // Q tile loads (128 rows x 128B, hi + lo)
    #pragma unroll
    for (int i = 0; i < 4; ++i) {
        int lin = i * 256 + tid;
        int r = lin >> 3, c = lin & 7;
        cpasync16(sb + FOFF(r, c),         qhp + r * 64 + c * 8);
        cpasync16(sb + 16384 + FOFF(r, c), qlp + r * 64 + c * 8);
    }
    auto kvload = [&](int t) {
        uint32_t stg = sb + 32768 + (t & 1) * 32768;
        size_t tofs = (size_t)(t * 64) * 64;
        #pragma unroll
        for (int i = 0; i < 2; ++i) {
            int lin = i * 256 + tid;
            int r = lin >> 3, c = lin & 7;
            uint32_t o = FOFF(r, c);
            size_t g = tofs + r * 64 + c * 8;
            cpasync16(stg + o,         khp + g);
            cpasync16(stg + 8192 + o,  klp + g);
            cpasync16(stg + 16384 + o, vhp + g);
            cpasync16(stg + 24576 + o, vlp + g);
        }
    };
    kvload(0);
    cp_commit();

    const int warp_m = wid * 16;
    uint32_t qhf[4][4], qlf[4][4];
    float Oacc[8][4] = {};
    float m0 = -1e30f, m1 = -1e30f, l0 = 0.f, l1 = 0.f;

    const int NT = S_ / 64;   // 32
    for (int t = 0; t < NT; ++t) {
        if (t + 1 < NT) { kvload(t + 1); cp_commit(); cp_wait<1>(); }
        else           { cp_wait<0>(); }
        __syncthreads();
        uint32_t stg = sb + 32768 + (t & 1) * 32768;

        if (t == 0) {
            #pragma unroll
            for (int kb = 0; kb < 4; ++kb) {
                int r = warp_m + (lane & 15);
                int c = kb * 2 + (lane >> 4);
                ldsm_x4(qhf[kb], sb + FOFF(r, c));
                ldsm_x4(qlf[kb], sb + 16384 + FOFF(r, c));
            }
        }

        // ---- S = Q K^T (3-term split) ----
        float sacc[8][4] = {};
        #pragma unroll
        for (int kb = 0; kb < 4; ++kb) {
            #pragma unroll
            for (int nbp = 0; nbp < 4; ++nbp) {
                int r = nbp * 16 + ((lane >> 4) << 3) + (lane & 7);
                int c = kb * 2 + ((lane >> 3) & 1);
                uint32_t khf[4], klf[4];
                ldsm_x4(khf, stg + FOFF(r, c));
                ldsm_x4(klf, stg + 8192 + FOFF(r, c));
                mma16816(sacc[2 * nbp],     qhf[kb], khf);
                mma16816(sacc[2 * nbp + 1], qhf[kb], khf + 2);
                mma16816(sacc[2 * nbp],     qlf[kb], khf);
                mma16816(sacc[2 * nbp + 1], qlf[kb], khf + 2);
                mma16816(sacc[2 * nbp],     qhf[kb], klf);
                mma16816(sacc[2 * nbp + 1], qhf[kb], klf + 2);
            }
        }

        // ---- online softmax (rows exclusive to this warp) ----
        float mx0 = -1e30f, mx1 = -1e30f;
        #pragma unroll
        for (int nb = 0; nb < 8; ++nb) {
            mx0 = fmaxf(mx0, fmaxf(sacc[nb][0], sacc[nb][1]));
            mx1 = fmaxf(mx1, fmaxf(sacc[nb][2], sacc[nb][3]));
        }
        mx0 = fmaxf(mx0, __shfl_xor_sync(0xffffffffu, mx0, 1));
        mx0 = fmaxf(mx0, __shfl_xor_sync(0xffffffffu, mx0, 2));
        mx1 = fmaxf(mx1, __shfl_xor_sync(0xffffffffu, mx1, 1));
        mx1 = fmaxf(mx1, __shfl_xor_sync(0xffffffffu, mx1, 2));
        float mn0 = fmaxf(m0, mx0), mn1 = fmaxf(m1, mx1);
        float c0 = __expf(m0 - mn0), c1 = __expf(m1 - mn1);
        float sum0 = 0.f, sum1 = 0.f;
        #pragma unroll
        for (int nb = 0; nb < 8; ++nb) {
            sacc[nb][0] = __expf(sacc[nb][0] - mn0); sum0 += sacc[nb][0];
            sacc[nb][1] = __expf(sacc[nb][1] - mn0); sum0 += sacc[nb][1];
            sacc[nb][2] = __expf(sacc[nb][2] - mn1); sum1 += sacc[nb][2];
            sacc[nb][3] = __expf(sacc[nb][3] - mn1); sum1 += sacc[nb][3];
        }
        sum0 += __shfl_xor_sync(0xffffffffu, sum0, 1);
        sum0 += __shfl_xor_sync(0xffffffffu, sum0, 2);
        sum1 += __shfl_xor_sync(0xffffffffu, sum1, 1);
        sum1 += __shfl_xor_sync(0xffffffffu, sum1, 2);
        l0 = l0 * c0 + sum0;
        l1 = l1 * c1 + sum1;
        m0 = mn0; m1 = mn1;
        #pragma unroll
        for (int nb = 0; nb < 8; ++nb) {
            Oacc[nb][0] *= c0; Oacc[nb][1] *= c0;
            Oacc[nb][2] *= c1; Oacc[nb][3] *= c1;
        }

        // ---- P -> split bf16 A-fragments (register reuse) ----
        uint32_t phf[4][4], plf[4][4];
        #pragma unroll
        for (int kb = 0; kb < 4; ++kb) {
            split2(sacc[2 * kb][0],     sacc[2 * kb][1],     phf[kb][0], plf[kb][0]);
            split2(sacc[2 * kb][2],     sacc[2 * kb][3],     phf[kb][1], plf[kb][1]);
            split2(sacc[2 * kb + 1][0], sacc[2 * kb + 1][1], phf[kb][2], plf[kb][2]);
            split2(sacc[2 * kb + 1][2], sacc[2 * kb + 1][3], phf[kb][3], plf[kb][3]);
        }

        // ---- O += P V (3-term split, ldmatrix.trans for V) ----
        #pragma unroll
        for (int kb = 0; kb < 4; ++kb) {
            #pragma unroll
            for (int nbp = 0; nbp < 4; ++nbp) {
                int r = kb * 16 + (((lane >> 3) & 1) << 3) + (lane & 7);
                int c = nbp * 2 + (lane >> 4);
                uint32_t vhf[4], vlf[4];
                ldsm_x4_t(vhf, stg + 16384 + FOFF(r, c));
                ldsm_x4_t(vlf, stg + 24576 + FOFF(r, c));
                mma16816(Oacc[2 * nbp],     phf[kb], vhf);
                mma16816(Oacc[2 * nbp + 1], phf[kb], vhf + 2);
                mma16816(Oacc[2 * nbp],     plf[kb], vhf);
                mma16816(Oacc[2 * nbp + 1], plf[kb], vhf + 2);
                mma16816(Oacc[2 * nbp],     phf[kb], vlf);
                mma16816(Oacc[2 * nbp + 1], phf[kb], vlf + 2);
            }
        }
        __syncthreads();
    }

    // ---- epilogue: normalize, split, write [b*S+s][D] ----
    float inv0 = 1.f / l0, inv1 = 1.f / l1;
    int b = bh >> 4, h = bh & 15;
    int r0 = s0 + warp_m + (lane >> 2);
    size_t base0 = ((size_t)b * S_ + r0) * D_ + h * 64 + (lane & 3) * 2;
    size_t base1 = base0 + 8 * D_;
    #pragma unroll
    for (int nb = 0; nb < 8; ++nb) {
        uint32_t hi, lo;
        split2(Oacc[nb][0] * inv0, Oacc[nb][1] * inv0, hi, lo);
        *(uint32_t*)(aoh + base0 + nb * 8) = hi;
        *(uint32_t*)(aol + base0 + nb * 8) = lo;
        split2(Oacc[nb][2] * inv1, Oacc[nb][3] * inv1, hi, lo);
        *(uint32_t*)(aoh + base1 + nb * 8) = hi;
        *(uint32_t*)(aol + base1 + nb * 8) = lo;
    }
}

// ---------------- launch ----------------
extern "C" void kernel_launch(void* const* d_in, const int* in_sizes, int n_in,
                              void* d_out, int out_size) {
    const float* query = (const float*)d_in[0];
    const float* key   = (const float*)d_in[1];
    const float* value = (const float*)d_in[2];
    const float* Wq    = (const float*)d_in[3];
    const float* Wk    = (const float*)d_in[4];
    const float* Wv    = (const float*)d_in[5];
    const float* Wo    = (const float*)d_in[6];
    float* out = (float*)d_out;

    __nv_bfloat16 *ah, *al, *wh, *wl, *qh, *ql, *kh, *kl, *vh, *vl, *aoh, *aol;
    cudaGetSymbolAddress((void**)&ah,  g_ah);
    cudaGetSymbolAddress((void**)&al,  g_al);
    cudaGetSymbolAddress((void**)&wh,  g_wh);
    cudaGetSymbolAddress((void**)&wl,  g_wl);
    cudaGetSymbolAddress((void**)&qh,  g_qh);
    cudaGetSymbolAddress((void**)&ql,  g_ql);
    cudaGetSymbolAddress((void**)&kh,  g_kh);
    cudaGetSymbolAddress((void**)&kl,  g_kl);
    cudaGetSymbolAddress((void**)&vh,  g_vh);
    cudaGetSymbolAddress((void**)&vl,  g_vl);
    cudaGetSymbolAddress((void**)&aoh, g_aoh);
    cudaGetSymbolAddress((void**)&aol, g_aol);

    cudaFuncSetAttribute(gemm_mma<0>, cudaFuncAttributeMaxDynamicSharedMemorySize, GEMM_SMEM);
    cudaFuncSetAttribute(gemm_mma<1>, cudaFuncAttributeMaxDynamicSharedMemorySize, GEMM_SMEM);
    cudaFuncSetAttribute(flash_mma, cudaFuncAttributeMaxDynamicSharedMemorySize, FLASH_SMEM);

    rearrange_w<<<(D_ * D_ + 255) / 256, 256>>>(Wq, Wk, Wv, Wo);

    dim3 ggrid(D_ / GBN, M_ / GBM);   // (8, 128)
    int splitBlocks = (M_ * D_ / 4) / 256;

    // projections -> head-major split bf16 (Q gets d_model^-0.5 folded in)
    split_bf16<<<splitBlocks, 256>>>(query, ah, al);
    gemm_mma<1><<<ggrid, 256, GEMM_SMEM>>>(ah, al, wh + 0 * D_ * D_, wl + 0 * D_ * D_,
                                           nullptr, qh, ql, 0.03125f);
    split_bf16<<<splitBlocks, 256>>>(key, ah, al);
    gemm_mma<1><<<ggrid, 256, GEMM_SMEM>>>(ah, al, wh + 1 * D_ * D_, wl + 1 * D_ * D_,
                                           nullptr, kh, kl, 1.0f);
    split_bf16<<<splitBlocks, 256>>>(value, ah, al);
    gemm_mma<1><<<ggrid, 256, GEMM_SMEM>>>(ah, al, wh + 2 * D_ * D_, wl + 2 * D_ * D_,
                                           nullptr, vh, vl, 1.0f);

    // attention (tensor-core flash, split bf16)
    dim3 fgrid(S_ / 128, B_ * H_);
    flash_mma<<<fgrid, 256, FLASH_SMEM>>>(qh, ql, kh, kl, vh, vl, aoh, aol);

    // output projection -> fp32 out
    gemm_mma<0><<<ggrid, 256, GEMM_SMEM>>>(aoh, aol, wh + 3 * D_ * D_, wl + 3 * D_ * D_,
                                           out, nullptr, nullptr, 1.0f);
}

// round 5
// speedup vs baseline: 3.5107x; 1.0757x over previous
#include <cuda_runtime.h>
#include <cuda_bf16.h>
#include <stdint.h>
#include <math.h>

#define B_  8
#define S_  2048
#define D_  1024
#define H_  16
#define DK_ 64
#define M_  (B_*S_)   // 16384

// ---------------- scratch (device globals: allocation-free) ----------------
__device__ __nv_bfloat16 g_ah[M_ * D_];
__device__ __nv_bfloat16 g_al[M_ * D_];
__device__ __nv_bfloat16 g_wh[4 * D_ * D_];  // weights hi, [N][K]: q,k,v,o
__device__ __nv_bfloat16 g_wl[4 * D_ * D_];
__device__ __nv_bfloat16 g_qh[M_ * D_];
__device__ __nv_bfloat16 g_ql[M_ * D_];
__device__ __nv_bfloat16 g_kh[M_ * D_];
__device__ __nv_bfloat16 g_kl[M_ * D_];
__device__ __nv_bfloat16 g_vh[M_ * D_];
__device__ __nv_bfloat16 g_vl[M_ * D_];
__device__ __nv_bfloat16 g_aoh[M_ * D_];
__device__ __nv_bfloat16 g_aol[M_ * D_];

// ---------------- helpers ----------------
__device__ __forceinline__ uint32_t smem_u32(const void* p) {
    return (uint32_t)__cvta_generic_to_shared(p);
}
__device__ __forceinline__ void cpasync16(uint32_t s, const void* g) {
    asm volatile("cp.async.cg.shared.global [%0], [%1], 16;" :: "r"(s), "l"(g));
}
__device__ __forceinline__ void cp_commit() {
    asm volatile("cp.async.commit_group;" ::: "memory");
}
template<int N> __device__ __forceinline__ void cp_wait() {
    asm volatile("cp.async.wait_group %0;" :: "n"(N) : "memory");
}
__device__ __forceinline__ void ldsm_x4(uint32_t* r, uint32_t a) {
    asm volatile("ldmatrix.sync.aligned.m8n8.x4.shared.b16 {%0,%1,%2,%3}, [%4];"
                 : "=r"(r[0]), "=r"(r[1]), "=r"(r[2]), "=r"(r[3]) : "r"(a));
}
__device__ __forceinline__ void ldsm_x4_t(uint32_t* r, uint32_t a) {
    asm volatile("ldmatrix.sync.aligned.m8n8.x4.trans.shared.b16 {%0,%1,%2,%3}, [%4];"
                 : "=r"(r[0]), "=r"(r[1]), "=r"(r[2]), "=r"(r[3]) : "r"(a));
}
__device__ __forceinline__ void ldsm_x2(uint32_t* r, uint32_t a) {
    asm volatile("ldmatrix.sync.aligned.m8n8.x2.shared.b16 {%0,%1}, [%2];"
                 : "=r"(r[0]), "=r"(r[1]) : "r"(a));
}
__device__ __forceinline__ void mma16816(float* d, const uint32_t* a, const uint32_t* b) {
    asm volatile(
        "mma.sync.aligned.m16n8k16.row.col.f32.bf16.bf16.f32 "
        "{%0,%1,%2,%3}, {%4,%5,%6,%7}, {%8,%9}, {%0,%1,%2,%3};"
        : "+f"(d[0]), "+f"(d[1]), "+f"(d[2]), "+f"(d[3])
        : "r"(a[0]), "r"(a[1]), "r"(a[2]), "r"(a[3]), "r"(b[0]), "r"(b[1]));
}
__device__ __forceinline__ uint32_t pk2(__nv_bfloat16 a, __nv_bfloat16 b) {
    return (uint32_t)__bfloat16_as_ushort(a) | ((uint32_t)__bfloat16_as_ushort(b) << 16);
}
__device__ __forceinline__ void split2(float x, float y, uint32_t& hi, uint32_t& lo) {
    __nv_bfloat162 h2 = __floats2bfloat162_rn(x, y);
    float lx = x - __bfloat162float(h2.x);
    float ly = y - __bfloat162float(h2.y);
    __nv_bfloat162 l2 = __floats2bfloat162_rn(lx, ly);
    hi = *reinterpret_cast<uint32_t*>(&h2);
    lo = *reinterpret_cast<uint32_t*>(&l2);
}

// 128B rows, 8x16B chunks, swizzle chunk' = chunk ^ (row & 7)
#define FOFF(r, c) ((uint32_t)((r) * 128 + ((((c) ^ ((r) & 7))) << 4)))

// ---------------- weight rearrange + bf16 split ----------------
__global__ void rearrange_w(const float* __restrict__ Wq, const float* __restrict__ Wk,
                            const float* __restrict__ Wv, const float* __restrict__ Wo) {
    int idx = blockIdx.x * blockDim.x + threadIdx.x;
    if (idx >= D_ * D_) return;
    int n = idx / D_;
    int k = idx % D_;
    int h = n >> 6, dk = n & 63;
    float w[4];
    w[0] = Wq[((size_t)h * D_ + k) * DK_ + dk];
    w[1] = Wk[((size_t)h * D_ + k) * DK_ + dk];
    w[2] = Wv[((size_t)h * D_ + k) * DK_ + dk];
    w[3] = Wo[(size_t)n * D_ + k];
    #pragma unroll
    for (int j = 0; j < 4; ++j) {
        __nv_bfloat16 hi = __float2bfloat16(w[j]);
        float lo = w[j] - __bfloat162float(hi);
        g_wh[j * D_ * D_ + idx] = hi;
        g_wl[j * D_ * D_ + idx] = __float2bfloat16(lo);
    }
}

// ---------------- activation bf16 split ----------------
__global__ void split_bf16(const float* __restrict__ x,
                           __nv_bfloat16* __restrict__ hi, __nv_bfloat16* __restrict__ lo) {
    int i = blockIdx.x * blockDim.x + threadIdx.x;
    float4 v = ((const float4*)x)[i];
    __nv_bfloat16 h0 = __float2bfloat16(v.x), h1 = __float2bfloat16(v.y),
                  h2 = __float2bfloat16(v.z), h3 = __float2bfloat16(v.w);
    __nv_bfloat16 l0 = __float2bfloat16(v.x - __bfloat162float(h0));
    __nv_bfloat16 l1 = __float2bfloat16(v.y - __bfloat162float(h1));
    __nv_bfloat16 l2 = __float2bfloat16(v.z - __bfloat162float(h2));
    __nv_bfloat16 l3 = __float2bfloat16(v.w - __bfloat162float(h3));
    ((uint2*)hi)[i] = make_uint2(pk2(h0, h1), pk2(h2, h3));
    ((uint2*)lo)[i] = make_uint2(pk2(l0, l1), pk2(l2, l3));
}

// ---------------- mma.sync split-bf16 GEMM (BK=64, 3-stage) ----------------
#define GBM 128
#define GBN 128
#define GBK 64
#define GTILE 16384                 // 128 rows x 128B
#define GSTAGE (4 * GTILE)          // Ah, Al, Bh, Bl = 64KB
#define GEMM_SMEM (3 * GSTAGE)      // 192KB

template<int MODE>
__global__ __launch_bounds__(256, 1)
void gemm_mma(const __nv_bfloat16* __restrict__ Ah, const __nv_bfloat16* __restrict__ Al,
              const __nv_bfloat16* __restrict__ Bh, const __nv_bfloat16* __restrict__ Bl,
              float* __restrict__ Cf,
              __nv_bfloat16* __restrict__ Chi, __nv_bfloat16* __restrict__ Clo,
              float scale) {
    extern __shared__ char smraw[];
    const uint32_t sb = smem_u32(smraw);
    const int tid = threadIdx.x;
    const int wid = tid >> 5, lane = tid & 31;
    const int bm = blockIdx.y * GBM;
    const int bn = blockIdx.x * GBN;
    const int warp_m = (wid & 1) * 64;
    const int warp_n = (wid >> 1) * 32;

    // cp.async: 4 chunks per thread per 16KB tile (1024 chunks / 256 thr)
    uint32_t soff[4];
    const __nv_bfloat16 *pA[4], *pAl[4], *pB[4], *pBl[4];
    #pragma unroll
    for (int i = 0; i < 4; ++i) {
        int lin = i * 256 + tid;
        int row = lin >> 3, c = lin & 7;
        soff[i] = FOFF(row, c);
        pA[i]  = Ah + (size_t)(bm + row) * D_ + c * 8;
        pAl[i] = Al + (size_t)(bm + row) * D_ + c * 8;
        pB[i]  = Bh + (size_t)(bn + row) * D_ + c * 8;
        pBl[i] = Bl + (size_t)(bn + row) * D_ + c * 8;
    }

    auto prefetch = [&](int t) {
        uint32_t stg = sb + (t % 3) * GSTAGE;
        int kofs = t * GBK;
        #pragma unroll
        for (int i = 0; i < 4; ++i) {
            cpasync16(stg + soff[i],             pA[i]  + kofs);
            cpasync16(stg + GTILE + soff[i],     pAl[i] + kofs);
            cpasync16(stg + 2 * GTILE + soff[i], pB[i]  + kofs);
            cpasync16(stg + 3 * GTILE + soff[i], pBl[i] + kofs);
        }
    };

    prefetch(0); cp_commit();
    prefetch(1); cp_commit();

    const int arow = warp_m + (lane & 15);
    const int brow = warp_n + (lane & 7);
    float acc[4][4][4] = {};

    const int NT = D_ / GBK;   // 16
    for (int t = 0; t < NT; ++t) {
        if (t == NT - 1) cp_wait<0>(); else cp_wait<1>();
        __syncthreads();
        if (t + 2 < NT) { prefetch(t + 2); cp_commit(); }
        uint32_t stg = sb + (t % 3) * GSTAGE;

        #pragma unroll
        for (int kk = 0; kk < 4; ++kk) {
            uint32_t ao = FOFF(arow, kk * 2 + (lane >> 4));
            uint32_t bo = FOFF(brow, kk * 2 + ((lane >> 3) & 1));
            uint32_t ah4[4][4], al4[4][4], bh2[4][2], bl2[4][2];
            #pragma unroll
            for (int mb = 0; mb < 4; ++mb) {
                ldsm_x4(ah4[mb], stg + ao + mb * 2048);
                ldsm_x4(al4[mb], stg + GTILE + ao + mb * 2048);
            }
            #pragma unroll
            for (int nb = 0; nb < 4; ++nb) {
                ldsm_x2(bh2[nb], stg + 2 * GTILE + bo + nb * 1024);
                ldsm_x2(bl2[nb], stg + 3 * GTILE + bo + nb * 1024);
            }
            #pragma unroll
            for (int mb = 0; mb < 4; ++mb)
                #pragma unroll
                for (int nb = 0; nb < 4; ++nb)
                    mma16816(acc[mb][nb], ah4[mb], bh2[nb]);
            #pragma unroll
            for (int mb = 0; mb < 4; ++mb)
                #pragma unroll
                for (int nb = 0; nb < 4; ++nb)
                    mma16816(acc[mb][nb], al4[mb], bh2[nb]);
            #pragma unroll
            for (int mb = 0; mb < 4; ++mb)
                #pragma unroll
                for (int nb = 0; nb < 4; ++nb)
                    mma16816(acc[mb][nb], ah4[mb], bl2[nb]);
        }
    }

    const int tm = bm + warp_m + (lane >> 2);
    const int tn = bn + warp_n + (lane & 3) * 2;
    if (MODE == 0) {
        #pragma unroll
        for (int mb = 0; mb < 4; ++mb)
            #pragma unroll
            for (int nb = 0; nb < 4; ++nb) {
                float* c0 = Cf + (size_t)(tm + mb * 16) * D_ + tn + nb * 8;
                *(float2*)c0 = make_float2(acc[mb][nb][0], acc[mb][nb][1]);
                float* c1 = c0 + 8 * D_;
                *(float2*)c1 = make_float2(acc[mb][nb][2], acc[mb][nb][3]);
            }
    } else {
        #pragma unroll
        for (int mb = 0; mb < 4; ++mb)
            #pragma unroll
            for (int nb = 0; nb < 4; ++nb) {
                int n = tn + nb * 8;
                int h = n >> 6, dk = n & 63;
                #pragma unroll
                for (int hh = 0; hh < 2; ++hh) {
                    int row = tm + mb * 16 + hh * 8;
                    int b = row >> 11, s = row & 2047;
                    size_t idx = (((size_t)b * H_ + h) * S_ + s) * 64 + dk;
                    uint32_t hi, lo;
                    split2(acc[mb][nb][hh * 2] * scale, acc[mb][nb][hh * 2 + 1] * scale, hi, lo);
                    *(uint32_t*)(Chi + idx) = hi;
                    *(uint32_t*)(Clo + idx) = lo;
                }
            }
    }
}

// ---------------- flash attention via mma.sync (3-stage KV ring) ----------------
#define FLASH_SMEM (32768 + 3 * 32768)   // Q hi/lo 32K + 3 KV stages of 32K

__global__ __launch_bounds__(256, 1)
void flash_mma(const __nv_bfloat16* __restrict__ qh, const __nv_bfloat16* __restrict__ ql,
               const __nv_bfloat16* __restrict__ kh, const __nv_bfloat16* __restrict__ kl,
               const __nv_bfloat16* __restrict__ vh, const __nv_bfloat16* __restrict__ vl,
               __nv_bfloat16* __restrict__ aoh, __nv_bfloat16* __restrict__ aol) {
    extern __shared__ char smraw[];
    const uint32_t sb = smem_u32(smraw);
    const int tid = threadIdx.x;
    const int wid = tid >> 5, lane = tid & 31;
    const int bh = blockIdx.y;
    const int s0 = blockIdx.x * 128;

    const size_t hb = (size_t)bh * S_ * 64;
    const __nv_bfloat16* qhp = qh + hb + (size_t)s0 * 64;
    const __nv_bfloat16* qlp = ql + hb + (size_t)s0 * 64;
    const __nv_bfloat16* khp = kh + hb;
    const __nv_bfloat16* klp = kl + hb;
    const __nv_bfloat16* vhp = vh + hb;
    const __nv_bfloat16* vlp = vl + hb;

    // Q tile (part of group 0)
    #pragma unroll
    for (int i = 0; i < 4; ++i) {
        int lin = i * 256 + tid;
        int r = lin >> 3, c = lin & 7;
        cpasync16(sb + FOFF(r, c),         qhp + r * 64 + c * 8);
        cpasync16(sb + 16384 + FOFF(r, c), qlp + r * 64 + c * 8);
    }
    auto kvload = [&](int t) {
        uint32_t stg = sb + 32768 + (t % 3) * 32768;
        size_t tofs = (size_t)(t * 64) * 64;
        #pragma unroll
        for (int i = 0; i < 2; ++i) {
            int lin = i * 256 + tid;
            int r = lin >> 3, c = lin & 7;
            uint32_t o = FOFF(r, c);
            size_t g = tofs + r * 64 + c * 8;
            cpasync16(stg + o,         khp + g);
            cpasync16(stg + 8192 + o,  klp + g);
            cpasync16(stg + 16384 + o, vhp + g);
            cpasync16(stg + 24576 + o, vlp + g);
        }
    };
    kvload(0); cp_commit();
    kvload(1); cp_commit();

    const int warp_m = wid * 16;
    uint32_t qhf[4][4], qlf[4][4];
    float Oacc[8][4] = {};
    float m0 = -1e30f, m1 = -1e30f, l0 = 0.f, l1 = 0.f;

    const int NT = S_ / 64;   // 32
    for (int t = 0; t < NT; ++t) {
        if (t == NT - 1) cp_wait<0>(); else cp_wait<1>();
        __syncthreads();
        if (t + 2 < NT) { kvload(t + 2); cp_commit(); }
        uint32_t stg = sb + 32768 + (t % 3) * 32768;

        if (t == 0) {
            #pragma unroll
            for (int kb = 0; kb < 4; ++kb) {
                int r = warp_m + (lane & 15);
                int c = kb * 2 + (lane >> 4);
                ldsm_x4(qhf[kb], sb + FOFF(r, c));
                ldsm_x4(qlf[kb], sb + 16384 + FOFF(r, c));
            }
        }

        // ---- S = Q K^T (3-term split) ----
        float sacc[8][4] = {};
        #pragma unroll
        for (int kb = 0; kb < 4; ++kb) {
            #pragma unroll
            for (int nbp = 0; nbp < 4; ++nbp) {
                int r = nbp * 16 + ((lane >> 4) << 3) + (lane & 7);
                int c = kb * 2 + ((lane >> 3) & 1);
                uint32_t khf[4], klf[4];
                ldsm_x4(khf, stg + FOFF(r, c));
                ldsm_x4(klf, stg + 8192 + FOFF(r, c));
                mma16816(sacc[2 * nbp],     qhf[kb], khf);
                mma16816(sacc[2 * nbp + 1], qhf[kb], khf + 2);
                mma16816(sacc[2 * nbp],     qlf[kb], khf);
                mma16816(sacc[2 * nbp + 1], qlf[kb], khf + 2);
                mma16816(sacc[2 * nbp],     qhf[kb], klf);
                mma16816(sacc[2 * nbp + 1], qhf[kb], klf + 2);
            }
        }

        // ---- online softmax ----
        float mx0 = -1e30f, mx1 = -1e30f;
        #pragma unroll
        for (int nb = 0; nb < 8; ++nb) {
            mx0 = fmaxf(mx0, fmaxf(sacc[nb][0], sacc[nb][1]));
            mx1 = fmaxf(mx1, fmaxf(sacc[nb][2], sacc[nb][3]));
        }
        mx0 = fmaxf(mx0, __shfl_xor_sync(0xffffffffu, mx0, 1));
        mx0 = fmaxf(mx0, __shfl_xor_sync(0xffffffffu, mx0, 2));
        mx1 = fmaxf(mx1, __shfl_xor_sync(0xffffffffu, mx1, 1));
        mx1 = fmaxf(mx1, __shfl_xor_sync(0xffffffffu, mx1, 2));
        float mn0 = fmaxf(m0, mx0), mn1 = fmaxf(m1, mx1);
        float c0 = __expf(m0 - mn0), c1 = __expf(m1 - mn1);
        float sum0 = 0.f, sum1 = 0.f;
        #pragma unroll
        for (int nb = 0; nb < 8; ++nb) {
            sacc[nb][0] = __expf(sacc[nb][0] - mn0); sum0 += sacc[nb][0];
            sacc[nb][1] = __expf(sacc[nb][1] - mn0); sum0 += sacc[nb][1];
            sacc[nb][2] = __expf(sacc[nb][2] - mn1); sum1 += sacc[nb][2];
            sacc[nb][3] = __expf(sacc[nb][3] - mn1); sum1 += sacc[nb][3];
        }
        sum0 += __shfl_xor_sync(0xffffffffu, sum0, 1);
        sum0 += __shfl_xor_sync(0xffffffffu, sum0, 2);
        sum1 += __shfl_xor_sync(0xffffffffu, sum1, 1);
        sum1 += __shfl_xor_sync(0xffffffffu, sum1, 2);
        l0 = l0 * c0 + sum0;
        l1 = l1 * c1 + sum1;
        m0 = mn0; m1 = mn1;
        #pragma unroll
        for (int nb = 0; nb < 8; ++nb) {
            Oacc[nb][0] *= c0; Oacc[nb][1] *= c0;
            Oacc[nb][2] *= c1; Oacc[nb][3] *= c1;
        }

        // ---- P -> split bf16 fragments ----
        uint32_t phf[4][4], plf[4][4];
        #pragma unroll
        for (int kb = 0; kb < 4; ++kb) {
            split2(sacc[2 * kb][0],     sacc[2 * kb][1],     phf[kb][0], plf[kb][0]);
            split2(sacc[2 * kb][2],     sacc[2 * kb][3],     phf[kb][1], plf[kb][1]);
            split2(sacc[2 * kb + 1][0], sacc[2 * kb + 1][1], phf[kb][2], plf[kb][2]);
            split2(sacc[2 * kb + 1][2], sacc[2 * kb + 1][3], phf[kb][3], plf[kb][3]);
        }

        // ---- O += P V (3-term split, trans V) ----
        #pragma unroll
        for (int kb = 0; kb < 4; ++kb) {
            #pragma unroll
            for (int nbp = 0; nbp < 4; ++nbp) {
                int r = kb * 16 + (((lane >> 3) & 1) << 3) + (lane & 7);
                int c = nbp * 2 + (lane >> 4);
                uint32_t vhf[4], vlf[4];
                ldsm_x4_t(vhf, stg + 16384 + FOFF(r, c));
                ldsm_x4_t(vlf, stg + 24576 + FOFF(r, c));
                mma16816(Oacc[2 * nbp],     phf[kb], vhf);
                mma16816(Oacc[2 * nbp + 1], phf[kb], vhf + 2);
                mma16816(Oacc[2 * nbp],     plf[kb], vhf);
                mma16816(Oacc[2 * nbp + 1], plf[kb], vhf + 2);
                mma16816(Oacc[2 * nbp],     phf[kb], vlf);
                mma16816(Oacc[2 * nbp + 1], phf[kb], vlf + 2);
            }
        }
    }

    // ---- epilogue ----
    float inv0 = 1.f / l0, inv1 = 1.f / l1;
    int b = bh >> 4, h = bh & 15;
    int r0 = s0 + warp_m + (lane >> 2);
    size_t base0 = ((size_t)b * S_ + r0) * D_ + h * 64 + (lane & 3) * 2;
    size_t base1 = base0 + 8 * D_;
    #pragma unroll
    for (int nb = 0; nb < 8; ++nb) {
        uint32_t hi, lo;
        split2(Oacc[nb][0] * inv0, Oacc[nb][1] * inv0, hi, lo);
        *(uint32_t*)(aoh + base0 + nb * 8) = hi;
        *(uint32_t*)(aol + base0 + nb * 8) = lo;
        split2(Oacc[nb][2] * inv1, Oacc[nb][3] * inv1, hi, lo);
        *(uint32_t*)(aoh + base1 + nb * 8) = hi;
        *(uint32_t*)(aol + base1 + nb * 8) = lo;
    }
}

// ---------------- launch ----------------
extern "C" void kernel_launch(void* const* d_in, const int* in_sizes, int n_in,
                              void* d_out, int out_size) {
    const float* query = (const float*)d_in[0];
    const float* key   = (const float*)d_in[1];
    const float* value = (const float*)d_in[2];
    const float* Wq    = (const float*)d_in[3];
    const float* Wk    = (const float*)d_in[4];
    const float* Wv    = (const float*)d_in[5];
    const float* Wo    = (const float*)d_in[6];
    float* out = (float*)d_out;

    __nv_bfloat16 *ah, *al, *wh, *wl, *qh, *ql, *kh, *kl, *vh, *vl, *aoh, *aol;
    cudaGetSymbolAddress((void**)&ah,  g_ah);
    cudaGetSymbolAddress((void**)&al,  g_al);
    cudaGetSymbolAddress((void**)&wh,  g_wh);
    cudaGetSymbolAddress((void**)&wl,  g_wl);
    cudaGetSymbolAddress((void**)&qh,  g_qh);
    cudaGetSymbolAddress((void**)&ql,  g_ql);
    cudaGetSymbolAddress((void**)&kh,  g_kh);
    cudaGetSymbolAddress((void**)&kl,  g_kl);
    cudaGetSymbolAddress((void**)&vh,  g_vh);
    cudaGetSymbolAddress((void**)&vl,  g_vl);
    cudaGetSymbolAddress((void**)&aoh, g_aoh);
    cudaGetSymbolAddress((void**)&aol, g_aol);

    cudaFuncSetAttribute(gemm_mma<0>, cudaFuncAttributeMaxDynamicSharedMemorySize, GEMM_SMEM);
    cudaFuncSetAttribute(gemm_mma<1>, cudaFuncAttributeMaxDynamicSharedMemorySize, GEMM_SMEM);
    cudaFuncSetAttribute(flash_mma, cudaFuncAttributeMaxDynamicSharedMemorySize, FLASH_SMEM);

    rearrange_w<<<(D_ * D_ + 255) / 256, 256>>>(Wq, Wk, Wv, Wo);

    dim3 ggrid(D_ / GBN, M_ / GBM);   // (8, 128)
    int splitBlocks = (M_ * D_ / 4) / 256;

    split_bf16<<<splitBlocks, 256>>>(query, ah, al);
    gemm_mma<1><<<ggrid, 256, GEMM_SMEM>>>(ah, al, wh + 0 * D_ * D_, wl + 0 * D_ * D_,
                                           nullptr, qh, ql, 0.03125f);
    split_bf16<<<splitBlocks, 256>>>(key, ah, al);
    gemm_mma<1><<<ggrid, 256, GEMM_SMEM>>>(ah, al, wh + 1 * D_ * D_, wl + 1 * D_ * D_,
                                           nullptr, kh, kl, 1.0f);
    split_bf16<<<splitBlocks, 256>>>(value, ah, al);
    gemm_mma<1><<<ggrid, 256, GEMM_SMEM>>>(ah, al, wh + 2 * D_ * D_, wl + 2 * D_ * D_,
                                           nullptr, vh, vl, 1.0f);

    dim3 fgrid(S_ / 128, B_ * H_);
    flash_mma<<<fgrid, 256, FLASH_SMEM>>>(qh, ql, kh, kl, vh, vl, aoh, aol);

    gemm_mma<0><<<ggrid, 256, GEMM_SMEM>>>(aoh, aol, wh + 3 * D_ * D_, wl + 3 * D_ * D_,
                                           out, nullptr, nullptr, 1.0f);
}

// round 6
// speedup vs baseline: 3.9904x; 1.1366x over previous
#include <cuda_runtime.h>
#include <cuda_bf16.h>
#include <cuda_fp16.h>
#include <stdint.h>
#include <math.h>

#define B_  8
#define S_  2048
#define D_  1024
#define H_  16
#define DK_ 64
#define M_  (B_*S_)   // 16384

// ---------------- scratch (device globals: allocation-free) ----------------
__device__ __nv_bfloat16 g_ah[M_ * D_];
__device__ __nv_bfloat16 g_al[M_ * D_];
__device__ __nv_bfloat16 g_wh[4 * D_ * D_];  // weights hi, [N][K]: q,k,v,o
__device__ __nv_bfloat16 g_wl[4 * D_ * D_];
__device__ __half g_qf[M_ * D_];             // head-major fp16 q (scale folded)
__device__ __half g_kf[M_ * D_];             // head-major fp16 k
__device__ __half g_vh16[M_ * D_];           // head-major fp16 v hi
__device__ __half g_vl16[M_ * D_];           // head-major fp16 v lo
__device__ __nv_bfloat16 g_aoh[M_ * D_];     // attention out split (feeds Wo)
__device__ __nv_bfloat16 g_aol[M_ * D_];

// ---------------- helpers ----------------
__device__ __forceinline__ uint32_t smem_u32(const void* p) {
    return (uint32_t)__cvta_generic_to_shared(p);
}
__device__ __forceinline__ void cpasync16(uint32_t s, const void* g) {
    asm volatile("cp.async.cg.shared.global [%0], [%1], 16;" :: "r"(s), "l"(g));
}
__device__ __forceinline__ void cp_commit() {
    asm volatile("cp.async.commit_group;" ::: "memory");
}
template<int N> __device__ __forceinline__ void cp_wait() {
    asm volatile("cp.async.wait_group %0;" :: "n"(N) : "memory");
}
__device__ __forceinline__ void ldsm_x4(uint32_t* r, uint32_t a) {
    asm volatile("ldmatrix.sync.aligned.m8n8.x4.shared.b16 {%0,%1,%2,%3}, [%4];"
                 : "=r"(r[0]), "=r"(r[1]), "=r"(r[2]), "=r"(r[3]) : "r"(a));
}
__device__ __forceinline__ void ldsm_x4_t(uint32_t* r, uint32_t a) {
    asm volatile("ldmatrix.sync.aligned.m8n8.x4.trans.shared.b16 {%0,%1,%2,%3}, [%4];"
                 : "=r"(r[0]), "=r"(r[1]), "=r"(r[2]), "=r"(r[3]) : "r"(a));
}
__device__ __forceinline__ void ldsm_x2(uint32_t* r, uint32_t a) {
    asm volatile("ldmatrix.sync.aligned.m8n8.x2.shared.b16 {%0,%1}, [%2];"
                 : "=r"(r[0]), "=r"(r[1]) : "r"(a));
}
__device__ __forceinline__ void mma16816(float* d, const uint32_t* a, const uint32_t* b) {
    asm volatile(
        "mma.sync.aligned.m16n8k16.row.col.f32.bf16.bf16.f32 "
        "{%0,%1,%2,%3}, {%4,%5,%6,%7}, {%8,%9}, {%0,%1,%2,%3};"
        : "+f"(d[0]), "+f"(d[1]), "+f"(d[2]), "+f"(d[3])
        : "r"(a[0]), "r"(a[1]), "r"(a[2]), "r"(a[3]), "r"(b[0]), "r"(b[1]));
}
__device__ __forceinline__ void mma16816h(float* d, const uint32_t* a, const uint32_t* b) {
    asm volatile(
        "mma.sync.aligned.m16n8k16.row.col.f32.f16.f16.f32 "
        "{%0,%1,%2,%3}, {%4,%5,%6,%7}, {%8,%9}, {%0,%1,%2,%3};"
        : "+f"(d[0]), "+f"(d[1]), "+f"(d[2]), "+f"(d[3])
        : "r"(a[0]), "r"(a[1]), "r"(a[2]), "r"(a[3]), "r"(b[0]), "r"(b[1]));
}
__device__ __forceinline__ uint32_t pk2(__nv_bfloat16 a, __nv_bfloat16 b) {
    return (uint32_t)__bfloat16_as_ushort(a) | ((uint32_t)__bfloat16_as_ushort(b) << 16);
}
__device__ __forceinline__ void split2(float x, float y, uint32_t& hi, uint32_t& lo) {
    __nv_bfloat162 h2 = __floats2bfloat162_rn(x, y);
    float lx = x - __bfloat162float(h2.x);
    float ly = y - __bfloat162float(h2.y);
    __nv_bfloat162 l2 = __floats2bfloat162_rn(lx, ly);
    hi = *reinterpret_cast<uint32_t*>(&h2);
    lo = *reinterpret_cast<uint32_t*>(&l2);
}
__device__ __forceinline__ void split2h(float x, float y, uint32_t& hi, uint32_t& lo) {
    __half2 h2 = __floats2half2_rn(x, y);
    float lx = x - __half2float(__low2half(h2));
    float ly = y - __half2float(__high2half(h2));
    __half2 l2 = __floats2half2_rn(lx, ly);
    hi = *reinterpret_cast<uint32_t*>(&h2);
    lo = *reinterpret_cast<uint32_t*>(&l2);
}

// 128B rows, 8x16B chunks, swizzle chunk' = chunk ^ (row & 7)
#define FOFF(r, c) ((uint32_t)((r) * 128 + ((((c) ^ ((r) & 7))) << 4)))

// ---------------- weight rearrange + bf16 split ----------------
__global__ void rearrange_w(const float* __restrict__ Wq, const float* __restrict__ Wk,
                            const float* __restrict__ Wv, const float* __restrict__ Wo) {
    int idx = blockIdx.x * blockDim.x + threadIdx.x;
    if (idx >= D_ * D_) return;
    int n = idx / D_;
    int k = idx % D_;
    int h = n >> 6, dk = n & 63;
    float w[4];
    w[0] = Wq[((size_t)h * D_ + k) * DK_ + dk];
    w[1] = Wk[((size_t)h * D_ + k) * DK_ + dk];
    w[2] = Wv[((size_t)h * D_ + k) * DK_ + dk];
    w[3] = Wo[(size_t)n * D_ + k];
    #pragma unroll
    for (int j = 0; j < 4; ++j) {
        __nv_bfloat16 hi = __float2bfloat16(w[j]);
        float lo = w[j] - __bfloat162float(hi);
        g_wh[j * D_ * D_ + idx] = hi;
        g_wl[j * D_ * D_ + idx] = __float2bfloat16(lo);
    }
}

// ---------------- activation bf16 split ----------------
__global__ void split_bf16(const float* __restrict__ x,
                           __nv_bfloat16* __restrict__ hi, __nv_bfloat16* __restrict__ lo) {
    int i = blockIdx.x * blockDim.x + threadIdx.x;
    float4 v = ((const float4*)x)[i];
    __nv_bfloat16 h0 = __float2bfloat16(v.x), h1 = __float2bfloat16(v.y),
                  h2 = __float2bfloat16(v.z), h3 = __float2bfloat16(v.w);
    __nv_bfloat16 l0 = __float2bfloat16(v.x - __bfloat162float(h0));
    __nv_bfloat16 l1 = __float2bfloat16(v.y - __bfloat162float(h1));
    __nv_bfloat16 l2 = __float2bfloat16(v.z - __bfloat162float(h2));
    __nv_bfloat16 l3 = __float2bfloat16(v.w - __bfloat162float(h3));
    ((uint2*)hi)[i] = make_uint2(pk2(h0, h1), pk2(h2, h3));
    ((uint2*)lo)[i] = make_uint2(pk2(l0, l1), pk2(l2, l3));
}

// ---------------- mma.sync split-bf16 GEMM (BK=64, 3-stage) ----------------
// MODE 0: fp32 C.  MODE 1: head-major fp16 (single, scaled).  MODE 2: head-major fp16 hi/lo.
#define GBM 128
#define GBN 128
#define GBK 64
#define GTILE 16384
#define GSTAGE (4 * GTILE)
#define GEMM_SMEM (3 * GSTAGE)

template<int MODE>
__global__ __launch_bounds__(256, 1)
void gemm_mma(const __nv_bfloat16* __restrict__ Ah, const __nv_bfloat16* __restrict__ Al,
              const __nv_bfloat16* __restrict__ Bh, const __nv_bfloat16* __restrict__ Bl,
              float* __restrict__ Cf,
              __half* __restrict__ Ch1, __half* __restrict__ Ch2,
              float scale) {
    extern __shared__ char smraw[];
    const uint32_t sb = smem_u32(smraw);
    const int tid = threadIdx.x;
    const int wid = tid >> 5, lane = tid & 31;
    const int bm = blockIdx.y * GBM;
    const int bn = blockIdx.x * GBN;
    const int warp_m = (wid & 1) * 64;
    const int warp_n = (wid >> 1) * 32;

    uint32_t soff[4];
    const __nv_bfloat16 *pA[4], *pAl[4], *pB[4], *pBl[4];
    #pragma unroll
    for (int i = 0; i < 4; ++i) {
        int lin = i * 256 + tid;
        int row = lin >> 3, c = lin & 7;
        soff[i] = FOFF(row, c);
        pA[i]  = Ah + (size_t)(bm + row) * D_ + c * 8;
        pAl[i] = Al + (size_t)(bm + row) * D_ + c * 8;
        pB[i]  = Bh + (size_t)(bn + row) * D_ + c * 8;
        pBl[i] = Bl + (size_t)(bn + row) * D_ + c * 8;
    }

    auto prefetch = [&](int t) {
        uint32_t stg = sb + (t % 3) * GSTAGE;
        int kofs = t * GBK;
        #pragma unroll
        for (int i = 0; i < 4; ++i) {
            cpasync16(stg + soff[i],             pA[i]  + kofs);
            cpasync16(stg + GTILE + soff[i],     pAl[i] + kofs);
            cpasync16(stg + 2 * GTILE + soff[i], pB[i]  + kofs);
            cpasync16(stg + 3 * GTILE + soff[i], pBl[i] + kofs);
        }
    };

    prefetch(0); cp_commit();
    prefetch(1); cp_commit();

    const int arow = warp_m + (lane & 15);
    const int brow = warp_n + (lane & 7);
    float acc[4][4][4] = {};

    const int NT = D_ / GBK;   // 16
    for (int t = 0; t < NT; ++t) {
        if (t == NT - 1) cp_wait<0>(); else cp_wait<1>();
        __syncthreads();
        if (t + 2 < NT) { prefetch(t + 2); cp_commit(); }
        uint32_t stg = sb + (t % 3) * GSTAGE;

        #pragma unroll
        for (int kk = 0; kk < 4; ++kk) {
            uint32_t ao = FOFF(arow, kk * 2 + (lane >> 4));
            uint32_t bo = FOFF(brow, kk * 2 + ((lane >> 3) & 1));
            uint32_t ah4[4][4], al4[4][4], bh2[4][2], bl2[4][2];
            #pragma unroll
            for (int mb = 0; mb < 4; ++mb) {
                ldsm_x4(ah4[mb], stg + ao + mb * 2048);
                ldsm_x4(al4[mb], stg + GTILE + ao + mb * 2048);
            }
            #pragma unroll
            for (int nb = 0; nb < 4; ++nb) {
                ldsm_x2(bh2[nb], stg + 2 * GTILE + bo + nb * 1024);
                ldsm_x2(bl2[nb], stg + 3 * GTILE + bo + nb * 1024);
            }
            #pragma unroll
            for (int mb = 0; mb < 4; ++mb)
                #pragma unroll
                for (int nb = 0; nb < 4; ++nb)
                    mma16816(acc[mb][nb], ah4[mb], bh2[nb]);
            #pragma unroll
            for (int mb = 0; mb < 4; ++mb)
                #pragma unroll
                for (int nb = 0; nb < 4; ++nb)
                    mma16816(acc[mb][nb], al4[mb], bh2[nb]);
            #pragma unroll
            for (int mb = 0; mb < 4; ++mb)
                #pragma unroll
                for (int nb = 0; nb < 4; ++nb)
                    mma16816(acc[mb][nb], ah4[mb], bl2[nb]);
        }
    }

    const int tm = bm + warp_m + (lane >> 2);
    const int tn = bn + warp_n + (lane & 3) * 2;
    if (MODE == 0) {
        #pragma unroll
        for (int mb = 0; mb < 4; ++mb)
            #pragma unroll
            for (int nb = 0; nb < 4; ++nb) {
                float* c0 = Cf + (size_t)(tm + mb * 16) * D_ + tn + nb * 8;
                *(float2*)c0 = make_float2(acc[mb][nb][0], acc[mb][nb][1]);
                float* c1 = c0 + 8 * D_;
                *(float2*)c1 = make_float2(acc[mb][nb][2], acc[mb][nb][3]);
            }
    } else {
        #pragma unroll
        for (int mb = 0; mb < 4; ++mb)
            #pragma unroll
            for (int nb = 0; nb < 4; ++nb) {
                int n = tn + nb * 8;
                int h = n >> 6, dk = n & 63;
                #pragma unroll
                for (int hh = 0; hh < 2; ++hh) {
                    int row = tm + mb * 16 + hh * 8;
                    int b = row >> 11, s = row & 2047;
                    size_t idx = (((size_t)b * H_ + h) * S_ + s) * 64 + dk;
                    float x = acc[mb][nb][hh * 2] * scale;
                    float y = acc[mb][nb][hh * 2 + 1] * scale;
                    if (MODE == 1) {
                        __half2 p = __floats2half2_rn(x, y);
                        *(uint32_t*)(Ch1 + idx) = *reinterpret_cast<uint32_t*>(&p);
                    } else {
                        uint32_t hi, lo;
                        split2h(x, y, hi, lo);
                        *(uint32_t*)(Ch1 + idx) = hi;
                        *(uint32_t*)(Ch2 + idx) = lo;
                    }
                }
            }
    }
}

// ---------------- flash attention fp16 (QK 1-term, PV 3-term) ----------------
// smem: Q 16K + 3 KV stages of 24K (K 8K, Vh 8K, Vl 8K) = 88K
#define KVSTG 24576
#define FLASH_SMEM (16384 + 3 * KVSTG)

__global__ __launch_bounds__(256, 1)
void flash_fp16(const __half* __restrict__ qf, const __half* __restrict__ kf,
                const __half* __restrict__ vh, const __half* __restrict__ vl,
                __nv_bfloat16* __restrict__ aoh, __nv_bfloat16* __restrict__ aol) {
    extern __shared__ char smraw[];
    const uint32_t sb = smem_u32(smraw);
    const int tid = threadIdx.x;
    const int wid = tid >> 5, lane = tid & 31;
    const int bh = blockIdx.y;
    const int s0 = blockIdx.x * 128;

    const size_t hb = (size_t)bh * S_ * 64;
    const __half* qp = qf + hb + (size_t)s0 * 64;
    const __half* kp = kf + hb;
    const __half* vhp = vh + hb;
    const __half* vlp = vl + hb;

    // Q tile (group 0): 128 rows x 128B
    #pragma unroll
    for (int i = 0; i < 4; ++i) {
        int lin = i * 256 + tid;
        int r = lin >> 3, c = lin & 7;
        cpasync16(sb + FOFF(r, c), qp + r * 64 + c * 8);
    }
    auto kvload = [&](int t) {
        uint32_t stg = sb + 16384 + (t % 3) * KVSTG;
        size_t tofs = (size_t)(t * 64) * 64;
        #pragma unroll
        for (int i = 0; i < 2; ++i) {
            int lin = i * 256 + tid;
            int r = lin >> 3, c = lin & 7;
            uint32_t o = FOFF(r, c);
            size_t g = tofs + r * 64 + c * 8;
            cpasync16(stg + o,         kp  + g);
            cpasync16(stg + 8192 + o,  vhp + g);
            cpasync16(stg + 16384 + o, vlp + g);
        }
    };
    kvload(0); cp_commit();
    kvload(1); cp_commit();

    const int warp_m = wid * 16;
    uint32_t qfr[4][4];
    float Oacc[8][4] = {};
    float m0 = -1e30f, m1 = -1e30f, l0 = 0.f, l1 = 0.f;

    const int NT = S_ / 64;   // 32
    for (int t = 0; t < NT; ++t) {
        if (t == NT - 1) cp_wait<0>(); else cp_wait<1>();
        __syncthreads();
        if (t + 2 < NT) { kvload(t + 2); cp_commit(); }
        uint32_t stg = sb + 16384 + (t % 3) * KVSTG;

        if (t == 0) {
            #pragma unroll
            for (int kb = 0; kb < 4; ++kb) {
                int r = warp_m + (lane & 15);
                int c = kb * 2 + (lane >> 4);
                ldsm_x4(qfr[kb], sb + FOFF(r, c));
            }
        }

        // ---- S = Q K^T (raw fp16, 1 term) ----
        float sacc[8][4] = {};
        #pragma unroll
        for (int kb = 0; kb < 4; ++kb) {
            #pragma unroll
            for (int nbp = 0; nbp < 4; ++nbp) {
                int r = nbp * 16 + ((lane >> 4) << 3) + (lane & 7);
                int c = kb * 2 + ((lane >> 3) & 1);
                uint32_t khf[4];
                ldsm_x4(khf, stg + FOFF(r, c));
                mma16816h(sacc[2 * nbp],     qfr[kb], khf);
                mma16816h(sacc[2 * nbp + 1], qfr[kb], khf + 2);
            }
        }

        // ---- online softmax ----
        float mx0 = -1e30f, mx1 = -1e30f;
        #pragma unroll
        for (int nb = 0; nb < 8; ++nb) {
            mx0 = fmaxf(mx0, fmaxf(sacc[nb][0], sacc[nb][1]));
            mx1 = fmaxf(mx1, fmaxf(sacc[nb][2], sacc[nb][3]));
        }
        mx0 = fmaxf(mx0, __shfl_xor_sync(0xffffffffu, mx0, 1));
        mx0 = fmaxf(mx0, __shfl_xor_sync(0xffffffffu, mx0, 2));
        mx1 = fmaxf(mx1, __shfl_xor_sync(0xffffffffu, mx1, 1));
        mx1 = fmaxf(mx1, __shfl_xor_sync(0xffffffffu, mx1, 2));
        float mn0 = fmaxf(m0, mx0), mn1 = fmaxf(m1, mx1);
        float c0 = __expf(m0 - mn0), c1 = __expf(m1 - mn1);
        float sum0 = 0.f, sum1 = 0.f;
        #pragma unroll
        for (int nb = 0; nb < 8; ++nb) {
            sacc[nb][0] = __expf(sacc[nb][0] - mn0); sum0 += sacc[nb][0];
            sacc[nb][1] = __expf(sacc[nb][1] - mn0); sum0 += sacc[nb][1];
            sacc[nb][2] = __expf(sacc[nb][2] - mn1); sum1 += sacc[nb][2];
            sacc[nb][3] = __expf(sacc[nb][3] - mn1); sum1 += sacc[nb][3];
        }
        sum0 += __shfl_xor_sync(0xffffffffu, sum0, 1);
        sum0 += __shfl_xor_sync(0xffffffffu, sum0, 2);
        sum1 += __shfl_xor_sync(0xffffffffu, sum1, 1);
        sum1 += __shfl_xor_sync(0xffffffffu, sum1, 2);
        l0 = l0 * c0 + sum0;
        l1 = l1 * c1 + sum1;
        m0 = mn0; m1 = mn1;
        #pragma unroll
        for (int nb = 0; nb < 8; ++nb) {
            Oacc[nb][0] *= c0; Oacc[nb][1] *= c0;
            Oacc[nb][2] *= c1; Oacc[nb][3] *= c1;
        }

        // ---- P -> split fp16 fragments ----
        uint32_t phf[4][4], plf[4][4];
        #pragma unroll
        for (int kb = 0; kb < 4; ++kb) {
            split2h(sacc[2 * kb][0],     sacc[2 * kb][1],     phf[kb][0], plf[kb][0]);
            split2h(sacc[2 * kb][2],     sacc[2 * kb][3],     phf[kb][1], plf[kb][1]);
            split2h(sacc[2 * kb + 1][0], sacc[2 * kb + 1][1], phf[kb][2], plf[kb][2]);
            split2h(sacc[2 * kb + 1][2], sacc[2 * kb + 1][3], phf[kb][3], plf[kb][3]);
        }

        // ---- O += P V (fp16 3-term, trans V) ----
        #pragma unroll
        for (int kb = 0; kb < 4; ++kb) {
            #pragma unroll
            for (int nbp = 0; nbp < 4; ++nbp) {
                int r = kb * 16 + (((lane >> 3) & 1) << 3) + (lane & 7);
                int c = nbp * 2 + (lane >> 4);
                uint32_t vhf[4], vlf[4];
                ldsm_x4_t(vhf, stg + 8192 + FOFF(r, c));
                ldsm_x4_t(vlf, stg + 16384 + FOFF(r, c));
                mma16816h(Oacc[2 * nbp],     phf[kb], vhf);
                mma16816h(Oacc[2 * nbp + 1], phf[kb], vhf + 2);
                mma16816h(Oacc[2 * nbp],     plf[kb], vhf);
                mma16816h(Oacc[2 * nbp + 1], plf[kb], vhf + 2);
                mma16816h(Oacc[2 * nbp],     phf[kb], vlf);
                mma16816h(Oacc[2 * nbp + 1], phf[kb], vlf + 2);
            }
        }
    }

    // ---- epilogue: normalize, split to bf16 hi/lo for Wo GEMM ----
    float inv0 = 1.f / l0, inv1 = 1.f / l1;
    int b = bh >> 4, h = bh & 15;
    int r0 = s0 + warp_m + (lane >> 2);
    size_t base0 = ((size_t)b * S_ + r0) * D_ + h * 64 + (lane & 3) * 2;
    size_t base1 = base0 + 8 * D_;
    #pragma unroll
    for (int nb = 0; nb < 8; ++nb) {
        uint32_t hi, lo;
        split2(Oacc[nb][0] * inv0, Oacc[nb][1] * inv0, hi, lo);
        *(uint32_t*)(aoh + base0 + nb * 8) = hi;
        *(uint32_t*)(aol + base0 + nb * 8) = lo;
        split2(Oacc[nb][2] * inv1, Oacc[nb][3] * inv1, hi, lo);
        *(uint32_t*)(aoh + base1 + nb * 8) = hi;
        *(uint32_t*)(aol + base1 + nb * 8) = lo;
    }
}

// ---------------- launch ----------------
extern "C" void kernel_launch(void* const* d_in, const int* in_sizes, int n_in,
                              void* d_out, int out_size) {
    const float* query = (const float*)d_in[0];
    const float* key   = (const float*)d_in[1];
    const float* value = (const float*)d_in[2];
    const float* Wq    = (const float*)d_in[3];
    const float* Wk    = (const float*)d_in[4];
    const float* Wv    = (const float*)d_in[5];
    const float* Wo    = (const float*)d_in[6];
    float* out = (float*)d_out;

    __nv_bfloat16 *ah, *al, *wh, *wl, *aoh, *aol;
    __half *qf, *kf, *vh16, *vl16;
    cudaGetSymbolAddress((void**)&ah,   g_ah);
    cudaGetSymbolAddress((void**)&al,   g_al);
    cudaGetSymbolAddress((void**)&wh,   g_wh);
    cudaGetSymbolAddress((void**)&wl,   g_wl);
    cudaGetSymbolAddress((void**)&qf,   g_qf);
    cudaGetSymbolAddress((void**)&kf,   g_kf);
    cudaGetSymbolAddress((void**)&vh16, g_vh16);
    cudaGetSymbolAddress((void**)&vl16, g_vl16);
    cudaGetSymbolAddress((void**)&aoh,  g_aoh);
    cudaGetSymbolAddress((void**)&aol,  g_aol);

    cudaFuncSetAttribute(gemm_mma<0>, cudaFuncAttributeMaxDynamicSharedMemorySize, GEMM_SMEM);
    cudaFuncSetAttribute(gemm_mma<1>, cudaFuncAttributeMaxDynamicSharedMemorySize, GEMM_SMEM);
    cudaFuncSetAttribute(gemm_mma<2>, cudaFuncAttributeMaxDynamicSharedMemorySize, GEMM_SMEM);
    cudaFuncSetAttribute(flash_fp16, cudaFuncAttributeMaxDynamicSharedMemorySize, FLASH_SMEM);

    rearrange_w<<<(D_ * D_ + 255) / 256, 256>>>(Wq, Wk, Wv, Wo);

    dim3 ggrid(D_ / GBN, M_ / GBM);   // (8, 128)
    int splitBlocks = (M_ * D_ / 4) / 256;

    split_bf16<<<splitBlocks, 256>>>(query, ah, al);
    gemm_mma<1><<<ggrid, 256, GEMM_SMEM>>>(ah, al, wh + 0 * D_ * D_, wl + 0 * D_ * D_,
                                           nullptr, qf, nullptr, 0.03125f);
    split_bf16<<<splitBlocks, 256>>>(key, ah, al);
    gemm_mma<1><<<ggrid, 256, GEMM_SMEM>>>(ah, al, wh + 1 * D_ * D_, wl + 1 * D_ * D_,
                                           nullptr, kf, nullptr, 1.0f);
    split_bf16<<<splitBlocks, 256>>>(value, ah, al);
    gemm_mma<2><<<ggrid, 256, GEMM_SMEM>>>(ah, al, wh + 2 * D_ * D_, wl + 2 * D_ * D_,
                                           nullptr, vh16, vl16, 1.0f);

    dim3 fgrid(S_ / 128, B_ * H_);
    flash_fp16<<<fgrid, 256, FLASH_SMEM>>>(qf, kf, vh16, vl16, aoh, aol);

    gemm_mma<0><<<ggrid, 256, GEMM_SMEM>>>(aoh, aol, wh + 3 * D_ * D_, wl + 3 * D_ * D_,
                                           out, nullptr, nullptr, 1.0f);
}

// round 7
// speedup vs baseline: 4.4324x; 1.1108x over previous
#include <cuda_runtime.h>
#include <cuda_bf16.h>
#include <cuda_fp16.h>
#include <stdint.h>
#include <math.h>

#define B_  8
#define S_  2048
#define D_  1024
#define H_  16
#define DK_ 64
#define M_  (B_*S_)   // 16384

// ---------------- scratch (device globals: allocation-free) ----------------
__device__ __nv_bfloat16 g_ah[M_ * D_];
__device__ __nv_bfloat16 g_al[M_ * D_];
__device__ __nv_bfloat16 g_wh[4 * D_ * D_];  // weights hi, [N][K]: q,k,v,o
__device__ __nv_bfloat16 g_wl[4 * D_ * D_];
__device__ __half g_qf[M_ * D_];             // head-major fp16 q (scale folded)
__device__ __half g_kf[M_ * D_];             // head-major fp16 k
__device__ __half g_vh16[M_ * D_];           // head-major fp16 v hi
__device__ __half g_vl16[M_ * D_];           // head-major fp16 v lo
__device__ __nv_bfloat16 g_aoh[M_ * D_];     // attention out split (feeds Wo)
__device__ __nv_bfloat16 g_aol[M_ * D_];

// ---------------- helpers ----------------
__device__ __forceinline__ uint32_t smem_u32(const void* p) {
    return (uint32_t)__cvta_generic_to_shared(p);
}
__device__ __forceinline__ void cpasync16(uint32_t s, const void* g) {
    asm volatile("cp.async.cg.shared.global [%0], [%1], 16;" :: "r"(s), "l"(g));
}
__device__ __forceinline__ void cp_commit() {
    asm volatile("cp.async.commit_group;" ::: "memory");
}
template<int N> __device__ __forceinline__ void cp_wait() {
    asm volatile("cp.async.wait_group %0;" :: "n"(N) : "memory");
}
__device__ __forceinline__ void ldsm_x4(uint32_t* r, uint32_t a) {
    asm volatile("ldmatrix.sync.aligned.m8n8.x4.shared.b16 {%0,%1,%2,%3}, [%4];"
                 : "=r"(r[0]), "=r"(r[1]), "=r"(r[2]), "=r"(r[3]) : "r"(a));
}
__device__ __forceinline__ void ldsm_x4_t(uint32_t* r, uint32_t a) {
    asm volatile("ldmatrix.sync.aligned.m8n8.x4.trans.shared.b16 {%0,%1,%2,%3}, [%4];"
                 : "=r"(r[0]), "=r"(r[1]), "=r"(r[2]), "=r"(r[3]) : "r"(a));
}
__device__ __forceinline__ void ldsm_x2(uint32_t* r, uint32_t a) {
    asm volatile("ldmatrix.sync.aligned.m8n8.x2.shared.b16 {%0,%1}, [%2];"
                 : "=r"(r[0]), "=r"(r[1]) : "r"(a));
}
__device__ __forceinline__ void mma16816(float* d, const uint32_t* a, const uint32_t* b) {
    asm volatile(
        "mma.sync.aligned.m16n8k16.row.col.f32.bf16.bf16.f32 "
        "{%0,%1,%2,%3}, {%4,%5,%6,%7}, {%8,%9}, {%0,%1,%2,%3};"
        : "+f"(d[0]), "+f"(d[1]), "+f"(d[2]), "+f"(d[3])
        : "r"(a[0]), "r"(a[1]), "r"(a[2]), "r"(a[3]), "r"(b[0]), "r"(b[1]));
}
__device__ __forceinline__ void mma16816h(float* d, const uint32_t* a, const uint32_t* b) {
    asm volatile(
        "mma.sync.aligned.m16n8k16.row.col.f32.f16.f16.f32 "
        "{%0,%1,%2,%3}, {%4,%5,%6,%7}, {%8,%9}, {%0,%1,%2,%3};"
        : "+f"(d[0]), "+f"(d[1]), "+f"(d[2]), "+f"(d[3])
        : "r"(a[0]), "r"(a[1]), "r"(a[2]), "r"(a[3]), "r"(b[0]), "r"(b[1]));
}
__device__ __forceinline__ uint32_t pk2(__nv_bfloat16 a, __nv_bfloat16 b) {
    return (uint32_t)__bfloat16_as_ushort(a) | ((uint32_t)__bfloat16_as_ushort(b) << 16);
}
__device__ __forceinline__ void split2(float x, float y, uint32_t& hi, uint32_t& lo) {
    __nv_bfloat162 h2 = __floats2bfloat162_rn(x, y);
    float lx = x - __bfloat162float(h2.x);
    float ly = y - __bfloat162float(h2.y);
    __nv_bfloat162 l2 = __floats2bfloat162_rn(lx, ly);
    hi = *reinterpret_cast<uint32_t*>(&h2);
    lo = *reinterpret_cast<uint32_t*>(&l2);
}
__device__ __forceinline__ void split2h(float x, float y, uint32_t& hi, uint32_t& lo) {
    __half2 h2 = __floats2half2_rn(x, y);
    float lx = x - __half2float(__low2half(h2));
    float ly = y - __half2float(__high2half(h2));
    __half2 l2 = __floats2half2_rn(lx, ly);
    hi = *reinterpret_cast<uint32_t*>(&h2);
    lo = *reinterpret_cast<uint32_t*>(&l2);
}

// 128B rows, 8x16B chunks, swizzle chunk' = chunk ^ (row & 7)
#define FOFF(r, c) ((uint32_t)((r) * 128 + ((((c) ^ ((r) & 7))) << 4)))

// ---------------- weight rearrange + bf16 split ----------------
__global__ void rearrange_w(const float* __restrict__ Wq, const float* __restrict__ Wk,
                            const float* __restrict__ Wv, const float* __restrict__ Wo) {
    int idx = blockIdx.x * blockDim.x + threadIdx.x;
    if (idx >= D_ * D_) return;
    int n = idx / D_;
    int k = idx % D_;
    int h = n >> 6, dk = n & 63;
    float w[4];
    w[0] = Wq[((size_t)h * D_ + k) * DK_ + dk];
    w[1] = Wk[((size_t)h * D_ + k) * DK_ + dk];
    w[2] = Wv[((size_t)h * D_ + k) * DK_ + dk];
    w[3] = Wo[(size_t)n * D_ + k];
    #pragma unroll
    for (int j = 0; j < 4; ++j) {
        __nv_bfloat16 hi = __float2bfloat16(w[j]);
        float lo = w[j] - __bfloat162float(hi);
        g_wh[j * D_ * D_ + idx] = hi;
        g_wl[j * D_ * D_ + idx] = __float2bfloat16(lo);
    }
}

// ---------------- activation bf16 split ----------------
__global__ void split_bf16(const float* __restrict__ x,
                           __nv_bfloat16* __restrict__ hi, __nv_bfloat16* __restrict__ lo) {
    int i = blockIdx.x * blockDim.x + threadIdx.x;
    float4 v = ((const float4*)x)[i];
    __nv_bfloat16 h0 = __float2bfloat16(v.x), h1 = __float2bfloat16(v.y),
                  h2 = __float2bfloat16(v.z), h3 = __float2bfloat16(v.w);
    __nv_bfloat16 l0 = __float2bfloat16(v.x - __bfloat162float(h0));
    __nv_bfloat16 l1 = __float2bfloat16(v.y - __bfloat162float(h1));
    __nv_bfloat16 l2 = __float2bfloat16(v.z - __bfloat162float(h2));
    __nv_bfloat16 l3 = __float2bfloat16(v.w - __bfloat162float(h3));
    ((uint2*)hi)[i] = make_uint2(pk2(h0, h1), pk2(h2, h3));
    ((uint2*)lo)[i] = make_uint2(pk2(l0, l1), pk2(l2, l3));
}

// ---------------- mma.sync split-bf16 GEMM (BK=64, 3-stage) ----------------
// MODE 0: fp32 C.  MODE 1: head-major fp16 (single, scaled).  MODE 2: head-major fp16 hi/lo.
// TERMS 3: Ah*Bh + Al*Bh + Ah*Bl.  TERMS 2: Ah*Bh + Al*Bh (Bl never touched).
#define GBM 128
#define GBN 128
#define GBK 64
#define GTILE 16384
#define GSTAGE (4 * GTILE)
#define GEMM_SMEM (3 * GSTAGE)

template<int MODE, int TERMS>
__global__ __launch_bounds__(256, 1)
void gemm_mma(const __nv_bfloat16* __restrict__ Ah, const __nv_bfloat16* __restrict__ Al,
              const __nv_bfloat16* __restrict__ Bh, const __nv_bfloat16* __restrict__ Bl,
              float* __restrict__ Cf,
              __half* __restrict__ Ch1, __half* __restrict__ Ch2,
              float scale) {
    extern __shared__ char smraw[];
    const uint32_t sb = smem_u32(smraw);
    const int tid = threadIdx.x;
    const int wid = tid >> 5, lane = tid & 31;
    const int bm = blockIdx.y * GBM;
    const int bn = blockIdx.x * GBN;
    const int warp_m = (wid & 1) * 64;
    const int warp_n = (wid >> 1) * 32;

    uint32_t soff[4];
    const __nv_bfloat16 *pA[4], *pAl[4], *pB[4], *pBl[4];
    #pragma unroll
    for (int i = 0; i < 4; ++i) {
        int lin = i * 256 + tid;
        int row = lin >> 3, c = lin & 7;
        soff[i] = FOFF(row, c);
        pA[i]  = Ah + (size_t)(bm + row) * D_ + c * 8;
        pAl[i] = Al + (size_t)(bm + row) * D_ + c * 8;
        pB[i]  = Bh + (size_t)(bn + row) * D_ + c * 8;
        pBl[i] = Bl + (size_t)(bn + row) * D_ + c * 8;
    }

    auto prefetch = [&](int t) {
        uint32_t stg = sb + (t % 3) * GSTAGE;
        int kofs = t * GBK;
        #pragma unroll
        for (int i = 0; i < 4; ++i) {
            cpasync16(stg + soff[i],             pA[i]  + kofs);
            cpasync16(stg + GTILE + soff[i],     pAl[i] + kofs);
            cpasync16(stg + 2 * GTILE + soff[i], pB[i]  + kofs);
            if (TERMS == 3)
                cpasync16(stg + 3 * GTILE + soff[i], pBl[i] + kofs);
        }
    };

    prefetch(0); cp_commit();
    prefetch(1); cp_commit();

    const int arow = warp_m + (lane & 15);
    const int brow = warp_n + (lane & 7);
    float acc[4][4][4] = {};

    const int NT = D_ / GBK;   // 16
    for (int t = 0; t < NT; ++t) {
        if (t == NT - 1) cp_wait<0>(); else cp_wait<1>();
        __syncthreads();
        if (t + 2 < NT) { prefetch(t + 2); cp_commit(); }
        uint32_t stg = sb + (t % 3) * GSTAGE;

        #pragma unroll
        for (int kk = 0; kk < 4; ++kk) {
            uint32_t ao = FOFF(arow, kk * 2 + (lane >> 4));
            uint32_t bo = FOFF(brow, kk * 2 + ((lane >> 3) & 1));
            uint32_t ah4[4][4], al4[4][4], bh2[4][2], bl2[4][2];
            #pragma unroll
            for (int mb = 0; mb < 4; ++mb) {
                ldsm_x4(ah4[mb], stg + ao + mb * 2048);
                ldsm_x4(al4[mb], stg + GTILE + ao + mb * 2048);
            }
            #pragma unroll
            for (int nb = 0; nb < 4; ++nb) {
                ldsm_x2(bh2[nb], stg + 2 * GTILE + bo + nb * 1024);
                if (TERMS == 3)
                    ldsm_x2(bl2[nb], stg + 3 * GTILE + bo + nb * 1024);
            }
            #pragma unroll
            for (int mb = 0; mb < 4; ++mb)
                #pragma unroll
                for (int nb = 0; nb < 4; ++nb)
                    mma16816(acc[mb][nb], ah4[mb], bh2[nb]);
            #pragma unroll
            for (int mb = 0; mb < 4; ++mb)
                #pragma unroll
                for (int nb = 0; nb < 4; ++nb)
                    mma16816(acc[mb][nb], al4[mb], bh2[nb]);
            if (TERMS == 3) {
                #pragma unroll
                for (int mb = 0; mb < 4; ++mb)
                    #pragma unroll
                    for (int nb = 0; nb < 4; ++nb)
                        mma16816(acc[mb][nb], ah4[mb], bl2[nb]);
            }
        }
    }

    const int tm = bm + warp_m + (lane >> 2);
    const int tn = bn + warp_n + (lane & 3) * 2;
    if (MODE == 0) {
        #pragma unroll
        for (int mb = 0; mb < 4; ++mb)
            #pragma unroll
            for (int nb = 0; nb < 4; ++nb) {
                float* c0 = Cf + (size_t)(tm + mb * 16) * D_ + tn + nb * 8;
                *(float2*)c0 = make_float2(acc[mb][nb][0], acc[mb][nb][1]);
                float* c1 = c0 + 8 * D_;
                *(float2*)c1 = make_float2(acc[mb][nb][2], acc[mb][nb][3]);
            }
    } else {
        #pragma unroll
        for (int mb = 0; mb < 4; ++mb)
            #pragma unroll
            for (int nb = 0; nb < 4; ++nb) {
                int n = tn + nb * 8;
                int h = n >> 6, dk = n & 63;
                #pragma unroll
                for (int hh = 0; hh < 2; ++hh) {
                    int row = tm + mb * 16 + hh * 8;
                    int b = row >> 11, s = row & 2047;
                    size_t idx = (((size_t)b * H_ + h) * S_ + s) * 64 + dk;
                    float x = acc[mb][nb][hh * 2] * scale;
                    float y = acc[mb][nb][hh * 2 + 1] * scale;
                    if (MODE == 1) {
                        __half2 p = __floats2half2_rn(x, y);
                        *(uint32_t*)(Ch1 + idx) = *reinterpret_cast<uint32_t*>(&p);
                    } else {
                        uint32_t hi, lo;
                        split2h(x, y, hi, lo);
                        *(uint32_t*)(Ch1 + idx) = hi;
                        *(uint32_t*)(Ch2 + idx) = lo;
                    }
                }
            }
    }
}

// ---------------- flash attention fp16 (QK 1-term, PV 3-term, KV tile 128) ----------------
// smem: Q 16K + 3 KV stages of 48K (K 16K, Vh 16K, Vl 16K) = 160K
#define KVSTG 49152
#define FLASH_SMEM (16384 + 3 * KVSTG)

__global__ __launch_bounds__(256, 1)
void flash_fp16(const __half* __restrict__ qf, const __half* __restrict__ kf,
                const __half* __restrict__ vh, const __half* __restrict__ vl,
                __nv_bfloat16* __restrict__ aoh, __nv_bfloat16* __restrict__ aol) {
    extern __shared__ char smraw[];
    const uint32_t sb = smem_u32(smraw);
    const int tid = threadIdx.x;
    const int wid = tid >> 5, lane = tid & 31;
    const int bh = blockIdx.y;
    const int s0 = blockIdx.x * 128;

    const size_t hb = (size_t)bh * S_ * 64;
    const __half* qp = qf + hb + (size_t)s0 * 64;
    const __half* kp = kf + hb;
    const __half* vhp = vh + hb;
    const __half* vlp = vl + hb;

    // Q tile (group 0): 128 rows x 128B
    #pragma unroll
    for (int i = 0; i < 4; ++i) {
        int lin = i * 256 + tid;
        int r = lin >> 3, c = lin & 7;
        cpasync16(sb + FOFF(r, c), qp + r * 64 + c * 8);
    }
    // KV tile: 128 rows x 64 fp16, K + Vh + Vl
    auto kvload = [&](int t) {
        uint32_t stg = sb + 16384 + (t % 3) * KVSTG;
        size_t tofs = (size_t)(t * 128) * 64;
        #pragma unroll
        for (int i = 0; i < 4; ++i) {
            int lin = i * 256 + tid;
            int r = lin >> 3, c = lin & 7;
            uint32_t o = FOFF(r, c);
            size_t g = tofs + r * 64 + c * 8;
            cpasync16(stg + o,         kp  + g);
            cpasync16(stg + 16384 + o, vhp + g);
            cpasync16(stg + 32768 + o, vlp + g);
        }
    };
    kvload(0); cp_commit();
    kvload(1); cp_commit();

    const int warp_m = wid * 16;
    uint32_t qfr[4][4];
    float Oacc[8][4] = {};
    float m0 = -1e30f, m1 = -1e30f, l0 = 0.f, l1 = 0.f;

    const int NT = S_ / 128;   // 16
    for (int t = 0; t < NT; ++t) {
        if (t == NT - 1) cp_wait<0>(); else cp_wait<1>();
        __syncthreads();
        if (t + 2 < NT) { kvload(t + 2); cp_commit(); }
        uint32_t stg = sb + 16384 + (t % 3) * KVSTG;

        if (t == 0) {
            #pragma unroll
            for (int kb = 0; kb < 4; ++kb) {
                int r = warp_m + (lane & 15);
                int c = kb * 2 + (lane >> 4);
                ldsm_x4(qfr[kb], sb + FOFF(r, c));
            }
        }

        // ---- S = Q K^T (raw fp16, 1 term), 16 n8-blocks ----
        float sacc[16][4] = {};
        #pragma unroll
        for (int kb = 0; kb < 4; ++kb) {
            #pragma unroll
            for (int nbp = 0; nbp < 8; ++nbp) {
                int r = nbp * 16 + ((lane >> 4) << 3) + (lane & 7);
                int c = kb * 2 + ((lane >> 3) & 1);
                uint32_t khf[4];
                ldsm_x4(khf, stg + FOFF(r, c));
                mma16816h(sacc[2 * nbp],     qfr[kb], khf);
                mma16816h(sacc[2 * nbp + 1], qfr[kb], khf + 2);
            }
        }

        // ---- online softmax ----
        float mx0 = -1e30f, mx1 = -1e30f;
        #pragma unroll
        for (int nb = 0; nb < 16; ++nb) {
            mx0 = fmaxf(mx0, fmaxf(sacc[nb][0], sacc[nb][1]));
            mx1 = fmaxf(mx1, fmaxf(sacc[nb][2], sacc[nb][3]));
        }
        mx0 = fmaxf(mx0, __shfl_xor_sync(0xffffffffu, mx0, 1));
        mx0 = fmaxf(mx0, __shfl_xor_sync(0xffffffffu, mx0, 2));
        mx1 = fmaxf(mx1, __shfl_xor_sync(0xffffffffu, mx1, 1));
        mx1 = fmaxf(mx1, __shfl_xor_sync(0xffffffffu, mx1, 2));
        float mn0 = fmaxf(m0, mx0), mn1 = fmaxf(m1, mx1);
        float c0 = __expf(m0 - mn0), c1 = __expf(m1 - mn1);
        float sum0 = 0.f, sum1 = 0.f;
        #pragma unroll
        for (int nb = 0; nb < 16; ++nb) {
            sacc[nb][0] = __expf(sacc[nb][0] - mn0); sum0 += sacc[nb][0];
            sacc[nb][1] = __expf(sacc[nb][1] - mn0); sum0 += sacc[nb][1];
            sacc[nb][2] = __expf(sacc[nb][2] - mn1); sum1 += sacc[nb][2];
            sacc[nb][3] = __expf(sacc[nb][3] - mn1); sum1 += sacc[nb][3];
        }
        sum0 += __shfl_xor_sync(0xffffffffu, sum0, 1);
        sum0 += __shfl_xor_sync(0xffffffffu, sum0, 2);
        sum1 += __shfl_xor_sync(0xffffffffu, sum1, 1);
        sum1 += __shfl_xor_sync(0xffffffffu, sum1, 2);
        l0 = l0 * c0 + sum0;
        l1 = l1 * c1 + sum1;
        m0 = mn0; m1 = mn1;
        #pragma unroll
        for (int nb = 0; nb < 8; ++nb) {
            Oacc[nb][0] *= c0; Oacc[nb][1] *= c0;
            Oacc[nb][2] *= c1; Oacc[nb][3] *= c1;
        }

        // ---- P -> split fp16 fragments (8 k-blocks of 16) ----
        uint32_t phf[8][4], plf[8][4];
        #pragma unroll
        for (int kb = 0; kb < 8; ++kb) {
            split2h(sacc[2 * kb][0],     sacc[2 * kb][1],     phf[kb][0], plf[kb][0]);
            split2h(sacc[2 * kb][2],     sacc[2 * kb][3],     phf[kb][1], plf[kb][1]);
            split2h(sacc[2 * kb + 1][0], sacc[2 * kb + 1][1], phf[kb][2], plf[kb][2]);
            split2h(sacc[2 * kb + 1][2], sacc[2 * kb + 1][3], phf[kb][3], plf[kb][3]);
        }

        // ---- O += P V (fp16 3-term, trans V) ----
        #pragma unroll
        for (int kb = 0; kb < 8; ++kb) {
            #pragma unroll
            for (int nbp = 0; nbp < 4; ++nbp) {
                int r = kb * 16 + (((lane >> 3) & 1) << 3) + (lane & 7);
                int c = nbp * 2 + (lane >> 4);
                uint32_t vhf[4], vlf[4];
                ldsm_x4_t(vhf, stg + 16384 + FOFF(r, c));
                ldsm_x4_t(vlf, stg + 32768 + FOFF(r, c));
                mma16816h(Oacc[2 * nbp],     phf[kb], vhf);
                mma16816h(Oacc[2 * nbp + 1], phf[kb], vhf + 2);
                mma16816h(Oacc[2 * nbp],     plf[kb], vhf);
                mma16816h(Oacc[2 * nbp + 1], plf[kb], vhf + 2);
                mma16816h(Oacc[2 * nbp],     phf[kb], vlf);
                mma16816h(Oacc[2 * nbp + 1], phf[kb], vlf + 2);
            }
        }
    }

    // ---- epilogue: normalize, split to bf16 hi/lo for Wo GEMM ----
    float inv0 = 1.f / l0, inv1 = 1.f / l1;
    int b = bh >> 4, h = bh & 15;
    int r0 = s0 + warp_m + (lane >> 2);
    size_t base0 = ((size_t)b * S_ + r0) * D_ + h * 64 + (lane & 3) * 2;
    size_t base1 = base0 + 8 * D_;
    #pragma unroll
    for (int nb = 0; nb < 8; ++nb) {
        uint32_t hi, lo;
        split2(Oacc[nb][0] * inv0, Oacc[nb][1] * inv0, hi, lo);
        *(uint32_t*)(aoh + base0 + nb * 8) = hi;
        *(uint32_t*)(aol + base0 + nb * 8) = lo;
        split2(Oacc[nb][2] * inv1, Oacc[nb][3] * inv1, hi, lo);
        *(uint32_t*)(aoh + base1 + nb * 8) = hi;
        *(uint32_t*)(aol + base1 + nb * 8) = lo;
    }
}

// ---------------- launch ----------------
extern "C" void kernel_launch(void* const* d_in, const int* in_sizes, int n_in,
                              void* d_out, int out_size) {
    const float* query = (const float*)d_in[0];
    const float* key   = (const float*)d_in[1];
    const float* value = (const float*)d_in[2];
    const float* Wq    = (const float*)d_in[3];
    const float* Wk    = (const float*)d_in[4];
    const float* Wv    = (const float*)d_in[5];
    const float* Wo    = (const float*)d_in[6];
    float* out = (float*)d_out;

    __nv_bfloat16 *ah, *al, *wh, *wl, *aoh, *aol;
    __half *qf, *kf, *vh16, *vl16;
    cudaGetSymbolAddress((void**)&ah,   g_ah);
    cudaGetSymbolAddress((void**)&al,   g_al);
    cudaGetSymbolAddress((void**)&wh,   g_wh);
    cudaGetSymbolAddress((void**)&wl,   g_wl);
    cudaGetSymbolAddress((void**)&qf,   g_qf);
    cudaGetSymbolAddress((void**)&kf,   g_kf);
    cudaGetSymbolAddress((void**)&vh16, g_vh16);
    cudaGetSymbolAddress((void**)&vl16, g_vl16);
    cudaGetSymbolAddress((void**)&aoh,  g_aoh);
    cudaGetSymbolAddress((void**)&aol,  g_aol);

    cudaFuncSetAttribute((const void*)gemm_mma<0,3>, cudaFuncAttributeMaxDynamicSharedMemorySize, GEMM_SMEM);
    cudaFuncSetAttribute((const void*)gemm_mma<1,2>, cudaFuncAttributeMaxDynamicSharedMemorySize, GEMM_SMEM);
    cudaFuncSetAttribute((const void*)gemm_mma<2,3>, cudaFuncAttributeMaxDynamicSharedMemorySize, GEMM_SMEM);
    cudaFuncSetAttribute((const void*)flash_fp16, cudaFuncAttributeMaxDynamicSharedMemorySize, FLASH_SMEM);

    rearrange_w<<<(D_ * D_ + 255) / 256, 256>>>(Wq, Wk, Wv, Wo);

    dim3 ggrid(D_ / GBN, M_ / GBM);   // (8, 128)
    int splitBlocks = (M_ * D_ / 4) / 256;

    // Q, K projections: 2-term (score path; loose error budget)
    split_bf16<<<splitBlocks, 256>>>(query, ah, al);
    gemm_mma<1,2><<<ggrid, 256, GEMM_SMEM>>>(ah, al, wh + 0 * D_ * D_, wl + 0 * D_ * D_,
                                             nullptr, qf, nullptr, 0.03125f);
    split_bf16<<<splitBlocks, 256>>>(key, ah, al);
    gemm_mma<1,2><<<ggrid, 256, GEMM_SMEM>>>(ah, al, wh + 1 * D_ * D_, wl + 1 * D_ * D_,
                                             nullptr, kf, nullptr, 1.0f);
    // V projection: 3-term (direct value path)
    split_bf16<<<splitBlocks, 256>>>(value, ah, al);
    gemm_mma<2,3><<<ggrid, 256, GEMM_SMEM>>>(ah, al, wh + 2 * D_ * D_, wl + 2 * D_ * D_,
                                             nullptr, vh16, vl16, 1.0f);

    dim3 fgrid(S_ / 128, B_ * H_);
    flash_fp16<<<fgrid, 256, FLASH_SMEM>>>(qf, kf, vh16, vl16, aoh, aol);

    // Output projection: 3-term
    gemm_mma<0,3><<<ggrid, 256, GEMM_SMEM>>>(aoh, aol, wh + 3 * D_ * D_, wl + 3 * D_ * D_,
                                             out, nullptr, nullptr, 1.0f);
}

// round 8
// speedup vs baseline: 5.4949x; 1.2397x over previous
#include <cuda_runtime.h>
#include <cuda_bf16.h>
#include <cuda_fp16.h>
#include <stdint.h>
#include <math.h>

#define B_  8
#define S_  2048
#define D_  1024
#define H_  16
#define DK_ 64
#define M_  (B_*S_)   // 16384

// ---------------- scratch (device globals: allocation-free) ----------------
__device__ __half g_af16[M_ * D_];           // fp16 activation (q/k projections)
__device__ __nv_bfloat16 g_ah[M_ * D_];      // bf16 split activation (v / wo paths)
__device__ __nv_bfloat16 g_al[M_ * D_];
__device__ __half g_wqk16[2 * D_ * D_];      // fp16 weights [N][K]: q, k
__device__ __nv_bfloat16 g_wh[2 * D_ * D_];  // bf16 weights hi [N][K]: v, o
__device__ __nv_bfloat16 g_wl[2 * D_ * D_];
__device__ __half g_qf[M_ * D_];             // head-major fp16 q (scale folded)
__device__ __half g_kf[M_ * D_];             // head-major fp16 k
__device__ __half g_vf[M_ * D_];             // head-major fp16 v (single)
__device__ __nv_bfloat16 g_aoh[M_ * D_];     // attention out split (feeds Wo)
__device__ __nv_bfloat16 g_aol[M_ * D_];

// ---------------- helpers ----------------
__device__ __forceinline__ uint32_t smem_u32(const void* p) {
    return (uint32_t)__cvta_generic_to_shared(p);
}
__device__ __forceinline__ void cpasync16(uint32_t s, const void* g) {
    asm volatile("cp.async.cg.shared.global [%0], [%1], 16;" :: "r"(s), "l"(g));
}
__device__ __forceinline__ void cp_commit() {
    asm volatile("cp.async.commit_group;" ::: "memory");
}
template<int N> __device__ __forceinline__ void cp_wait() {
    asm volatile("cp.async.wait_group %0;" :: "n"(N) : "memory");
}
__device__ __forceinline__ void ldsm_x4(uint32_t* r, uint32_t a) {
    asm volatile("ldmatrix.sync.aligned.m8n8.x4.shared.b16 {%0,%1,%2,%3}, [%4];"
                 : "=r"(r[0]), "=r"(r[1]), "=r"(r[2]), "=r"(r[3]) : "r"(a));
}
__device__ __forceinline__ void ldsm_x4_t(uint32_t* r, uint32_t a) {
    asm volatile("ldmatrix.sync.aligned.m8n8.x4.trans.shared.b16 {%0,%1,%2,%3}, [%4];"
                 : "=r"(r[0]), "=r"(r[1]), "=r"(r[2]), "=r"(r[3]) : "r"(a));
}
__device__ __forceinline__ void ldsm_x2(uint32_t* r, uint32_t a) {
    asm volatile("ldmatrix.sync.aligned.m8n8.x2.shared.b16 {%0,%1}, [%2];"
                 : "=r"(r[0]), "=r"(r[1]) : "r"(a));
}
__device__ __forceinline__ void mma16816(float* d, const uint32_t* a, const uint32_t* b) {
    asm volatile(
        "mma.sync.aligned.m16n8k16.row.col.f32.bf16.bf16.f32 "
        "{%0,%1,%2,%3}, {%4,%5,%6,%7}, {%8,%9}, {%0,%1,%2,%3};"
        : "+f"(d[0]), "+f"(d[1]), "+f"(d[2]), "+f"(d[3])
        : "r"(a[0]), "r"(a[1]), "r"(a[2]), "r"(a[3]), "r"(b[0]), "r"(b[1]));
}
__device__ __forceinline__ void mma16816h(float* d, const uint32_t* a, const uint32_t* b) {
    asm volatile(
        "mma.sync.aligned.m16n8k16.row.col.f32.f16.f16.f32 "
        "{%0,%1,%2,%3}, {%4,%5,%6,%7}, {%8,%9}, {%0,%1,%2,%3};"
        : "+f"(d[0]), "+f"(d[1]), "+f"(d[2]), "+f"(d[3])
        : "r"(a[0]), "r"(a[1]), "r"(a[2]), "r"(a[3]), "r"(b[0]), "r"(b[1]));
}
__device__ __forceinline__ uint32_t pk2(__nv_bfloat16 a, __nv_bfloat16 b) {
    return (uint32_t)__bfloat16_as_ushort(a) | ((uint32_t)__bfloat16_as_ushort(b) << 16);
}
__device__ __forceinline__ void split2(float x, float y, uint32_t& hi, uint32_t& lo) {
    __nv_bfloat162 h2 = __floats2bfloat162_rn(x, y);
    float lx = x - __bfloat162float(h2.x);
    float ly = y - __bfloat162float(h2.y);
    __nv_bfloat162 l2 = __floats2bfloat162_rn(lx, ly);
    hi = *reinterpret_cast<uint32_t*>(&h2);
    lo = *reinterpret_cast<uint32_t*>(&l2);
}
__device__ __forceinline__ void split2h(float x, float y, uint32_t& hi, uint32_t& lo) {
    __half2 h2 = __floats2half2_rn(x, y);
    float lx = x - __half2float(__low2half(h2));
    float ly = y - __half2float(__high2half(h2));
    __half2 l2 = __floats2half2_rn(lx, ly);
    hi = *reinterpret_cast<uint32_t*>(&h2);
    lo = *reinterpret_cast<uint32_t*>(&l2);
}

// 128B rows, 8x16B chunks, swizzle chunk' = chunk ^ (row & 7)
#define FOFF(r, c) ((uint32_t)((r) * 128 + ((((c) ^ ((r) & 7))) << 4)))

// ---------------- weight rearrange ----------------
// Wq/Wk -> fp16 [N][K]; Wv/Wo -> bf16 hi/lo [N][K].
__global__ void rearrange_w(const float* __restrict__ Wq, const float* __restrict__ Wk,
                            const float* __restrict__ Wv, const float* __restrict__ Wo) {
    int idx = blockIdx.x * blockDim.x + threadIdx.x;
    if (idx >= D_ * D_) return;
    int n = idx / D_;
    int k = idx % D_;
    int h = n >> 6, dk = n & 63;
    g_wqk16[idx]            = __float2half(Wq[((size_t)h * D_ + k) * DK_ + dk]);
    g_wqk16[D_ * D_ + idx]  = __float2half(Wk[((size_t)h * D_ + k) * DK_ + dk]);
    float wv = Wv[((size_t)h * D_ + k) * DK_ + dk];
    float wo = Wo[(size_t)n * D_ + k];
    __nv_bfloat16 vh = __float2bfloat16(wv);
    __nv_bfloat16 oh = __float2bfloat16(wo);
    g_wh[idx]           = vh;
    g_wl[idx]           = __float2bfloat16(wv - __bfloat162float(vh));
    g_wh[D_ * D_ + idx] = oh;
    g_wl[D_ * D_ + idx] = __float2bfloat16(wo - __bfloat162float(oh));
}

// ---------------- activation converts ----------------
__global__ void conv_fp16(const float* __restrict__ x, __half* __restrict__ o) {
    int i = blockIdx.x * blockDim.x + threadIdx.x;
    float4 v = ((const float4*)x)[i];
    __half2 a = __floats2half2_rn(v.x, v.y);
    __half2 b = __floats2half2_rn(v.z, v.w);
    ((uint2*)o)[i] = make_uint2(*reinterpret_cast<uint32_t*>(&a),
                                *reinterpret_cast<uint32_t*>(&b));
}
__global__ void split_bf16(const float* __restrict__ x,
                           __nv_bfloat16* __restrict__ hi, __nv_bfloat16* __restrict__ lo) {
    int i = blockIdx.x * blockDim.x + threadIdx.x;
    float4 v = ((const float4*)x)[i];
    __nv_bfloat16 h0 = __float2bfloat16(v.x), h1 = __float2bfloat16(v.y),
                  h2 = __float2bfloat16(v.z), h3 = __float2bfloat16(v.w);
    __nv_bfloat16 l0 = __float2bfloat16(v.x - __bfloat162float(h0));
    __nv_bfloat16 l1 = __float2bfloat16(v.y - __bfloat162float(h1));
    __nv_bfloat16 l2 = __float2bfloat16(v.z - __bfloat162float(h2));
    __nv_bfloat16 l3 = __float2bfloat16(v.w - __bfloat162float(h3));
    ((uint2*)hi)[i] = make_uint2(pk2(h0, h1), pk2(h2, h3));
    ((uint2*)lo)[i] = make_uint2(pk2(l0, l1), pk2(l2, l3));
}

// ---------------- fp16 1-term GEMM (Q/K projections) ----------------
// C = A[M,1024] * B^T (B [N][K] fp16); head-major fp16 out with scale.
// 128x128 tile, BK=64, 3-stage 32KB stages, 2 CTAs/SM.
#define G1TILE 16384
#define G1STG  (2 * G1TILE)        // A + B
#define G1SMEM (3 * G1STG)         // 96KB

__global__ __launch_bounds__(256, 2)
void gemm_fp16_1t(const __half* __restrict__ A, const __half* __restrict__ Bw,
                  __half* __restrict__ Co, float scale) {
    extern __shared__ char smraw[];
    const uint32_t sb = smem_u32(smraw);
    const int tid = threadIdx.x;
    const int wid = tid >> 5, lane = tid & 31;
    const int bm = blockIdx.y * 128;
    const int bn = blockIdx.x * 128;
    const int warp_m = (wid & 1) * 64;
    const int warp_n = (wid >> 1) * 32;

    uint32_t soff[4];
    const __half *pA[4], *pB[4];
    #pragma unroll
    for (int i = 0; i < 4; ++i) {
        int lin = i * 256 + tid;
        int row = lin >> 3, c = lin & 7;
        soff[i] = FOFF(row, c);
        pA[i] = A  + (size_t)(bm + row) * D_ + c * 8;
        pB[i] = Bw + (size_t)(bn + row) * D_ + c * 8;
    }
    auto prefetch = [&](int t) {
        uint32_t stg = sb + (t % 3) * G1STG;
        int kofs = t * 64;
        #pragma unroll
        for (int i = 0; i < 4; ++i) {
            cpasync16(stg + soff[i],          pA[i] + kofs);
            cpasync16(stg + G1TILE + soff[i], pB[i] + kofs);
        }
    };
    prefetch(0); cp_commit();
    prefetch(1); cp_commit();

    const int arow = warp_m + (lane & 15);
    const int brow = warp_n + (lane & 7);
    float acc[4][4][4] = {};

    const int NT = D_ / 64;   // 16
    for (int t = 0; t < NT; ++t) {
        if (t == NT - 1) cp_wait<0>(); else cp_wait<1>();
        __syncthreads();
        if (t + 2 < NT) { prefetch(t + 2); cp_commit(); }
        uint32_t stg = sb + (t % 3) * G1STG;

        #pragma unroll
        for (int kk = 0; kk < 4; ++kk) {
            uint32_t ao = FOFF(arow, kk * 2 + (lane >> 4));
            uint32_t bo = FOFF(brow, kk * 2 + ((lane >> 3) & 1));
            uint32_t a4[4][4], b2[4][2];
            #pragma unroll
            for (int mb = 0; mb < 4; ++mb)
                ldsm_x4(a4[mb], stg + ao + mb * 2048);
            #pragma unroll
            for (int nb = 0; nb < 4; ++nb)
                ldsm_x2(b2[nb], stg + G1TILE + bo + nb * 1024);
            #pragma unroll
            for (int mb = 0; mb < 4; ++mb)
                #pragma unroll
                for (int nb = 0; nb < 4; ++nb)
                    mma16816h(acc[mb][nb], a4[mb], b2[nb]);
        }
    }

    const int tm = bm + warp_m + (lane >> 2);
    const int tn = bn + warp_n + (lane & 3) * 2;
    #pragma unroll
    for (int mb = 0; mb < 4; ++mb)
        #pragma unroll
        for (int nb = 0; nb < 4; ++nb) {
            int n = tn + nb * 8;
            int h = n >> 6, dk = n & 63;
            #pragma unroll
            for (int hh = 0; hh < 2; ++hh) {
                int row = tm + mb * 16 + hh * 8;
                int b = row >> 11, s = row & 2047;
                size_t idx = (((size_t)b * H_ + h) * S_ + s) * 64 + dk;
                __half2 p = __floats2half2_rn(acc[mb][nb][hh * 2] * scale,
                                              acc[mb][nb][hh * 2 + 1] * scale);
                *(uint32_t*)(Co + idx) = *reinterpret_cast<uint32_t*>(&p);
            }
        }
}

// ---------------- bf16 3-term GEMM (V / Wo) ----------------
// MODE 0: fp32 C.  MODE 1: head-major single fp16 with scale.
#define GBM 128
#define GBN 128
#define GBK 64
#define GTILE 16384
#define GSTAGE (4 * GTILE)
#define GEMM_SMEM (3 * GSTAGE)

template<int MODE>
__global__ __launch_bounds__(256, 1)
void gemm_mma(const __nv_bfloat16* __restrict__ Ah, const __nv_bfloat16* __restrict__ Al,
              const __nv_bfloat16* __restrict__ Bh, const __nv_bfloat16* __restrict__ Bl,
              float* __restrict__ Cf, __half* __restrict__ Ch, float scale) {
    extern __shared__ char smraw[];
    const uint32_t sb = smem_u32(smraw);
    const int tid = threadIdx.x;
    const int wid = tid >> 5, lane = tid & 31;
    const int bm = blockIdx.y * GBM;
    const int bn = blockIdx.x * GBN;
    const int warp_m = (wid & 1) * 64;
    const int warp_n = (wid >> 1) * 32;

    uint32_t soff[4];
    const __nv_bfloat16 *pA[4], *pAl[4], *pB[4], *pBl[4];
    #pragma unroll
    for (int i = 0; i < 4; ++i) {
        int lin = i * 256 + tid;
        int row = lin >> 3, c = lin & 7;
        soff[i] = FOFF(row, c);
        pA[i]  = Ah + (size_t)(bm + row) * D_ + c * 8;
        pAl[i] = Al + (size_t)(bm + row) * D_ + c * 8;
        pB[i]  = Bh + (size_t)(bn + row) * D_ + c * 8;
        pBl[i] = Bl + (size_t)(bn + row) * D_ + c * 8;
    }
    auto prefetch = [&](int t) {
        uint32_t stg = sb + (t % 3) * GSTAGE;
        int kofs = t * GBK;
        #pragma unroll
        for (int i = 0; i < 4; ++i) {
            cpasync16(stg + soff[i],             pA[i]  + kofs);
            cpasync16(stg + GTILE + soff[i],     pAl[i] + kofs);
            cpasync16(stg + 2 * GTILE + soff[i], pB[i]  + kofs);
            cpasync16(stg + 3 * GTILE + soff[i], pBl[i] + kofs);
        }
    };
    prefetch(0); cp_commit();
    prefetch(1); cp_commit();

    const int arow = warp_m + (lane & 15);
    const int brow = warp_n + (lane & 7);
    float acc[4][4][4] = {};

    const int NT = D_ / GBK;
    for (int t = 0; t < NT; ++t) {
        if (t == NT - 1) cp_wait<0>(); else cp_wait<1>();
        __syncthreads();
        if (t + 2 < NT) { prefetch(t + 2); cp_commit(); }
        uint32_t stg = sb + (t % 3) * GSTAGE;

        #pragma unroll
        for (int kk = 0; kk < 4; ++kk) {
            uint32_t ao = FOFF(arow, kk * 2 + (lane >> 4));
            uint32_t bo = FOFF(brow, kk * 2 + ((lane >> 3) & 1));
            uint32_t ah4[4][4], al4[4][4], bh2[4][2], bl2[4][2];
            #pragma unroll
            for (int mb = 0; mb < 4; ++mb) {
                ldsm_x4(ah4[mb], stg + ao + mb * 2048);
                ldsm_x4(al4[mb], stg + GTILE + ao + mb * 2048);
            }
            #pragma unroll
            for (int nb = 0; nb < 4; ++nb) {
                ldsm_x2(bh2[nb], stg + 2 * GTILE + bo + nb * 1024);
                ldsm_x2(bl2[nb], stg + 3 * GTILE + bo + nb * 1024);
            }
            #pragma unroll
            for (int mb = 0; mb < 4; ++mb)
                #pragma unroll
                for (int nb = 0; nb < 4; ++nb)
                    mma16816(acc[mb][nb], ah4[mb], bh2[nb]);
            #pragma unroll
            for (int mb = 0; mb < 4; ++mb)
                #pragma unroll
                for (int nb = 0; nb < 4; ++nb)
                    mma16816(acc[mb][nb], al4[mb], bh2[nb]);
            #pragma unroll
            for (int mb = 0; mb < 4; ++mb)
                #pragma unroll
                for (int nb = 0; nb < 4; ++nb)
                    mma16816(acc[mb][nb], ah4[mb], bl2[nb]);
        }
    }

    const int tm = bm + warp_m + (lane >> 2);
    const int tn = bn + warp_n + (lane & 3) * 2;
    if (MODE == 0) {
        #pragma unroll
        for (int mb = 0; mb < 4; ++mb)
            #pragma unroll
            for (int nb = 0; nb < 4; ++nb) {
                float* c0 = Cf + (size_t)(tm + mb * 16) * D_ + tn + nb * 8;
                *(float2*)c0 = make_float2(acc[mb][nb][0], acc[mb][nb][1]);
                float* c1 = c0 + 8 * D_;
                *(float2*)c1 = make_float2(acc[mb][nb][2], acc[mb][nb][3]);
            }
    } else {
        #pragma unroll
        for (int mb = 0; mb < 4; ++mb)
            #pragma unroll
            for (int nb = 0; nb < 4; ++nb) {
                int n = tn + nb * 8;
                int h = n >> 6, dk = n & 63;
                #pragma unroll
                for (int hh = 0; hh < 2; ++hh) {
                    int row = tm + mb * 16 + hh * 8;
                    int b = row >> 11, s = row & 2047;
                    size_t idx = (((size_t)b * H_ + h) * S_ + s) * 64 + dk;
                    __half2 p = __floats2half2_rn(acc[mb][nb][hh * 2] * scale,
                                                  acc[mb][nb][hh * 2 + 1] * scale);
                    *(uint32_t*)(Ch + idx) = *reinterpret_cast<uint32_t*>(&p);
                }
            }
    }
}

// ---------------- flash attention fp16 (QK 1-term, PV 2-term: P split, V single) ----------------
// smem: Q 16K + 3 KV stages of 32K (K 16K, V 16K) = 112K
#define KVSTG 32768
#define FLASH_SMEM (16384 + 3 * KVSTG)

__global__ __launch_bounds__(256, 1)
void flash_fp16(const __half* __restrict__ qf, const __half* __restrict__ kf,
                const __half* __restrict__ vf,
                __nv_bfloat16* __restrict__ aoh, __nv_bfloat16* __restrict__ aol) {
    extern __shared__ char smraw[];
    const uint32_t sb = smem_u32(smraw);
    const int tid = threadIdx.x;
    const int wid = tid >> 5, lane = tid & 31;
    const int bh = blockIdx.y;
    const int s0 = blockIdx.x * 128;

    const size_t hb = (size_t)bh * S_ * 64;
    const __half* qp = qf + hb + (size_t)s0 * 64;
    const __half* kp = kf + hb;
    const __half* vp = vf + hb;

    #pragma unroll
    for (int i = 0; i < 4; ++i) {
        int lin = i * 256 + tid;
        int r = lin >> 3, c = lin & 7;
        cpasync16(sb + FOFF(r, c), qp + r * 64 + c * 8);
    }
    auto kvload = [&](int t) {
        uint32_t stg = sb + 16384 + (t % 3) * KVSTG;
        size_t tofs = (size_t)(t * 128) * 64;
        #pragma unroll
        for (int i = 0; i < 4; ++i) {
            int lin = i * 256 + tid;
            int r = lin >> 3, c = lin & 7;
            uint32_t o = FOFF(r, c);
            size_t g = tofs + r * 64 + c * 8;
            cpasync16(stg + o,         kp + g);
            cpasync16(stg + 16384 + o, vp + g);
        }
    };
    kvload(0); cp_commit();
    kvload(1); cp_commit();

    const int warp_m = wid * 16;
    uint32_t qfr[4][4];
    float Oacc[8][4] = {};
    float m0 = -1e30f, m1 = -1e30f, l0 = 0.f, l1 = 0.f;

    const int NT = S_ / 128;   // 16
    for (int t = 0; t < NT; ++t) {
        if (t == NT - 1) cp_wait<0>(); else cp_wait<1>();
        __syncthreads();
        if (t + 2 < NT) { kvload(t + 2); cp_commit(); }
        uint32_t stg = sb + 16384 + (t % 3) * KVSTG;

        if (t == 0) {
            #pragma unroll
            for (int kb = 0; kb < 4; ++kb) {
                int r = warp_m + (lane & 15);
                int c = kb * 2 + (lane >> 4);
                ldsm_x4(qfr[kb], sb + FOFF(r, c));
            }
        }

        // ---- S = Q K^T (fp16, 1 term) ----
        float sacc[16][4] = {};
        #pragma unroll
        for (int kb = 0; kb < 4; ++kb) {
            #pragma unroll
            for (int nbp = 0; nbp < 8; ++nbp) {
                int r = nbp * 16 + ((lane >> 4) << 3) + (lane & 7);
                int c = kb * 2 + ((lane >> 3) & 1);
                uint32_t khf[4];
                ldsm_x4(khf, stg + FOFF(r, c));
                mma16816h(sacc[2 * nbp],     qfr[kb], khf);
                mma16816h(sacc[2 * nbp + 1], qfr[kb], khf + 2);
            }
        }

        // ---- online softmax ----
        float mx0 = -1e30f, mx1 = -1e30f;
        #pragma unroll
        for (int nb = 0; nb < 16; ++nb) {
            mx0 = fmaxf(mx0, fmaxf(sacc[nb][0], sacc[nb][1]));
            mx1 = fmaxf(mx1, fmaxf(sacc[nb][2], sacc[nb][3]));
        }
        mx0 = fmaxf(mx0, __shfl_xor_sync(0xffffffffu, mx0, 1));
        mx0 = fmaxf(mx0, __shfl_xor_sync(0xffffffffu, mx0, 2));
        mx1 = fmaxf(mx1, __shfl_xor_sync(0xffffffffu, mx1, 1));
        mx1 = fmaxf(mx1, __shfl_xor_sync(0xffffffffu, mx1, 2));
        float mn0 = fmaxf(m0, mx0), mn1 = fmaxf(m1, mx1);
        float c0 = __expf(m0 - mn0), c1 = __expf(m1 - mn1);
        float sum0 = 0.f, sum1 = 0.f;
        #pragma unroll
        for (int nb = 0; nb < 16; ++nb) {
            sacc[nb][0] = __expf(sacc[nb][0] - mn0); sum0 += sacc[nb][0];
            sacc[nb][1] = __expf(sacc[nb][1] - mn0); sum0 += sacc[nb][1];
            sacc[nb][2] = __expf(sacc[nb][2] - mn1); sum1 += sacc[nb][2];
            sacc[nb][3] = __expf(sacc[nb][3] - mn1); sum1 += sacc[nb][3];
        }
        sum0 += __shfl_xor_sync(0xffffffffu, sum0, 1);
        sum0 += __shfl_xor_sync(0xffffffffu, sum0, 2);
        sum1 += __shfl_xor_sync(0xffffffffu, sum1, 1);
        sum1 += __shfl_xor_sync(0xffffffffu, sum1, 2);
        l0 = l0 * c0 + sum0;
        l1 = l1 * c1 + sum1;
        m0 = mn0; m1 = mn1;
        #pragma unroll
        for (int nb = 0; nb < 8; ++nb) {
            Oacc[nb][0] *= c0; Oacc[nb][1] *= c0;
            Oacc[nb][2] *= c1; Oacc[nb][3] *= c1;
        }

        // ---- P -> split fp16 fragments ----
        uint32_t phf[8][4], plf[8][4];
        #pragma unroll
        for (int kb = 0; kb < 8; ++kb) {
            split2h(sacc[2 * kb][0],     sacc[2 * kb][1],     phf[kb][0], plf[kb][0]);
            split2h(sacc[2 * kb][2],     sacc[2 * kb][3],     phf[kb][1], plf[kb][1]);
            split2h(sacc[2 * kb + 1][0], sacc[2 * kb + 1][1], phf[kb][2], plf[kb][2]);
            split2h(sacc[2 * kb + 1][2], sacc[2 * kb + 1][3], phf[kb][3], plf[kb][3]);
        }

        // ---- O += P V (2-term: Ph*V + Pl*V, V single fp16) ----
        #pragma unroll
        for (int kb = 0; kb < 8; ++kb) {
            #pragma unroll
            for (int nbp = 0; nbp < 4; ++nbp) {
                int r = kb * 16 + (((lane >> 3) & 1) << 3) + (lane & 7);
                int c = nbp * 2 + (lane >> 4);
                uint32_t vfr[4];
                ldsm_x4_t(vfr, stg + 16384 + FOFF(r, c));
                mma16816h(Oacc[2 * nbp],     phf[kb], vfr);
                mma16816h(Oacc[2 * nbp + 1], phf[kb], vfr + 2);
                mma16816h(Oacc[2 * nbp],     plf[kb], vfr);
                mma16816h(Oacc[2 * nbp + 1], plf[kb], vfr + 2);
            }
        }
    }

    // ---- epilogue: normalize, split to bf16 hi/lo for Wo GEMM ----
    float inv0 = 1.f / l0, inv1 = 1.f / l1;
    int b = bh >> 4, h = bh & 15;
    int r0 = s0 + warp_m + (lane >> 2);
    size_t base0 = ((size_t)b * S_ + r0) * D_ + h * 64 + (lane & 3) * 2;
    size_t base1 = base0 + 8 * D_;
    #pragma unroll
    for (int nb = 0; nb < 8; ++nb) {
        uint32_t hi, lo;
        split2(Oacc[nb][0] * inv0, Oacc[nb][1] * inv0, hi, lo);
        *(uint32_t*)(aoh + base0 + nb * 8) = hi;
        *(uint32_t*)(aol + base0 + nb * 8) = lo;
        split2(Oacc[nb][2] * inv1, Oacc[nb][3] * inv1, hi, lo);
        *(uint32_t*)(aoh + base1 + nb * 8) = hi;
        *(uint32_t*)(aol + base1 + nb * 8) = lo;
    }
}

// ---------------- launch ----------------
extern "C" void kernel_launch(void* const* d_in, const int* in_sizes, int n_in,
                              void* d_out, int out_size) {
    const float* query = (const float*)d_in[0];
    const float* key   = (const float*)d_in[1];
    const float* value = (const float*)d_in[2];
    const float* Wq    = (const float*)d_in[3];
    const float* Wk    = (const float*)d_in[4];
    const float* Wv    = (const float*)d_in[5];
    const float* Wo    = (const float*)d_in[6];
    float* out = (float*)d_out;

    __nv_bfloat16 *ah, *al, *wh, *wl, *aoh, *aol;
    __half *af16, *wqk16, *qf, *kf, *vf;
    cudaGetSymbolAddress((void**)&af16,  g_af16);
    cudaGetSymbolAddress((void**)&ah,    g_ah);
    cudaGetSymbolAddress((void**)&al,    g_al);
    cudaGetSymbolAddress((void**)&wqk16, g_wqk16);
    cudaGetSymbolAddress((void**)&wh,    g_wh);
    cudaGetSymbolAddress((void**)&wl,    g_wl);
    cudaGetSymbolAddress((void**)&qf,    g_qf);
    cudaGetSymbolAddress((void**)&kf,    g_kf);
    cudaGetSymbolAddress((void**)&vf,    g_vf);
    cudaGetSymbolAddress((void**)&aoh,   g_aoh);
    cudaGetSymbolAddress((void**)&aol,   g_aol);

    cudaFuncSetAttribute((const void*)gemm_fp16_1t, cudaFuncAttributeMaxDynamicSharedMemorySize, G1SMEM);
    cudaFuncSetAttribute((const void*)gemm_mma<0>, cudaFuncAttributeMaxDynamicSharedMemorySize, GEMM_SMEM);
    cudaFuncSetAttribute((const void*)gemm_mma<1>, cudaFuncAttributeMaxDynamicSharedMemorySize, GEMM_SMEM);
    cudaFuncSetAttribute((const void*)flash_fp16, cudaFuncAttributeMaxDynamicSharedMemorySize, FLASH_SMEM);

    rearrange_w<<<(D_ * D_ + 255) / 256, 256>>>(Wq, Wk, Wv, Wo);

    dim3 ggrid(D_ / GBN, M_ / GBM);   // (8, 128)
    int cvtBlocks = (M_ * D_ / 4) / 256;

    // Q, K projections: fp16 1-term (score path)
    conv_fp16<<<cvtBlocks, 256>>>(query, af16);
    gemm_fp16_1t<<<ggrid, 256, G1SMEM>>>(af16, wqk16, qf, 0.03125f);
    conv_fp16<<<cvtBlocks, 256>>>(key, af16);
    gemm_fp16_1t<<<ggrid, 256, G1SMEM>>>(af16, wqk16 + D_ * D_, kf, 1.0f);

    // V projection: bf16 3-term, emit single fp16
    split_bf16<<<cvtBlocks, 256>>>(value, ah, al);
    gemm_mma<1><<<ggrid, 256, GEMM_SMEM>>>(ah, al, wh, wl, nullptr, vf, 1.0f);

    dim3 fgrid(S_ / 128, B_ * H_);
    flash_fp16<<<fgrid, 256, FLASH_SMEM>>>(qf, kf, vf, aoh, aol);

    // Output projection: bf16 3-term, fp32 out
    gemm_mma<0><<<ggrid, 256, GEMM_SMEM>>>(aoh, aol, wh + D_ * D_, wl + D_ * D_,
                                           out, nullptr, 1.0f);
}

// round 9
// speedup vs baseline: 5.5612x; 1.0121x over previous
#include <cuda_runtime.h>
#include <cuda_bf16.h>
#include <cuda_fp16.h>
#include <stdint.h>
#include <math.h>

#define B_  8
#define S_  2048
#define D_  1024
#define H_  16
#define DK_ 64
#define M_  (B_*S_)   // 16384

// ---------------- scratch (device globals: allocation-free) ----------------
__device__ __half g_afq[M_ * D_];            // fp16 query activation
__device__ __half g_afk[M_ * D_];            // fp16 key activation
__device__ __nv_bfloat16 g_ah[M_ * D_];      // bf16 split activation (v / wo paths)
__device__ __nv_bfloat16 g_al[M_ * D_];
__device__ __half g_wqk16[2 * D_ * D_];      // fp16 weights [N][K]: q, k
__device__ __nv_bfloat16 g_wh[2 * D_ * D_];  // bf16 weights hi [N][K]: v, o
__device__ __nv_bfloat16 g_wl[2 * D_ * D_];
__device__ __half g_qf[M_ * D_];             // head-major fp16 q (log2e/32 folded)
__device__ __half g_kf[M_ * D_];             // head-major fp16 k
__device__ __half g_vf[M_ * D_];             // head-major fp16 v
__device__ __nv_bfloat16 g_aoh[M_ * D_];     // attention out split (feeds Wo)
__device__ __nv_bfloat16 g_aol[M_ * D_];

// ---------------- helpers ----------------
__device__ __forceinline__ uint32_t smem_u32(const void* p) {
    return (uint32_t)__cvta_generic_to_shared(p);
}
__device__ __forceinline__ void cpasync16(uint32_t s, const void* g) {
    asm volatile("cp.async.cg.shared.global [%0], [%1], 16;" :: "r"(s), "l"(g));
}
__device__ __forceinline__ void cp_commit() {
    asm volatile("cp.async.commit_group;" ::: "memory");
}
template<int N> __device__ __forceinline__ void cp_wait() {
    asm volatile("cp.async.wait_group %0;" :: "n"(N) : "memory");
}
__device__ __forceinline__ void ldsm_x4(uint32_t* r, uint32_t a) {
    asm volatile("ldmatrix.sync.aligned.m8n8.x4.shared.b16 {%0,%1,%2,%3}, [%4];"
                 : "=r"(r[0]), "=r"(r[1]), "=r"(r[2]), "=r"(r[3]) : "r"(a));
}
__device__ __forceinline__ void ldsm_x4_t(uint32_t* r, uint32_t a) {
    asm volatile("ldmatrix.sync.aligned.m8n8.x4.trans.shared.b16 {%0,%1,%2,%3}, [%4];"
                 : "=r"(r[0]), "=r"(r[1]), "=r"(r[2]), "=r"(r[3]) : "r"(a));
}
__device__ __forceinline__ void ldsm_x2(uint32_t* r, uint32_t a) {
    asm volatile("ldmatrix.sync.aligned.m8n8.x2.shared.b16 {%0,%1}, [%2];"
                 : "=r"(r[0]), "=r"(r[1]) : "r"(a));
}
__device__ __forceinline__ void mma16816(float* d, const uint32_t* a, const uint32_t* b) {
    asm volatile(
        "mma.sync.aligned.m16n8k16.row.col.f32.bf16.bf16.f32 "
        "{%0,%1,%2,%3}, {%4,%5,%6,%7}, {%8,%9}, {%0,%1,%2,%3};"
        : "+f"(d[0]), "+f"(d[1]), "+f"(d[2]), "+f"(d[3])
        : "r"(a[0]), "r"(a[1]), "r"(a[2]), "r"(a[3]), "r"(b[0]), "r"(b[1]));
}
__device__ __forceinline__ void mma16816h(float* d, const uint32_t* a, const uint32_t* b) {
    asm volatile(
        "mma.sync.aligned.m16n8k16.row.col.f32.f16.f16.f32 "
        "{%0,%1,%2,%3}, {%4,%5,%6,%7}, {%8,%9}, {%0,%1,%2,%3};"
        : "+f"(d[0]), "+f"(d[1]), "+f"(d[2]), "+f"(d[3])
        : "r"(a[0]), "r"(a[1]), "r"(a[2]), "r"(a[3]), "r"(b[0]), "r"(b[1]));
}
__device__ __forceinline__ float fexp2(float x) {
    float y; asm("ex2.approx.f32 %0, %1;" : "=f"(y) : "f"(x)); return y;
}
__device__ __forceinline__ uint32_t pk2(__nv_bfloat16 a, __nv_bfloat16 b) {
    return (uint32_t)__bfloat16_as_ushort(a) | ((uint32_t)__bfloat16_as_ushort(b) << 16);
}
__device__ __forceinline__ void split2(float x, float y, uint32_t& hi, uint32_t& lo) {
    __nv_bfloat162 h2 = __floats2bfloat162_rn(x, y);
    float lx = x - __bfloat162float(h2.x);
    float ly = y - __bfloat162float(h2.y);
    __nv_bfloat162 l2 = __floats2bfloat162_rn(lx, ly);
    hi = *reinterpret_cast<uint32_t*>(&h2);
    lo = *reinterpret_cast<uint32_t*>(&l2);
}
__device__ __forceinline__ void split2h(float x, float y, uint32_t& hi, uint32_t& lo) {
    __half2 h2 = __floats2half2_rn(x, y);
    float lx = x - __half2float(__low2half(h2));
    float ly = y - __half2float(__high2half(h2));
    __half2 l2 = __floats2half2_rn(lx, ly);
    hi = *reinterpret_cast<uint32_t*>(&h2);
    lo = *reinterpret_cast<uint32_t*>(&l2);
}

// 128B rows, 8x16B chunks, swizzle chunk' = chunk ^ (row & 7)
#define FOFF(r, c) ((uint32_t)((r) * 128 + ((((c) ^ ((r) & 7))) << 4)))

// q scale: d_model^-0.5 * log2(e), so softmax runs in exp2 domain
#define QSCALE 0.04508422f

// ---------------- weight rearrange ----------------
__global__ void rearrange_w(const float* __restrict__ Wq, const float* __restrict__ Wk,
                            const float* __restrict__ Wv, const float* __restrict__ Wo) {
    int idx = blockIdx.x * blockDim.x + threadIdx.x;
    if (idx >= D_ * D_) return;
    int n = idx / D_;
    int k = idx % D_;
    int h = n >> 6, dk = n & 63;
    g_wqk16[idx]            = __float2half(Wq[((size_t)h * D_ + k) * DK_ + dk]);
    g_wqk16[D_ * D_ + idx]  = __float2half(Wk[((size_t)h * D_ + k) * DK_ + dk]);
    float wv = Wv[((size_t)h * D_ + k) * DK_ + dk];
    float wo = Wo[(size_t)n * D_ + k];
    __nv_bfloat16 vh = __float2bfloat16(wv);
    __nv_bfloat16 oh = __float2bfloat16(wo);
    g_wh[idx]           = vh;
    g_wl[idx]           = __float2bfloat16(wv - __bfloat162float(vh));
    g_wh[D_ * D_ + idx] = oh;
    g_wl[D_ * D_ + idx] = __float2bfloat16(wo - __bfloat162float(oh));
}

// ---------------- activation converts ----------------
// grid.y = 2: y=0 converts x0->o0, y=1 converts x1->o1
__global__ void conv_fp16_2(const float* __restrict__ x0, const float* __restrict__ x1,
                            __half* __restrict__ o0, __half* __restrict__ o1) {
    int i = blockIdx.x * blockDim.x + threadIdx.x;
    const float* x = blockIdx.y ? x1 : x0;
    __half* o = blockIdx.y ? o1 : o0;
    float4 v = ((const float4*)x)[i];
    __half2 a = __floats2half2_rn(v.x, v.y);
    __half2 b = __floats2half2_rn(v.z, v.w);
    ((uint2*)o)[i] = make_uint2(*reinterpret_cast<uint32_t*>(&a),
                                *reinterpret_cast<uint32_t*>(&b));
}
__global__ void split_bf16(const float* __restrict__ x,
                           __nv_bfloat16* __restrict__ hi, __nv_bfloat16* __restrict__ lo) {
    int i = blockIdx.x * blockDim.x + threadIdx.x;
    float4 v = ((const float4*)x)[i];
    __nv_bfloat16 h0 = __float2bfloat16(v.x), h1 = __float2bfloat16(v.y),
                  h2 = __float2bfloat16(v.z), h3 = __float2bfloat16(v.w);
    __nv_bfloat16 l0 = __float2bfloat16(v.x - __bfloat162float(h0));
    __nv_bfloat16 l1 = __float2bfloat16(v.y - __bfloat162float(h1));
    __nv_bfloat16 l2 = __float2bfloat16(v.z - __bfloat162float(h2));
    __nv_bfloat16 l3 = __float2bfloat16(v.w - __bfloat162float(h3));
    ((uint2*)hi)[i] = make_uint2(pk2(h0, h1), pk2(h2, h3));
    ((uint2*)lo)[i] = make_uint2(pk2(l0, l1), pk2(l2, l3));
}

// ---------------- fp16 1-term GEMM, fused Q+K (grid.z = 2) ----------------
#define G1TILE 16384
#define G1STG  (2 * G1TILE)
#define G1SMEM (3 * G1STG)   // 96KB

__global__ __launch_bounds__(256, 2)
void gemm_qk(const __half* __restrict__ Aq, const __half* __restrict__ Ak,
             const __half* __restrict__ W,
             __half* __restrict__ Cq, __half* __restrict__ Ck) {
    extern __shared__ char smraw[];
    const uint32_t sb = smem_u32(smraw);
    const int z = blockIdx.z;
    const __half* A  = z ? Ak : Aq;
    const __half* Bw = W + (size_t)z * D_ * D_;
    __half* Co = z ? Ck : Cq;
    const float scale = z ? 1.0f : QSCALE;

    const int tid = threadIdx.x;
    const int wid = tid >> 5, lane = tid & 31;
    const int bm = blockIdx.y * 128;
    const int bn = blockIdx.x * 128;
    const int warp_m = (wid & 1) * 64;
    const int warp_n = (wid >> 1) * 32;

    uint32_t soff[4];
    const __half *pA[4], *pB[4];
    #pragma unroll
    for (int i = 0; i < 4; ++i) {
        int lin = i * 256 + tid;
        int row = lin >> 3, c = lin & 7;
        soff[i] = FOFF(row, c);
        pA[i] = A  + (size_t)(bm + row) * D_ + c * 8;
        pB[i] = Bw + (size_t)(bn + row) * D_ + c * 8;
    }
    auto prefetch = [&](int t) {
        uint32_t stg = sb + (t % 3) * G1STG;
        int kofs = t * 64;
        #pragma unroll
        for (int i = 0; i < 4; ++i) {
            cpasync16(stg + soff[i],          pA[i] + kofs);
            cpasync16(stg + G1TILE + soff[i], pB[i] + kofs);
        }
    };
    prefetch(0); cp_commit();
    prefetch(1); cp_commit();

    const int arow = warp_m + (lane & 15);
    const int brow = warp_n + (lane & 7);
    float acc[4][4][4] = {};

    const int NT = D_ / 64;   // 16
    for (int t = 0; t < NT; ++t) {
        if (t == NT - 1) cp_wait<0>(); else cp_wait<1>();
        __syncthreads();
        if (t + 2 < NT) { prefetch(t + 2); cp_commit(); }
        uint32_t stg = sb + (t % 3) * G1STG;

        #pragma unroll
        for (int kk = 0; kk < 4; ++kk) {
            uint32_t ao = FOFF(arow, kk * 2 + (lane >> 4));
            uint32_t bo = FOFF(brow, kk * 2 + ((lane >> 3) & 1));
            uint32_t a4[4][4], b2[4][2];
            #pragma unroll
            for (int mb = 0; mb < 4; ++mb)
                ldsm_x4(a4[mb], stg + ao + mb * 2048);
            #pragma unroll
            for (int nb = 0; nb < 4; ++nb)
                ldsm_x2(b2[nb], stg + G1TILE + bo + nb * 1024);
            #pragma unroll
            for (int mb = 0; mb < 4; ++mb)
                #pragma unroll
                for (int nb = 0; nb < 4; ++nb)
                    mma16816h(acc[mb][nb], a4[mb], b2[nb]);
        }
    }

    const int tm = bm + warp_m + (lane >> 2);
    const int tn = bn + warp_n + (lane & 3) * 2;
    #pragma unroll
    for (int mb = 0; mb < 4; ++mb)
        #pragma unroll
        for (int nb = 0; nb < 4; ++nb) {
            int n = tn + nb * 8;
            int h = n >> 6, dk = n & 63;
            #pragma unroll
            for (int hh = 0; hh < 2; ++hh) {
                int row = tm + mb * 16 + hh * 8;
                int b = row >> 11, s = row & 2047;
                size_t idx = (((size_t)b * H_ + h) * S_ + s) * 64 + dk;
                __half2 p = __floats2half2_rn(acc[mb][nb][hh * 2] * scale,
                                              acc[mb][nb][hh * 2 + 1] * scale);
                *(uint32_t*)(Co + idx) = *reinterpret_cast<uint32_t*>(&p);
            }
        }
}

// ---------------- bf16 3-term GEMM (V / Wo) ----------------
#define GBM 128
#define GBN 128
#define GBK 64
#define GTILE 16384
#define GSTAGE (4 * GTILE)
#define GEMM_SMEM (3 * GSTAGE)

template<int MODE>
__global__ __launch_bounds__(256, 1)
void gemm_mma(const __nv_bfloat16* __restrict__ Ah, const __nv_bfloat16* __restrict__ Al,
              const __nv_bfloat16* __restrict__ Bh, const __nv_bfloat16* __restrict__ Bl,
              float* __restrict__ Cf, __half* __restrict__ Ch, float scale) {
    extern __shared__ char smraw[];
    const uint32_t sb = smem_u32(smraw);
    const int tid = threadIdx.x;
    const int wid = tid >> 5, lane = tid & 31;
    const int bm = blockIdx.y * GBM;
    const int bn = blockIdx.x * GBN;
    const int warp_m = (wid & 1) * 64;
    const int warp_n = (wid >> 1) * 32;

    uint32_t soff[4];
    const __nv_bfloat16 *pA[4], *pAl[4], *pB[4], *pBl[4];
    #pragma unroll
    for (int i = 0; i < 4; ++i) {
        int lin = i * 256 + tid;
        int row = lin >> 3, c = lin & 7;
        soff[i] = FOFF(row, c);
        pA[i]  = Ah + (size_t)(bm + row) * D_ + c * 8;
        pAl[i] = Al + (size_t)(bm + row) * D_ + c * 8;
        pB[i]  = Bh + (size_t)(bn + row) * D_ + c * 8;
        pBl[i] = Bl + (size_t)(bn + row) * D_ + c * 8;
    }
    auto prefetch = [&](int t) {
        uint32_t stg = sb + (t % 3) * GSTAGE;
        int kofs = t * GBK;
        #pragma unroll
        for (int i = 0; i < 4; ++i) {
            cpasync16(stg + soff[i],             pA[i]  + kofs);
            cpasync16(stg + GTILE + soff[i],     pAl[i] + kofs);
            cpasync16(stg + 2 * GTILE + soff[i], pB[i]  + kofs);
            cpasync16(stg + 3 * GTILE + soff[i], pBl[i] + kofs);
        }
    };
    prefetch(0); cp_commit();
    prefetch(1); cp_commit();

    const int arow = warp_m + (lane & 15);
    const int brow = warp_n + (lane & 7);
    float acc[4][4][4] = {};

    const int NT = D_ / GBK;
    for (int t = 0; t < NT; ++t) {
        if (t == NT - 1) cp_wait<0>(); else cp_wait<1>();
        __syncthreads();
        if (t + 2 < NT) { prefetch(t + 2); cp_commit(); }
        uint32_t stg = sb + (t % 3) * GSTAGE;

        #pragma unroll
        for (int kk = 0; kk < 4; ++kk) {
            uint32_t ao = FOFF(arow, kk * 2 + (lane >> 4));
            uint32_t bo = FOFF(brow, kk * 2 + ((lane >> 3) & 1));
            uint32_t ah4[4][4], al4[4][4], bh2[4][2], bl2[4][2];
            #pragma unroll
            for (int mb = 0; mb < 4; ++mb) {
                ldsm_x4(ah4[mb], stg + ao + mb * 2048);
                ldsm_x4(al4[mb], stg + GTILE + ao + mb * 2048);
            }
            #pragma unroll
            for (int nb = 0; nb < 4; ++nb) {
                ldsm_x2(bh2[nb], stg + 2 * GTILE + bo + nb * 1024);
                ldsm_x2(bl2[nb], stg + 3 * GTILE + bo + nb * 1024);
            }
            #pragma unroll
            for (int mb = 0; mb < 4; ++mb)
                #pragma unroll
                for (int nb = 0; nb < 4; ++nb)
                    mma16816(acc[mb][nb], ah4[mb], bh2[nb]);
            #pragma unroll
            for (int mb = 0; mb < 4; ++mb)
                #pragma unroll
                for (int nb = 0; nb < 4; ++nb)
                    mma16816(acc[mb][nb], al4[mb], bh2[nb]);
            #pragma unroll
            for (int mb = 0; mb < 4; ++mb)
                #pragma unroll
                for (int nb = 0; nb < 4; ++nb)
                    mma16816(acc[mb][nb], ah4[mb], bl2[nb]);
        }
    }

    const int tm = bm + warp_m + (lane >> 2);
    const int tn = bn + warp_n + (lane & 3) * 2;
    if (MODE == 0) {
        #pragma unroll
        for (int mb = 0; mb < 4; ++mb)
            #pragma unroll
            for (int nb = 0; nb < 4; ++nb) {
                float* c0 = Cf + (size_t)(tm + mb * 16) * D_ + tn + nb * 8;
                *(float2*)c0 = make_float2(acc[mb][nb][0], acc[mb][nb][1]);
                float* c1 = c0 + 8 * D_;
                *(float2*)c1 = make_float2(acc[mb][nb][2], acc[mb][nb][3]);
            }
    } else {
        #pragma unroll
        for (int mb = 0; mb < 4; ++mb)
            #pragma unroll
            for (int nb = 0; nb < 4; ++nb) {
                int n = tn + nb * 8;
                int h = n >> 6, dk = n & 63;
                #pragma unroll
                for (int hh = 0; hh < 2; ++hh) {
                    int row = tm + mb * 16 + hh * 8;
                    int b = row >> 11, s = row & 2047;
                    size_t idx = (((size_t)b * H_ + h) * S_ + s) * 64 + dk;
                    __half2 p = __floats2half2_rn(acc[mb][nb][hh * 2] * scale,
                                                  acc[mb][nb][hh * 2 + 1] * scale);
                    *(uint32_t*)(Ch + idx) = *reinterpret_cast<uint32_t*>(&p);
                }
            }
    }
}

// ---------------- flash attention fp16, exp2 domain, kb-interleaved PV ----------------
// smem: Q 16K + 3 KV stages of 32K (K 16K, V 16K) = 112K
#define KVSTG 32768
#define FLASH_SMEM (16384 + 3 * KVSTG)

__global__ __launch_bounds__(256, 1)
void flash_fp16(const __half* __restrict__ qf, const __half* __restrict__ kf,
                const __half* __restrict__ vf,
                __nv_bfloat16* __restrict__ aoh, __nv_bfloat16* __restrict__ aol) {
    extern __shared__ char smraw[];
    const uint32_t sb = smem_u32(smraw);
    const int tid = threadIdx.x;
    const int wid = tid >> 5, lane = tid & 31;
    const int bh = blockIdx.y;
    const int s0 = blockIdx.x * 128;

    const size_t hb = (size_t)bh * S_ * 64;
    const __half* qp = qf + hb + (size_t)s0 * 64;
    const __half* kp = kf + hb;
    const __half* vp = vf + hb;

    #pragma unroll
    for (int i = 0; i < 4; ++i) {
        int lin = i * 256 + tid;
        int r = lin >> 3, c = lin & 7;
        cpasync16(sb + FOFF(r, c), qp + r * 64 + c * 8);
    }
    auto kvload = [&](int t) {
        uint32_t stg = sb + 16384 + (t % 3) * KVSTG;
        size_t tofs = (size_t)(t * 128) * 64;
        #pragma unroll
        for (int i = 0; i < 4; ++i) {
            int lin = i * 256 + tid;
            int r = lin >> 3, c = lin & 7;
            uint32_t o = FOFF(r, c);
            size_t g = tofs + r * 64 + c * 8;
            cpasync16(stg + o,         kp + g);
            cpasync16(stg + 16384 + o, vp + g);
        }
    };
    kvload(0); cp_commit();
    kvload(1); cp_commit();

    const int warp_m = wid * 16;
    uint32_t qfr[4][4];
    float Oacc[8][4] = {};
    float m0 = -1e30f, m1 = -1e30f, l0 = 0.f, l1 = 0.f;

    const int NT = S_ / 128;   // 16
    for (int t = 0; t < NT; ++t) {
        if (t == NT - 1) cp_wait<0>(); else cp_wait<1>();
        __syncthreads();
        if (t + 2 < NT) { kvload(t + 2); cp_commit(); }
        uint32_t stg = sb + 16384 + (t % 3) * KVSTG;

        if (t == 0) {
            #pragma unroll
            for (int kb = 0; kb < 4; ++kb) {
                int r = warp_m + (lane & 15);
                int c = kb * 2 + (lane >> 4);
                ldsm_x4(qfr[kb], sb + FOFF(r, c));
            }
        }

        // ---- S = Q K^T (fp16, 1 term), scores already in log2 domain ----
        float sacc[16][4] = {};
        #pragma unroll
        for (int kb = 0; kb < 4; ++kb) {
            #pragma unroll
            for (int nbp = 0; nbp < 8; ++nbp) {
                int r = nbp * 16 + ((lane >> 4) << 3) + (lane & 7);
                int c = kb * 2 + ((lane >> 3) & 1);
                uint32_t khf[4];
                ldsm_x4(khf, stg + FOFF(r, c));
                mma16816h(sacc[2 * nbp],     qfr[kb], khf);
                mma16816h(sacc[2 * nbp + 1], qfr[kb], khf + 2);
            }
        }

        // ---- row max ----
        float mx0 = -1e30f, mx1 = -1e30f;
        #pragma unroll
        for (int nb = 0; nb < 16; ++nb) {
            mx0 = fmaxf(mx0, fmaxf(sacc[nb][0], sacc[nb][1]));
            mx1 = fmaxf(mx1, fmaxf(sacc[nb][2], sacc[nb][3]));
        }
        mx0 = fmaxf(mx0, __shfl_xor_sync(0xffffffffu, mx0, 1));
        mx0 = fmaxf(mx0, __shfl_xor_sync(0xffffffffu, mx0, 2));
        mx1 = fmaxf(mx1, __shfl_xor_sync(0xffffffffu, mx1, 1));
        mx1 = fmaxf(mx1, __shfl_xor_sync(0xffffffffu, mx1, 2));
        float mn0 = fmaxf(m0, mx0), mn1 = fmaxf(m1, mx1);
        float c0 = fexp2(m0 - mn0), c1 = fexp2(m1 - mn1);
        m0 = mn0; m1 = mn1;
        #pragma unroll
        for (int nb = 0; nb < 8; ++nb) {
            Oacc[nb][0] *= c0; Oacc[nb][1] *= c0;
            Oacc[nb][2] *= c1; Oacc[nb][3] *= c1;
        }
        l0 *= c0; l1 *= c1;

        // ---- per-kb: exp2 -> split -> PV (interleaves MUFU with MMA) ----
        float sum0 = 0.f, sum1 = 0.f;
        #pragma unroll
        for (int kb = 0; kb < 8; ++kb) {
            float e00 = fexp2(sacc[2 * kb][0] - mn0);
            float e01 = fexp2(sacc[2 * kb][1] - mn0);
            float e02 = fexp2(sacc[2 * kb][2] - mn1);
            float e03 = fexp2(sacc[2 * kb][3] - mn1);
            float e10 = fexp2(sacc[2 * kb + 1][0] - mn0);
            float e11 = fexp2(sacc[2 * kb + 1][1] - mn0);
            float e12 = fexp2(sacc[2 * kb + 1][2] - mn1);
            float e13 = fexp2(sacc[2 * kb + 1][3] - mn1);
            sum0 += (e00 + e01) + (e10 + e11);
            sum1 += (e02 + e03) + (e12 + e13);
            uint32_t ph[4], pl[4];
            split2h(e00, e01, ph[0], pl[0]);
            split2h(e02, e03, ph[1], pl[1]);
            split2h(e10, e11, ph[2], pl[2]);
            split2h(e12, e13, ph[3], pl[3]);
            #pragma unroll
            for (int nbp = 0; nbp < 4; ++nbp) {
                int r = kb * 16 + (((lane >> 3) & 1) << 3) + (lane & 7);
                int c = nbp * 2 + (lane >> 4);
                uint32_t vfr[4];
                ldsm_x4_t(vfr, stg + 16384 + FOFF(r, c));
                mma16816h(Oacc[2 * nbp],     ph, vfr);
                mma16816h(Oacc[2 * nbp + 1], ph, vfr + 2);
                mma16816h(Oacc[2 * nbp],     pl, vfr);
                mma16816h(Oacc[2 * nbp + 1], pl, vfr + 2);
            }
        }
        sum0 += __shfl_xor_sync(0xffffffffu, sum0, 1);
        sum0 += __shfl_xor_sync(0xffffffffu, sum0, 2);
        sum1 += __shfl_xor_sync(0xffffffffu, sum1, 1);
        sum1 += __shfl_xor_sync(0xffffffffu, sum1, 2);
        l0 += sum0;
        l1 += sum1;
    }

    // ---- epilogue: normalize, split to bf16 hi/lo for Wo GEMM ----
    float inv0 = 1.f / l0, inv1 = 1.f / l1;
    int b = bh >> 4, h = bh & 15;
    int r0 = s0 + warp_m + (lane >> 2);
    size_t base0 = ((size_t)b * S_ + r0) * D_ + h * 64 + (lane & 3) * 2;
    size_t base1 = base0 + 8 * D_;
    #pragma unroll
    for (int nb = 0; nb < 8; ++nb) {
        uint32_t hi, lo;
        split2(Oacc[nb][0] * inv0, Oacc[nb][1] * inv0, hi, lo);
        *(uint32_t*)(aoh + base0 + nb * 8) = hi;
        *(uint32_t*)(aol + base0 + nb * 8) = lo;
        split2(Oacc[nb][2] * inv1, Oacc[nb][3] * inv1, hi, lo);
        *(uint32_t*)(aoh + base1 + nb * 8) = hi;
        *(uint32_t*)(aol + base1 + nb * 8) = lo;
    }
}

// ---------------- launch ----------------
extern "C" void kernel_launch(void* const* d_in, const int* in_sizes, int n_in,
                              void* d_out, int out_size) {
    const float* query = (const float*)d_in[0];
    const float* key   = (const float*)d_in[1];
    const float* value = (const float*)d_in[2];
    const float* Wq    = (const float*)d_in[3];
    const float* Wk    = (const float*)d_in[4];
    const float* Wv    = (const float*)d_in[5];
    const float* Wo    = (const float*)d_in[6];
    float* out = (float*)d_out;

    __nv_bfloat16 *ah, *al, *wh, *wl, *aoh, *aol;
    __half *afq, *afk, *wqk16, *qf, *kf, *vf;
    cudaGetSymbolAddress((void**)&afq,   g_afq);
    cudaGetSymbolAddress((void**)&afk,   g_afk);
    cudaGetSymbolAddress((void**)&ah,    g_ah);
    cudaGetSymbolAddress((void**)&al,    g_al);
    cudaGetSymbolAddress((void**)&wqk16, g_wqk16);
    cudaGetSymbolAddress((void**)&wh,    g_wh);
    cudaGetSymbolAddress((void**)&wl,    g_wl);
    cudaGetSymbolAddress((void**)&qf,    g_qf);
    cudaGetSymbolAddress((void**)&kf,    g_kf);
    cudaGetSymbolAddress((void**)&vf,    g_vf);
    cudaGetSymbolAddress((void**)&aoh,   g_aoh);
    cudaGetSymbolAddress((void**)&aol,   g_aol);

    cudaFuncSetAttribute((const void*)gemm_qk, cudaFuncAttributeMaxDynamicSharedMemorySize, G1SMEM);
    cudaFuncSetAttribute((const void*)gemm_mma<0>, cudaFuncAttributeMaxDynamicSharedMemorySize, GEMM_SMEM);
    cudaFuncSetAttribute((const void*)gemm_mma<1>, cudaFuncAttributeMaxDynamicSharedMemorySize, GEMM_SMEM);
    cudaFuncSetAttribute((const void*)flash_fp16, cudaFuncAttributeMaxDynamicSharedMemorySize, FLASH_SMEM);

    rearrange_w<<<(D_ * D_ + 255) / 256, 256>>>(Wq, Wk, Wv, Wo);

    int cvtBlocks = (M_ * D_ / 4) / 256;

    // Q+K converts fused, then Q+K projections fused (fp16 1-term)
    conv_fp16_2<<<dim3(cvtBlocks, 2), 256>>>(query, key, afq, afk);
    gemm_qk<<<dim3(8, 128, 2), 256, G1SMEM>>>(afq, afk, wqk16, qf, kf);

    // V projection: bf16 3-term, emit single fp16
    split_bf16<<<cvtBlocks, 256>>>(value, ah, al);
    dim3 ggrid(D_ / GBN, M_ / GBM);
    gemm_mma<1><<<ggrid, 256, GEMM_SMEM>>>(ah, al, wh, wl, nullptr, vf, 1.0f);

    dim3 fgrid(S_ / 128, B_ * H_);
    flash_fp16<<<fgrid, 256, FLASH_SMEM>>>(qf, kf, vf, aoh, aol);

    // Output projection: bf16 3-term, fp32 out
    gemm_mma<0><<<ggrid, 256, GEMM_SMEM>>>(aoh, aol, wh + D_ * D_, wl + D_ * D_,
                                           out, nullptr, 1.0f);
}

// round 10
// speedup vs baseline: 7.7537x; 1.3943x over previous
#include <cuda_runtime.h>
#include <cuda_bf16.h>
#include <cuda_fp16.h>
#include <stdint.h>
#include <math.h>

#define B_  8
#define S_  2048
#define D_  1024
#define H_  16
#define DK_ 64
#define M_  (B_*S_)   // 16384

// ---------------- scratch (device globals: allocation-free) ----------------
__device__ __half g_afq[M_ * D_];            // fp16 activations
__device__ __half g_afk[M_ * D_];
__device__ __half g_afv[M_ * D_];
__device__ __half g_w16[3 * D_ * D_];        // fp16 weights [N][K]: q, k, v
__device__ __half g_wo16[D_ * D_];           // fp16 Wo [N][K]
__device__ __half g_qf[M_ * D_];             // head-major fp16 q (log2e/32 folded)
__device__ __half g_kf[M_ * D_];
__device__ __half g_vf[M_ * D_];
__device__ __half g_aoh[M_ * D_];            // attention out fp16 hi/lo (feeds Wo)
__device__ __half g_aol[M_ * D_];

// ---------------- helpers ----------------
__device__ __forceinline__ uint32_t smem_u32(const void* p) {
    return (uint32_t)__cvta_generic_to_shared(p);
}
__device__ __forceinline__ void cpasync16(uint32_t s, const void* g) {
    asm volatile("cp.async.cg.shared.global [%0], [%1], 16;" :: "r"(s), "l"(g));
}
__device__ __forceinline__ void cp_commit() {
    asm volatile("cp.async.commit_group;" ::: "memory");
}
template<int N> __device__ __forceinline__ void cp_wait() {
    asm volatile("cp.async.wait_group %0;" :: "n"(N) : "memory");
}
__device__ __forceinline__ void ldsm_x4(uint32_t* r, uint32_t a) {
    asm volatile("ldmatrix.sync.aligned.m8n8.x4.shared.b16 {%0,%1,%2,%3}, [%4];"
                 : "=r"(r[0]), "=r"(r[1]), "=r"(r[2]), "=r"(r[3]) : "r"(a));
}
__device__ __forceinline__ void ldsm_x4_t(uint32_t* r, uint32_t a) {
    asm volatile("ldmatrix.sync.aligned.m8n8.x4.trans.shared.b16 {%0,%1,%2,%3}, [%4];"
                 : "=r"(r[0]), "=r"(r[1]), "=r"(r[2]), "=r"(r[3]) : "r"(a));
}
__device__ __forceinline__ void ldsm_x2(uint32_t* r, uint32_t a) {
    asm volatile("ldmatrix.sync.aligned.m8n8.x2.shared.b16 {%0,%1}, [%2];"
                 : "=r"(r[0]), "=r"(r[1]) : "r"(a));
}
__device__ __forceinline__ void mma16816h(float* d, const uint32_t* a, const uint32_t* b) {
    asm volatile(
        "mma.sync.aligned.m16n8k16.row.col.f32.f16.f16.f32 "
        "{%0,%1,%2,%3}, {%4,%5,%6,%7}, {%8,%9}, {%0,%1,%2,%3};"
        : "+f"(d[0]), "+f"(d[1]), "+f"(d[2]), "+f"(d[3])
        : "r"(a[0]), "r"(a[1]), "r"(a[2]), "r"(a[3]), "r"(b[0]), "r"(b[1]));
}
__device__ __forceinline__ float fexp2(float x) {
    float y; asm("ex2.approx.f32 %0, %1;" : "=f"(y) : "f"(x)); return y;
}
__device__ __forceinline__ uint32_t pkh2(float x, float y) {
    __half2 h2 = __floats2half2_rn(x, y);
    return *reinterpret_cast<uint32_t*>(&h2);
}
__device__ __forceinline__ void split2h(float x, float y, uint32_t& hi, uint32_t& lo) {
    __half2 h2 = __floats2half2_rn(x, y);
    float lx = x - __half2float(__low2half(h2));
    float ly = y - __half2float(__high2half(h2));
    __half2 l2 = __floats2half2_rn(lx, ly);
    hi = *reinterpret_cast<uint32_t*>(&h2);
    lo = *reinterpret_cast<uint32_t*>(&l2);
}

// 128B rows, 8x16B chunks, swizzle chunk' = chunk ^ (row & 7)
#define FOFF(r, c) ((uint32_t)((r) * 128 + ((((c) ^ ((r) & 7))) << 4)))

// q scale: d_model^-0.5 * log2(e) -> softmax in exp2 domain
#define QSCALE 0.04508422f

// ---------------- weight rearrange (all fp16) ----------------
__global__ void rearrange_w(const float* __restrict__ Wq, const float* __restrict__ Wk,
                            const float* __restrict__ Wv, const float* __restrict__ Wo) {
    int idx = blockIdx.x * blockDim.x + threadIdx.x;
    if (idx >= D_ * D_) return;
    int n = idx / D_;
    int k = idx % D_;
    int h = n >> 6, dk = n & 63;
    size_t src = ((size_t)h * D_ + k) * DK_ + dk;
    g_w16[idx]               = __float2half(Wq[src]);
    g_w16[D_ * D_ + idx]     = __float2half(Wk[src]);
    g_w16[2 * D_ * D_ + idx] = __float2half(Wv[src]);
    g_wo16[idx]              = __float2half(Wo[(size_t)n * D_ + k]);
}

// ---------------- activation convert (grid.y = 3: q, k, v) ----------------
__global__ void conv_fp16_3(const float* __restrict__ x0, const float* __restrict__ x1,
                            const float* __restrict__ x2,
                            __half* __restrict__ o0, __half* __restrict__ o1,
                            __half* __restrict__ o2) {
    int i = blockIdx.x * blockDim.x + threadIdx.x;
    const float* x = blockIdx.y == 0 ? x0 : (blockIdx.y == 1 ? x1 : x2);
    __half* o = blockIdx.y == 0 ? o0 : (blockIdx.y == 1 ? o1 : o2);
    float4 v = ((const float4*)x)[i];
    ((uint2*)o)[i] = make_uint2(pkh2(v.x, v.y), pkh2(v.z, v.w));
}

// ---------------- fp16 1-term GEMM, fused Q+K+V (grid.z = 3) ----------------
#define G1TILE 16384
#define G1STG  (2 * G1TILE)
#define G1SMEM (3 * G1STG)   // 96KB, 2 CTAs/SM

__global__ __launch_bounds__(256, 2)
void gemm_qkv(const __half* __restrict__ Aq, const __half* __restrict__ Ak,
              const __half* __restrict__ Av, const __half* __restrict__ W,
              __half* __restrict__ Cq, __half* __restrict__ Ck, __half* __restrict__ Cv) {
    extern __shared__ char smraw[];
    const uint32_t sb = smem_u32(smraw);
    const int z = blockIdx.z;
    const __half* A  = z == 0 ? Aq : (z == 1 ? Ak : Av);
    const __half* Bw = W + (size_t)z * D_ * D_;
    __half* Co = z == 0 ? Cq : (z == 1 ? Ck : Cv);
    const float scale = z == 0 ? QSCALE : 1.0f;

    const int tid = threadIdx.x;
    const int wid = tid >> 5, lane = tid & 31;
    const int bm = blockIdx.y * 128;
    const int bn = blockIdx.x * 128;
    const int warp_m = (wid & 1) * 64;
    const int warp_n = (wid >> 1) * 32;

    uint32_t soff[4];
    const __half *pA[4], *pB[4];
    #pragma unroll
    for (int i = 0; i < 4; ++i) {
        int lin = i * 256 + tid;
        int row = lin >> 3, c = lin & 7;
        soff[i] = FOFF(row, c);
        pA[i] = A  + (size_t)(bm + row) * D_ + c * 8;
        pB[i] = Bw + (size_t)(bn + row) * D_ + c * 8;
    }
    auto prefetch = [&](int t) {
        uint32_t stg = sb + (t % 3) * G1STG;
        int kofs = t * 64;
        #pragma unroll
        for (int i = 0; i < 4; ++i) {
            cpasync16(stg + soff[i],          pA[i] + kofs);
            cpasync16(stg + G1TILE + soff[i], pB[i] + kofs);
        }
    };
    prefetch(0); cp_commit();
    prefetch(1); cp_commit();

    const int arow = warp_m + (lane & 15);
    const int brow = warp_n + (lane & 7);
    float acc[4][4][4] = {};

    const int NT = D_ / 64;   // 16
    for (int t = 0; t < NT; ++t) {
        if (t == NT - 1) cp_wait<0>(); else cp_wait<1>();
        __syncthreads();
        if (t + 2 < NT) { prefetch(t + 2); cp_commit(); }
        uint32_t stg = sb + (t % 3) * G1STG;

        #pragma unroll
        for (int kk = 0; kk < 4; ++kk) {
            uint32_t ao = FOFF(arow, kk * 2 + (lane >> 4));
            uint32_t bo = FOFF(brow, kk * 2 + ((lane >> 3) & 1));
            uint32_t a4[4][4], b2[4][2];
            #pragma unroll
            for (int mb = 0; mb < 4; ++mb)
                ldsm_x4(a4[mb], stg + ao + mb * 2048);
            #pragma unroll
            for (int nb = 0; nb < 4; ++nb)
                ldsm_x2(b2[nb], stg + G1TILE + bo + nb * 1024);
            #pragma unroll
            for (int mb = 0; mb < 4; ++mb)
                #pragma unroll
                for (int nb = 0; nb < 4; ++nb)
                    mma16816h(acc[mb][nb], a4[mb], b2[nb]);
        }
    }

    const int tm = bm + warp_m + (lane >> 2);
    const int tn = bn + warp_n + (lane & 3) * 2;
    #pragma unroll
    for (int mb = 0; mb < 4; ++mb)
        #pragma unroll
        for (int nb = 0; nb < 4; ++nb) {
            int n = tn + nb * 8;
            int h = n >> 6, dk = n & 63;
            #pragma unroll
            for (int hh = 0; hh < 2; ++hh) {
                int row = tm + mb * 16 + hh * 8;
                int b = row >> 11, s = row & 2047;
                size_t idx = (((size_t)b * H_ + h) * S_ + s) * 64 + dk;
                *(uint32_t*)(Co + idx) = pkh2(acc[mb][nb][hh * 2] * scale,
                                              acc[mb][nb][hh * 2 + 1] * scale);
            }
        }
}

// ---------------- fp16 2-term GEMM for Wo: C = (Ah+Al) * B^T, fp32 out ----------------
#define WTILE 16384
#define WSTG  (3 * WTILE)      // Ah, Al, B = 48KB
#define WSMEM (3 * WSTG)       // 144KB

__global__ __launch_bounds__(256, 1)
void gemm_wo(const __half* __restrict__ Ah, const __half* __restrict__ Al,
             const __half* __restrict__ Bw, float* __restrict__ Cf) {
    extern __shared__ char smraw[];
    const uint32_t sb = smem_u32(smraw);
    const int tid = threadIdx.x;
    const int wid = tid >> 5, lane = tid & 31;
    const int bm = blockIdx.y * 128;
    const int bn = blockIdx.x * 128;
    const int warp_m = (wid & 1) * 64;
    const int warp_n = (wid >> 1) * 32;

    uint32_t soff[4];
    const __half *pA[4], *pAl[4], *pB[4];
    #pragma unroll
    for (int i = 0; i < 4; ++i) {
        int lin = i * 256 + tid;
        int row = lin >> 3, c = lin & 7;
        soff[i] = FOFF(row, c);
        pA[i]  = Ah + (size_t)(bm + row) * D_ + c * 8;
        pAl[i] = Al + (size_t)(bm + row) * D_ + c * 8;
        pB[i]  = Bw + (size_t)(bn + row) * D_ + c * 8;
    }
    auto prefetch = [&](int t) {
        uint32_t stg = sb + (t % 3) * WSTG;
        int kofs = t * 64;
        #pragma unroll
        for (int i = 0; i < 4; ++i) {
            cpasync16(stg + soff[i],             pA[i]  + kofs);
            cpasync16(stg + WTILE + soff[i],     pAl[i] + kofs);
            cpasync16(stg + 2 * WTILE + soff[i], pB[i]  + kofs);
        }
    };
    prefetch(0); cp_commit();
    prefetch(1); cp_commit();

    const int arow = warp_m + (lane & 15);
    const int brow = warp_n + (lane & 7);
    float acc[4][4][4] = {};

    const int NT = D_ / 64;   // 16
    for (int t = 0; t < NT; ++t) {
        if (t == NT - 1) cp_wait<0>(); else cp_wait<1>();
        __syncthreads();
        if (t + 2 < NT) { prefetch(t + 2); cp_commit(); }
        uint32_t stg = sb + (t % 3) * WSTG;

        #pragma unroll
        for (int kk = 0; kk < 4; ++kk) {
            uint32_t ao = FOFF(arow, kk * 2 + (lane >> 4));
            uint32_t bo = FOFF(brow, kk * 2 + ((lane >> 3) & 1));
            uint32_t ah4[4][4], al4[4][4], b2[4][2];
            #pragma unroll
            for (int mb = 0; mb < 4; ++mb) {
                ldsm_x4(ah4[mb], stg + ao + mb * 2048);
                ldsm_x4(al4[mb], stg + WTILE + ao + mb * 2048);
            }
            #pragma unroll
            for (int nb = 0; nb < 4; ++nb)
                ldsm_x2(b2[nb], stg + 2 * WTILE + bo + nb * 1024);
            #pragma unroll
            for (int mb = 0; mb < 4; ++mb)
                #pragma unroll
                for (int nb = 0; nb < 4; ++nb)
                    mma16816h(acc[mb][nb], ah4[mb], b2[nb]);
            #pragma unroll
            for (int mb = 0; mb < 4; ++mb)
                #pragma unroll
                for (int nb = 0; nb < 4; ++nb)
                    mma16816h(acc[mb][nb], al4[mb], b2[nb]);
        }
    }

    const int tm = bm + warp_m + (lane >> 2);
    const int tn = bn + warp_n + (lane & 3) * 2;
    #pragma unroll
    for (int mb = 0; mb < 4; ++mb)
        #pragma unroll
        for (int nb = 0; nb < 4; ++nb) {
            float* c0 = Cf + (size_t)(tm + mb * 16) * D_ + tn + nb * 8;
            *(float2*)c0 = make_float2(acc[mb][nb][0], acc[mb][nb][1]);
            float* c1 = c0 + 8 * D_;
            *(float2*)c1 = make_float2(acc[mb][nb][2], acc[mb][nb][3]);
        }
}

// ---------------- flash attention fp16 (QK 1-term, PV 1-term P) ----------------
// smem: Q 16K + 3 KV stages of 32K (K 16K, V 16K) = 112K
#define KVSTG 32768
#define FLASH_SMEM (16384 + 3 * KVSTG)

__global__ __launch_bounds__(256, 1)
void flash_fp16(const __half* __restrict__ qf, const __half* __restrict__ kf,
                const __half* __restrict__ vf,
                __half* __restrict__ aoh, __half* __restrict__ aol) {
    extern __shared__ char smraw[];
    const uint32_t sb = smem_u32(smraw);
    const int tid = threadIdx.x;
    const int wid = tid >> 5, lane = tid & 31;
    const int bh = blockIdx.y;
    const int s0 = blockIdx.x * 128;

    const size_t hb = (size_t)bh * S_ * 64;
    const __half* qp = qf + hb + (size_t)s0 * 64;
    const __half* kp = kf + hb;
    const __half* vp = vf + hb;

    #pragma unroll
    for (int i = 0; i < 4; ++i) {
        int lin = i * 256 + tid;
        int r = lin >> 3, c = lin & 7;
        cpasync16(sb + FOFF(r, c), qp + r * 64 + c * 8);
    }
    auto kvload = [&](int t) {
        uint32_t stg = sb + 16384 + (t % 3) * KVSTG;
        size_t tofs = (size_t)(t * 128) * 64;
        #pragma unroll
        for (int i = 0; i < 4; ++i) {
            int lin = i * 256 + tid;
            int r = lin >> 3, c = lin & 7;
            uint32_t o = FOFF(r, c);
            size_t g = tofs + r * 64 + c * 8;
            cpasync16(stg + o,         kp + g);
            cpasync16(stg + 16384 + o, vp + g);
        }
    };
    kvload(0); cp_commit();
    kvload(1); cp_commit();

    const int warp_m = wid * 16;
    uint32_t qfr[4][4];
    float Oacc[8][4] = {};
    float m0 = -1e30f, m1 = -1e30f, l0 = 0.f, l1 = 0.f;

    const int NT = S_ / 128;   // 16
    for (int t = 0; t < NT; ++t) {
        if (t == NT - 1) cp_wait<0>(); else cp_wait<1>();
        __syncthreads();
        if (t + 2 < NT) { kvload(t + 2); cp_commit(); }
        uint32_t stg = sb + 16384 + (t % 3) * KVSTG;

        if (t == 0) {
            #pragma unroll
            for (int kb = 0; kb < 4; ++kb) {
                int r = warp_m + (lane & 15);
                int c = kb * 2 + (lane >> 4);
                ldsm_x4(qfr[kb], sb + FOFF(r, c));
            }
        }

        // ---- S = Q K^T (fp16, 1 term), log2 domain ----
        float sacc[16][4] = {};
        #pragma unroll
        for (int kb = 0; kb < 4; ++kb) {
            #pragma unroll
            for (int nbp = 0; nbp < 8; ++nbp) {
                int r = nbp * 16 + ((lane >> 4) << 3) + (lane & 7);
                int c = kb * 2 + ((lane >> 3) & 1);
                uint32_t khf[4];
                ldsm_x4(khf, stg + FOFF(r, c));
                mma16816h(sacc[2 * nbp],     qfr[kb], khf);
                mma16816h(sacc[2 * nbp + 1], qfr[kb], khf + 2);
            }
        }

        // ---- row max ----
        float mx0 = -1e30f, mx1 = -1e30f;
        #pragma unroll
        for (int nb = 0; nb < 16; ++nb) {
            mx0 = fmaxf(mx0, fmaxf(sacc[nb][0], sacc[nb][1]));
            mx1 = fmaxf(mx1, fmaxf(sacc[nb][2], sacc[nb][3]));
        }
        mx0 = fmaxf(mx0, __shfl_xor_sync(0xffffffffu, mx0, 1));
        mx0 = fmaxf(mx0, __shfl_xor_sync(0xffffffffu, mx0, 2));
        mx1 = fmaxf(mx1, __shfl_xor_sync(0xffffffffu, mx1, 1));
        mx1 = fmaxf(mx1, __shfl_xor_sync(0xffffffffu, mx1, 2));
        float mn0 = fmaxf(m0, mx0), mn1 = fmaxf(m1, mx1);
        float c0 = fexp2(m0 - mn0), c1 = fexp2(m1 - mn1);
        m0 = mn0; m1 = mn1;
        #pragma unroll
        for (int nb = 0; nb < 8; ++nb) {
            Oacc[nb][0] *= c0; Oacc[nb][1] *= c0;
            Oacc[nb][2] *= c1; Oacc[nb][3] *= c1;
        }
        l0 *= c0; l1 *= c1;

        // ---- per-kb: exp2 -> fp16 P -> PV (single term) ----
        float sum0 = 0.f, sum1 = 0.f;
        #pragma unroll
        for (int kb = 0; kb < 8; ++kb) {
            float e00 = fexp2(sacc[2 * kb][0] - mn0);
            float e01 = fexp2(sacc[2 * kb][1] - mn0);
            float e02 = fexp2(sacc[2 * kb][2] - mn1);
            float e03 = fexp2(sacc[2 * kb][3] - mn1);
            float e10 = fexp2(sacc[2 * kb + 1][0] - mn0);
            float e11 = fexp2(sacc[2 * kb + 1][1] - mn0);
            float e12 = fexp2(sacc[2 * kb + 1][2] - mn1);
            float e13 = fexp2(sacc[2 * kb + 1][3] - mn1);
            sum0 += (e00 + e01) + (e10 + e11);
            sum1 += (e02 + e03) + (e12 + e13);
            uint32_t ph[4];
            ph[0] = pkh2(e00, e01);
            ph[1] = pkh2(e02, e03);
            ph[2] = pkh2(e10, e11);
            ph[3] = pkh2(e12, e13);
            #pragma unroll
            for (int nbp = 0; nbp < 4; ++nbp) {
                int r = kb * 16 + (((lane >> 3) & 1) << 3) + (lane & 7);
                int c = nbp * 2 + (lane >> 4);
                uint32_t vfr[4];
                ldsm_x4_t(vfr, stg + 16384 + FOFF(r, c));
                mma16816h(Oacc[2 * nbp],     ph, vfr);
                mma16816h(Oacc[2 * nbp + 1], ph, vfr + 2);
            }
        }
        sum0 += __shfl_xor_sync(0xffffffffu, sum0, 1);
        sum0 += __shfl_xor_sync(0xffffffffu, sum0, 2);
        sum1 += __shfl_xor_sync(0xffffffffu, sum1, 1);
        sum1 += __shfl_xor_sync(0xffffffffu, sum1, 2);
        l0 += sum0;
        l1 += sum1;
    }

    // ---- epilogue: normalize, split to fp16 hi/lo for Wo GEMM ----
    float inv0 = 1.f / l0, inv1 = 1.f / l1;
    int b = bh >> 4, h = bh & 15;
    int r0 = s0 + warp_m + (lane >> 2);
    size_t base0 = ((size_t)b * S_ + r0) * D_ + h * 64 + (lane & 3) * 2;
    size_t base1 = base0 + 8 * D_;
    #pragma unroll
    for (int nb = 0; nb < 8; ++nb) {
        uint32_t hi, lo;
        split2h(Oacc[nb][0] * inv0, Oacc[nb][1] * inv0, hi, lo);
        *(uint32_t*)(aoh + base0 + nb * 8) = hi;
        *(uint32_t*)(aol + base0 + nb * 8) = lo;
        split2h(Oacc[nb][2] * inv1, Oacc[nb][3] * inv1, hi, lo);
        *(uint32_t*)(aoh + base1 + nb * 8) = hi;
        *(uint32_t*)(aol + base1 + nb * 8) = lo;
    }
}

// ---------------- launch ----------------
extern "C" void kernel_launch(void* const* d_in, const int* in_sizes, int n_in,
                              void* d_out, int out_size) {
    const float* query = (const float*)d_in[0];
    const float* key   = (const float*)d_in[1];
    const float* value = (const float*)d_in[2];
    const float* Wq    = (const float*)d_in[3];
    const float* Wk    = (const float*)d_in[4];
    const float* Wv    = (const float*)d_in[5];
    const float* Wo    = (const float*)d_in[6];
    float* out = (float*)d_out;

    __half *afq, *afk, *afv, *w16, *wo16, *qf, *kf, *vf, *aoh, *aol;
    cudaGetSymbolAddress((void**)&afq,  g_afq);
    cudaGetSymbolAddress((void**)&afk,  g_afk);
    cudaGetSymbolAddress((void**)&afv,  g_afv);
    cudaGetSymbolAddress((void**)&w16,  g_w16);
    cudaGetSymbolAddress((void**)&wo16, g_wo16);
    cudaGetSymbolAddress((void**)&qf,   g_qf);
    cudaGetSymbolAddress((void**)&kf,   g_kf);
    cudaGetSymbolAddress((void**)&vf,   g_vf);
    cudaGetSymbolAddress((void**)&aoh,  g_aoh);
    cudaGetSymbolAddress((void**)&aol,  g_aol);

    cudaFuncSetAttribute((const void*)gemm_qkv, cudaFuncAttributeMaxDynamicSharedMemorySize, G1SMEM);
    cudaFuncSetAttribute((const void*)gemm_wo, cudaFuncAttributeMaxDynamicSharedMemorySize, WSMEM);
    cudaFuncSetAttribute((const void*)flash_fp16, cudaFuncAttributeMaxDynamicSharedMemorySize, FLASH_SMEM);

    rearrange_w<<<(D_ * D_ + 255) / 256, 256>>>(Wq, Wk, Wv, Wo);

    int cvtBlocks = (M_ * D_ / 4) / 256;

    // Q+K+V converts fused, then Q+K+V projections fused (fp16 1-term)
    conv_fp16_3<<<dim3(cvtBlocks, 3), 256>>>(query, key, value, afq, afk, afv);
    gemm_qkv<<<dim3(8, 128, 3), 256, G1SMEM>>>(afq, afk, afv, w16, qf, kf, vf);

    // flash attention (fp16, single-P PV)
    flash_fp16<<<dim3(S_ / 128, B_ * H_), 256, FLASH_SMEM>>>(qf, kf, vf, aoh, aol);

    // output projection: fp16 2-term
    gemm_wo<<<dim3(8, 128), 256, WSMEM>>>(aoh, aol, wo16, out);
}

// round 11
// speedup vs baseline: 8.1062x; 1.0455x over previous
#include <cuda_runtime.h>
#include <cuda_bf16.h>
#include <cuda_fp16.h>
#include <stdint.h>
#include <math.h>

#define B_  8
#define S_  2048
#define D_  1024
#define H_  16
#define DK_ 64
#define M_  (B_*S_)   // 16384

// ---------------- scratch (device globals: allocation-free) ----------------
__device__ __half g_afq[M_ * D_];            // fp16 activations
__device__ __half g_afk[M_ * D_];
__device__ __half g_afv[M_ * D_];
__device__ __half g_w16[3 * D_ * D_];        // fp16 weights [N][K]: q, k, v
__device__ __half g_wo16[D_ * D_];           // fp16 Wo [N][K]
__device__ __half g_qf[M_ * D_];             // head-major fp16 q (log2e/32 folded)
__device__ __half g_kf[M_ * D_];
__device__ __half g_vf[M_ * D_];
__device__ __half g_aoh[M_ * D_];            // attention out fp16 hi/lo (feeds Wo)
__device__ __half g_aol[M_ * D_];

// ---------------- helpers ----------------
__device__ __forceinline__ uint32_t smem_u32(const void* p) {
    return (uint32_t)__cvta_generic_to_shared(p);
}
__device__ __forceinline__ void cpasync16(uint32_t s, const void* g) {
    asm volatile("cp.async.cg.shared.global [%0], [%1], 16;" :: "r"(s), "l"(g));
}
__device__ __forceinline__ void cp_commit() {
    asm volatile("cp.async.commit_group;" ::: "memory");
}
template<int N> __device__ __forceinline__ void cp_wait() {
    asm volatile("cp.async.wait_group %0;" :: "n"(N) : "memory");
}
__device__ __forceinline__ void ldsm_x4(uint32_t* r, uint32_t a) {
    asm volatile("ldmatrix.sync.aligned.m8n8.x4.shared.b16 {%0,%1,%2,%3}, [%4];"
                 : "=r"(r[0]), "=r"(r[1]), "=r"(r[2]), "=r"(r[3]) : "r"(a));
}
__device__ __forceinline__ void ldsm_x4_t(uint32_t* r, uint32_t a) {
    asm volatile("ldmatrix.sync.aligned.m8n8.x4.trans.shared.b16 {%0,%1,%2,%3}, [%4];"
                 : "=r"(r[0]), "=r"(r[1]), "=r"(r[2]), "=r"(r[3]) : "r"(a));
}
__device__ __forceinline__ void ldsm_x2(uint32_t* r, uint32_t a) {
    asm volatile("ldmatrix.sync.aligned.m8n8.x2.shared.b16 {%0,%1}, [%2];"
                 : "=r"(r[0]), "=r"(r[1]) : "r"(a));
}
__device__ __forceinline__ void mma16816h(float* d, const uint32_t* a, const uint32_t* b) {
    asm volatile(
        "mma.sync.aligned.m16n8k16.row.col.f32.f16.f16.f32 "
        "{%0,%1,%2,%3}, {%4,%5,%6,%7}, {%8,%9}, {%0,%1,%2,%3};"
        : "+f"(d[0]), "+f"(d[1]), "+f"(d[2]), "+f"(d[3])
        : "r"(a[0]), "r"(a[1]), "r"(a[2]), "r"(a[3]), "r"(b[0]), "r"(b[1]));
}
__device__ __forceinline__ float fexp2(float x) {
    float y; asm("ex2.approx.f32 %0, %1;" : "=f"(y) : "f"(x)); return y;
}
__device__ __forceinline__ uint32_t pkh2(float x, float y) {
    __half2 h2 = __floats2half2_rn(x, y);
    return *reinterpret_cast<uint32_t*>(&h2);
}
__device__ __forceinline__ void split2h(float x, float y, uint32_t& hi, uint32_t& lo) {
    __half2 h2 = __floats2half2_rn(x, y);
    float lx = x - __half2float(__low2half(h2));
    float ly = y - __half2float(__high2half(h2));
    __half2 l2 = __floats2half2_rn(lx, ly);
    hi = *reinterpret_cast<uint32_t*>(&h2);
    lo = *reinterpret_cast<uint32_t*>(&l2);
}

// 128B rows, 8x16B chunks, swizzle chunk' = chunk ^ (row & 7)
#define FOFF(r, c) ((uint32_t)((r) * 128 + ((((c) ^ ((r) & 7))) << 4)))

// q scale: d_model^-0.5 * log2(e) -> softmax in exp2 domain
#define QSCALE 0.04508422f

// ---------------- weight rearrange (all fp16) ----------------
__global__ void rearrange_w(const float* __restrict__ Wq, const float* __restrict__ Wk,
                            const float* __restrict__ Wv, const float* __restrict__ Wo) {
    int idx = blockIdx.x * blockDim.x + threadIdx.x;
    if (idx >= D_ * D_) return;
    int n = idx / D_;
    int k = idx % D_;
    int h = n >> 6, dk = n & 63;
    size_t src = ((size_t)h * D_ + k) * DK_ + dk;
    g_w16[idx]               = __float2half(Wq[src]);
    g_w16[D_ * D_ + idx]     = __float2half(Wk[src]);
    g_w16[2 * D_ * D_ + idx] = __float2half(Wv[src]);
    g_wo16[idx]              = __float2half(Wo[(size_t)n * D_ + k]);
}

// ---------------- activation convert (grid.y = 3: q, k, v) ----------------
__global__ void conv_fp16_3(const float* __restrict__ x0, const float* __restrict__ x1,
                            const float* __restrict__ x2,
                            __half* __restrict__ o0, __half* __restrict__ o1,
                            __half* __restrict__ o2) {
    int i = blockIdx.x * blockDim.x + threadIdx.x;
    const float* x = blockIdx.y == 0 ? x0 : (blockIdx.y == 1 ? x1 : x2);
    __half* o = blockIdx.y == 0 ? o0 : (blockIdx.y == 1 ? o1 : o2);
    float4 v = ((const float4*)x)[i];
    ((uint2*)o)[i] = make_uint2(pkh2(v.x, v.y), pkh2(v.z, v.w));
}

// ---------------- fp16 1-term GEMM, fused Q+K+V (grid.z = 3) ----------------
#define G1TILE 16384
#define G1STG  (2 * G1TILE)
#define G1SMEM (3 * G1STG)   // 96KB, 2 CTAs/SM

__global__ __launch_bounds__(256, 2)
void gemm_qkv(const __half* __restrict__ Aq, const __half* __restrict__ Ak,
              const __half* __restrict__ Av, const __half* __restrict__ W,
              __half* __restrict__ Cq, __half* __restrict__ Ck, __half* __restrict__ Cv) {
    extern __shared__ char smraw[];
    const uint32_t sb = smem_u32(smraw);
    const int z = blockIdx.z;
    const __half* A  = z == 0 ? Aq : (z == 1 ? Ak : Av);
    const __half* Bw = W + (size_t)z * D_ * D_;
    __half* Co = z == 0 ? Cq : (z == 1 ? Ck : Cv);
    const float scale = z == 0 ? QSCALE : 1.0f;

    const int tid = threadIdx.x;
    const int wid = tid >> 5, lane = tid & 31;
    const int bm = blockIdx.y * 128;
    const int bn = blockIdx.x * 128;
    const int warp_m = (wid & 1) * 64;
    const int warp_n = (wid >> 1) * 32;

    uint32_t soff[4];
    const __half *pA[4], *pB[4];
    #pragma unroll
    for (int i = 0; i < 4; ++i) {
        int lin = i * 256 + tid;
        int row = lin >> 3, c = lin & 7;
        soff[i] = FOFF(row, c);
        pA[i] = A  + (size_t)(bm + row) * D_ + c * 8;
        pB[i] = Bw + (size_t)(bn + row) * D_ + c * 8;
    }
    auto prefetch = [&](int t) {
        uint32_t stg = sb + (t % 3) * G1STG;
        int kofs = t * 64;
        #pragma unroll
        for (int i = 0; i < 4; ++i) {
            cpasync16(stg + soff[i],          pA[i] + kofs);
            cpasync16(stg + G1TILE + soff[i], pB[i] + kofs);
        }
    };
    prefetch(0); cp_commit();
    prefetch(1); cp_commit();

    const int arow = warp_m + (lane & 15);
    const int brow = warp_n + (lane & 7);
    float acc[4][4][4] = {};

    const int NT = D_ / 64;   // 16
    for (int t = 0; t < NT; ++t) {
        if (t == NT - 1) cp_wait<0>(); else cp_wait<1>();
        __syncthreads();
        if (t + 2 < NT) { prefetch(t + 2); cp_commit(); }
        uint32_t stg = sb + (t % 3) * G1STG;

        #pragma unroll
        for (int kk = 0; kk < 4; ++kk) {
            uint32_t ao = FOFF(arow, kk * 2 + (lane >> 4));
            uint32_t bo = FOFF(brow, kk * 2 + ((lane >> 3) & 1));
            uint32_t a4[4][4], b2[4][2];
            #pragma unroll
            for (int mb = 0; mb < 4; ++mb)
                ldsm_x4(a4[mb], stg + ao + mb * 2048);
            #pragma unroll
            for (int nb = 0; nb < 4; ++nb)
                ldsm_x2(b2[nb], stg + G1TILE + bo + nb * 1024);
            #pragma unroll
            for (int mb = 0; mb < 4; ++mb)
                #pragma unroll
                for (int nb = 0; nb < 4; ++nb)
                    mma16816h(acc[mb][nb], a4[mb], b2[nb]);
        }
    }

    const int tm = bm + warp_m + (lane >> 2);
    const int tn = bn + warp_n + (lane & 3) * 2;
    #pragma unroll
    for (int mb = 0; mb < 4; ++mb)
        #pragma unroll
        for (int nb = 0; nb < 4; ++nb) {
            int n = tn + nb * 8;
            int h = n >> 6, dk = n & 63;
            #pragma unroll
            for (int hh = 0; hh < 2; ++hh) {
                int row = tm + mb * 16 + hh * 8;
                int b = row >> 11, s = row & 2047;
                size_t idx = (((size_t)b * H_ + h) * S_ + s) * 64 + dk;
                *(uint32_t*)(Co + idx) = pkh2(acc[mb][nb][hh * 2] * scale,
                                              acc[mb][nb][hh * 2 + 1] * scale);
            }
        }
}

// ---------------- fp16 2-term GEMM for Wo (2-stage, 2 CTAs/SM) ----------------
#define WTILE 16384
#define WSTG  (3 * WTILE)      // Ah, Al, B = 48KB
#define WSMEM (2 * WSTG)       // 96KB

__global__ __launch_bounds__(256, 2)
void gemm_wo(const __half* __restrict__ Ah, const __half* __restrict__ Al,
             const __half* __restrict__ Bw, float* __restrict__ Cf) {
    extern __shared__ char smraw[];
    const uint32_t sb = smem_u32(smraw);
    const int tid = threadIdx.x;
    const int wid = tid >> 5, lane = tid & 31;
    const int bm = blockIdx.y * 128;
    const int bn = blockIdx.x * 128;
    const int warp_m = (wid & 1) * 64;
    const int warp_n = (wid >> 1) * 32;

    uint32_t soff[4];
    const __half *pA[4], *pAl[4], *pB[4];
    #pragma unroll
    for (int i = 0; i < 4; ++i) {
        int lin = i * 256 + tid;
        int row = lin >> 3, c = lin & 7;
        soff[i] = FOFF(row, c);
        pA[i]  = Ah + (size_t)(bm + row) * D_ + c * 8;
        pAl[i] = Al + (size_t)(bm + row) * D_ + c * 8;
        pB[i]  = Bw + (size_t)(bn + row) * D_ + c * 8;
    }
    auto prefetch = [&](int t) {
        uint32_t stg = sb + (t & 1) * WSTG;
        int kofs = t * 64;
        #pragma unroll
        for (int i = 0; i < 4; ++i) {
            cpasync16(stg + soff[i],             pA[i]  + kofs);
            cpasync16(stg + WTILE + soff[i],     pAl[i] + kofs);
            cpasync16(stg + 2 * WTILE + soff[i], pB[i]  + kofs);
        }
    };
    prefetch(0); cp_commit();

    const int arow = warp_m + (lane & 15);
    const int brow = warp_n + (lane & 7);
    float acc[4][4][4] = {};

    const int NT = D_ / 64;   // 16
    for (int t = 0; t < NT; ++t) {
        cp_wait<0>();
        __syncthreads();
        if (t + 1 < NT) { prefetch(t + 1); cp_commit(); }
        uint32_t stg = sb + (t & 1) * WSTG;

        #pragma unroll
        for (int kk = 0; kk < 4; ++kk) {
            uint32_t ao = FOFF(arow, kk * 2 + (lane >> 4));
            uint32_t bo = FOFF(brow, kk * 2 + ((lane >> 3) & 1));
            uint32_t ah4[4][4], al4[4][4], b2[4][2];
            #pragma unroll
            for (int mb = 0; mb < 4; ++mb) {
                ldsm_x4(ah4[mb], stg + ao + mb * 2048);
                ldsm_x4(al4[mb], stg + WTILE + ao + mb * 2048);
            }
            #pragma unroll
            for (int nb = 0; nb < 4; ++nb)
                ldsm_x2(b2[nb], stg + 2 * WTILE + bo + nb * 1024);
            #pragma unroll
            for (int mb = 0; mb < 4; ++mb)
                #pragma unroll
                for (int nb = 0; nb < 4; ++nb)
                    mma16816h(acc[mb][nb], ah4[mb], b2[nb]);
            #pragma unroll
            for (int mb = 0; mb < 4; ++mb)
                #pragma unroll
                for (int nb = 0; nb < 4; ++nb)
                    mma16816h(acc[mb][nb], al4[mb], b2[nb]);
        }
        __syncthreads();
    }

    const int tm = bm + warp_m + (lane >> 2);
    const int tn = bn + warp_n + (lane & 3) * 2;
    #pragma unroll
    for (int mb = 0; mb < 4; ++mb)
        #pragma unroll
        for (int nb = 0; nb < 4; ++nb) {
            float* c0 = Cf + (size_t)(tm + mb * 16) * D_ + tn + nb * 8;
            *(float2*)c0 = make_float2(acc[mb][nb][0], acc[mb][nb][1]);
            float* c1 = c0 + 8 * D_;
            *(float2*)c1 = make_float2(acc[mb][nb][2], acc[mb][nb][3]);
        }
}

// ---------------- flash attention fp16 (KV tile 64, 2 CTAs/SM) ----------------
// smem: Q 16K + 3 KV stages of 16K (K 8K, V 8K) = 64K -> 2 CTAs/SM
#define KVSTG 16384
#define FLASH_SMEM (16384 + 3 * KVSTG)

__global__ __launch_bounds__(256, 2)
void flash_fp16(const __half* __restrict__ qf, const __half* __restrict__ kf,
                const __half* __restrict__ vf,
                __half* __restrict__ aoh, __half* __restrict__ aol) {
    extern __shared__ char smraw[];
    const uint32_t sb = smem_u32(smraw);
    const int tid = threadIdx.x;
    const int wid = tid >> 5, lane = tid & 31;
    const int bh = blockIdx.y;
    const int s0 = blockIdx.x * 128;

    const size_t hb = (size_t)bh * S_ * 64;
    const __half* qp = qf + hb + (size_t)s0 * 64;
    const __half* kp = kf + hb;
    const __half* vp = vf + hb;

    #pragma unroll
    for (int i = 0; i < 4; ++i) {
        int lin = i * 256 + tid;
        int r = lin >> 3, c = lin & 7;
        cpasync16(sb + FOFF(r, c), qp + r * 64 + c * 8);
    }
    auto kvload = [&](int t) {
        uint32_t stg = sb + 16384 + (t % 3) * KVSTG;
        size_t tofs = (size_t)(t * 64) * 64;
        #pragma unroll
        for (int i = 0; i < 2; ++i) {
            int lin = i * 256 + tid;
            int r = lin >> 3, c = lin & 7;
            uint32_t o = FOFF(r, c);
            size_t g = tofs + r * 64 + c * 8;
            cpasync16(stg + o,        kp + g);
            cpasync16(stg + 8192 + o, vp + g);
        }
    };
    kvload(0); cp_commit();
    kvload(1); cp_commit();

    const int warp_m = wid * 16;
    uint32_t qfr[4][4];
    float Oacc[8][4] = {};
    float m0 = -1e30f, m1 = -1e30f, l0 = 0.f, l1 = 0.f;

    const int NT = S_ / 64;   // 32
    for (int t = 0; t < NT; ++t) {
        if (t == NT - 1) cp_wait<0>(); else cp_wait<1>();
        __syncthreads();
        if (t + 2 < NT) { kvload(t + 2); cp_commit(); }
        uint32_t stg = sb + 16384 + (t % 3) * KVSTG;

        if (t == 0) {
            #pragma unroll
            for (int kb = 0; kb < 4; ++kb) {
                int r = warp_m + (lane & 15);
                int c = kb * 2 + (lane >> 4);
                ldsm_x4(qfr[kb], sb + FOFF(r, c));
            }
        }

        // ---- S = Q K^T (fp16, 1 term), log2 domain ----
        float sacc[8][4] = {};
        #pragma unroll
        for (int kb = 0; kb < 4; ++kb) {
            #pragma unroll
            for (int nbp = 0; nbp < 4; ++nbp) {
                int r = nbp * 16 + ((lane >> 4) << 3) + (lane & 7);
                int c = kb * 2 + ((lane >> 3) & 1);
                uint32_t khf[4];
                ldsm_x4(khf, stg + FOFF(r, c));
                mma16816h(sacc[2 * nbp],     qfr[kb], khf);
                mma16816h(sacc[2 * nbp + 1], qfr[kb], khf + 2);
            }
        }

        // ---- row max ----
        float mx0 = -1e30f, mx1 = -1e30f;
        #pragma unroll
        for (int nb = 0; nb < 8; ++nb) {
            mx0 = fmaxf(mx0, fmaxf(sacc[nb][0], sacc[nb][1]));
            mx1 = fmaxf(mx1, fmaxf(sacc[nb][2], sacc[nb][3]));
        }
        mx0 = fmaxf(mx0, __shfl_xor_sync(0xffffffffu, mx0, 1));
        mx0 = fmaxf(mx0, __shfl_xor_sync(0xffffffffu, mx0, 2));
        mx1 = fmaxf(mx1, __shfl_xor_sync(0xffffffffu, mx1, 1));
        mx1 = fmaxf(mx1, __shfl_xor_sync(0xffffffffu, mx1, 2));
        float mn0 = fmaxf(m0, mx0), mn1 = fmaxf(m1, mx1);
        float c0 = fexp2(m0 - mn0), c1 = fexp2(m1 - mn1);
        m0 = mn0; m1 = mn1;
        #pragma unroll
        for (int nb = 0; nb < 8; ++nb) {
            Oacc[nb][0] *= c0; Oacc[nb][1] *= c0;
            Oacc[nb][2] *= c1; Oacc[nb][3] *= c1;
        }
        l0 *= c0; l1 *= c1;

        // ---- per-kb: exp2 -> fp16 P -> PV ----
        float sum0 = 0.f, sum1 = 0.f;
        #pragma unroll
        for (int kb = 0; kb < 4; ++kb) {
            float e00 = fexp2(sacc[2 * kb][0] - mn0);
            float e01 = fexp2(sacc[2 * kb][1] - mn0);
            float e02 = fexp2(sacc[2 * kb][2] - mn1);
            float e03 = fexp2(sacc[2 * kb][3] - mn1);
            float e10 = fexp2(sacc[2 * kb + 1][0] - mn0);
            float e11 = fexp2(sacc[2 * kb + 1][1] - mn0);
            float e12 = fexp2(sacc[2 * kb + 1][2] - mn1);
            float e13 = fexp2(sacc[2 * kb + 1][3] - mn1);
            sum0 += (e00 + e01) + (e10 + e11);
            sum1 += (e02 + e03) + (e12 + e13);
            uint32_t ph[4];
            ph[0] = pkh2(e00, e01);
            ph[1] = pkh2(e02, e03);
            ph[2] = pkh2(e10, e11);
            ph[3] = pkh2(e12, e13);
            #pragma unroll
            for (int nbp = 0; nbp < 4; ++nbp) {
                int r = kb * 16 + (((lane >> 3) & 1) << 3) + (lane & 7);
                int c = nbp * 2 + (lane >> 4);
                uint32_t vfr[4];
                ldsm_x4_t(vfr, stg + 8192 + FOFF(r, c));
                mma16816h(Oacc[2 * nbp],     ph, vfr);
                mma16816h(Oacc[2 * nbp + 1], ph, vfr + 2);
            }
        }
        sum0 += __shfl_xor_sync(0xffffffffu, sum0, 1);
        sum0 += __shfl_xor_sync(0xffffffffu, sum0, 2);
        sum1 += __shfl_xor_sync(0xffffffffu, sum1, 1);
        sum1 += __shfl_xor_sync(0xffffffffu, sum1, 2);
        l0 += sum0;
        l1 += sum1;
    }

    // ---- epilogue: normalize, split to fp16 hi/lo for Wo GEMM ----
    float inv0 = 1.f / l0, inv1 = 1.f / l1;
    int b = bh >> 4, h = bh & 15;
    int r0 = s0 + warp_m + (lane >> 2);
    size_t base0 = ((size_t)b * S_ + r0) * D_ + h * 64 + (lane & 3) * 2;
    size_t base1 = base0 + 8 * D_;
    #pragma unroll
    for (int nb = 0; nb < 8; ++nb) {
        uint32_t hi, lo;
        split2h(Oacc[nb][0] * inv0, Oacc[nb][1] * inv0, hi, lo);
        *(uint32_t*)(aoh + base0 + nb * 8) = hi;
        *(uint32_t*)(aol + base0 + nb * 8) = lo;
        split2h(Oacc[nb][2] * inv1, Oacc[nb][3] * inv1, hi, lo);
        *(uint32_t*)(aoh + base1 + nb * 8) = hi;
        *(uint32_t*)(aol + base1 + nb * 8) = lo;
    }
}

// ---------------- launch ----------------
extern "C" void kernel_launch(void* const* d_in, const int* in_sizes, int n_in,
                              void* d_out, int out_size) {
    const float* query = (const float*)d_in[0];
    const float* key   = (const float*)d_in[1];
    const float* value = (const float*)d_in[2];
    const float* Wq    = (const float*)d_in[3];
    const float* Wk    = (const float*)d_in[4];
    const float* Wv    = (const float*)d_in[5];
    const float* Wo    = (const float*)d_in[6];
    float* out = (float*)d_out;

    __half *afq, *afk, *afv, *w16, *wo16, *qf, *kf, *vf, *aoh, *aol;
    cudaGetSymbolAddress((void**)&afq,  g_afq);
    cudaGetSymbolAddress((void**)&afk,  g_afk);
    cudaGetSymbolAddress((void**)&afv,  g_afv);
    cudaGetSymbolAddress((void**)&w16,  g_w16);
    cudaGetSymbolAddress((void**)&wo16, g_wo16);
    cudaGetSymbolAddress((void**)&qf,   g_qf);
    cudaGetSymbolAddress((void**)&kf,   g_kf);
    cudaGetSymbolAddress((void**)&vf,   g_vf);
    cudaGetSymbolAddress((void**)&aoh,  g_aoh);
    cudaGetSymbolAddress((void**)&aol,  g_aol);

    cudaFuncSetAttribute((const void*)gemm_qkv, cudaFuncAttributeMaxDynamicSharedMemorySize, G1SMEM);
    cudaFuncSetAttribute((const void*)gemm_wo, cudaFuncAttributeMaxDynamicSharedMemorySize, WSMEM);
    cudaFuncSetAttribute((const void*)flash_fp16, cudaFuncAttributeMaxDynamicSharedMemorySize, FLASH_SMEM);

    rearrange_w<<<(D_ * D_ + 255) / 256, 256>>>(Wq, Wk, Wv, Wo);

    int cvtBlocks = (M_ * D_ / 4) / 256;

    conv_fp16_3<<<dim3(cvtBlocks, 3), 256>>>(query, key, value, afq, afk, afv);
    gemm_qkv<<<dim3(8, 128, 3), 256, G1SMEM>>>(afq, afk, afv, w16, qf, kf, vf);

    flash_fp16<<<dim3(S_ / 128, B_ * H_), 256, FLASH_SMEM>>>(qf, kf, vf, aoh, aol);

    gemm_wo<<<dim3(8, 128), 256, WSMEM>>>(aoh, aol, wo16, out);
}

// round 12
// speedup vs baseline: 8.4357x; 1.0406x over previous
#include <cuda_runtime.h>
#include <cuda_bf16.h>
#include <cuda_fp16.h>
#include <stdint.h>
#include <math.h>

#define B_  8
#define S_  2048
#define D_  1024
#define H_  16
#define DK_ 64
#define M_  (B_*S_)   // 16384

// ---------------- scratch (device globals: allocation-free) ----------------
__device__ __half g_afq[M_ * D_];
__device__ __half g_afk[M_ * D_];
__device__ __half g_afv[M_ * D_];
__device__ __half g_w16[3 * D_ * D_];        // fp16 weights [N][K]: q, k, v
__device__ __half g_wo16[D_ * D_];           // fp16 Wo [N][K]
__device__ __half g_qf[M_ * D_];             // head-major fp16 q (log2e/32 folded)
__device__ __half g_kf[M_ * D_];
__device__ __half g_vf[M_ * D_];
__device__ __half g_aoh[M_ * D_];            // attention out fp16 hi/lo (feeds Wo)
__device__ __half g_aol[M_ * D_];

// ---------------- helpers ----------------
__device__ __forceinline__ uint32_t smem_u32(const void* p) {
    return (uint32_t)__cvta_generic_to_shared(p);
}
__device__ __forceinline__ void cpasync16(uint32_t s, const void* g) {
    asm volatile("cp.async.cg.shared.global [%0], [%1], 16;" :: "r"(s), "l"(g));
}
__device__ __forceinline__ void cp_commit() {
    asm volatile("cp.async.commit_group;" ::: "memory");
}
template<int N> __device__ __forceinline__ void cp_wait() {
    asm volatile("cp.async.wait_group %0;" :: "n"(N) : "memory");
}
__device__ __forceinline__ void ldsm_x4(uint32_t* r, uint32_t a) {
    asm volatile("ldmatrix.sync.aligned.m8n8.x4.shared.b16 {%0,%1,%2,%3}, [%4];"
                 : "=r"(r[0]), "=r"(r[1]), "=r"(r[2]), "=r"(r[3]) : "r"(a));
}
__device__ __forceinline__ void ldsm_x4_t(uint32_t* r, uint32_t a) {
    asm volatile("ldmatrix.sync.aligned.m8n8.x4.trans.shared.b16 {%0,%1,%2,%3}, [%4];"
                 : "=r"(r[0]), "=r"(r[1]), "=r"(r[2]), "=r"(r[3]) : "r"(a));
}
__device__ __forceinline__ void ldsm_x2(uint32_t* r, uint32_t a) {
    asm volatile("ldmatrix.sync.aligned.m8n8.x2.shared.b16 {%0,%1}, [%2];"
                 : "=r"(r[0]), "=r"(r[1]) : "r"(a));
}
__device__ __forceinline__ void mma16816h(float* d, const uint32_t* a, const uint32_t* b) {
    asm volatile(
        "mma.sync.aligned.m16n8k16.row.col.f32.f16.f16.f32 "
        "{%0,%1,%2,%3}, {%4,%5,%6,%7}, {%8,%9}, {%0,%1,%2,%3};"
        : "+f"(d[0]), "+f"(d[1]), "+f"(d[2]), "+f"(d[3])
        : "r"(a[0]), "r"(a[1]), "r"(a[2]), "r"(a[3]), "r"(b[0]), "r"(b[1]));
}
__device__ __forceinline__ float fexp2(float x) {
    float y; asm("ex2.approx.f32 %0, %1;" : "=f"(y) : "f"(x)); return y;
}
// pack two fp32 to half2, then exp2 in f16x2 (fused exp+pack)
__device__ __forceinline__ uint32_t hexp2_2(float x, float y) {
    __half2 a = __floats2half2_rn(x, y);
    uint32_t in = *reinterpret_cast<uint32_t*>(&a), out;
    asm("ex2.approx.f16x2 %0, %1;" : "=r"(out) : "r"(in));
    return out;
}
__device__ __forceinline__ uint32_t pkh2(float x, float y) {
    __half2 h2 = __floats2half2_rn(x, y);
    return *reinterpret_cast<uint32_t*>(&h2);
}
__device__ __forceinline__ void split2h(float x, float y, uint32_t& hi, uint32_t& lo) {
    __half2 h2 = __floats2half2_rn(x, y);
    float lx = x - __half2float(__low2half(h2));
    float ly = y - __half2float(__high2half(h2));
    __half2 l2 = __floats2half2_rn(lx, ly);
    hi = *reinterpret_cast<uint32_t*>(&h2);
    lo = *reinterpret_cast<uint32_t*>(&l2);
}

// 128B rows, 8x16B chunks, swizzle chunk' = chunk ^ (row & 7)
#define FOFF(r, c) ((uint32_t)((r) * 128 + ((((c) ^ ((r) & 7))) << 4)))

// q scale: d_model^-0.5 * log2(e) -> softmax in exp2 domain
#define QSCALE 0.04508422f

// ---------------- weight rearrange (all fp16) ----------------
__global__ void rearrange_w(const float* __restrict__ Wq, const float* __restrict__ Wk,
                            const float* __restrict__ Wv, const float* __restrict__ Wo) {
    int idx = blockIdx.x * blockDim.x + threadIdx.x;
    if (idx >= D_ * D_) return;
    int n = idx / D_;
    int k = idx % D_;
    int h = n >> 6, dk = n & 63;
    size_t src = ((size_t)h * D_ + k) * DK_ + dk;
    g_w16[idx]               = __float2half(Wq[src]);
    g_w16[D_ * D_ + idx]     = __float2half(Wk[src]);
    g_w16[2 * D_ * D_ + idx] = __float2half(Wv[src]);
    g_wo16[idx]              = __float2half(Wo[(size_t)n * D_ + k]);
}

// ---------------- activation convert (grid.y = 3: q, k, v) ----------------
__global__ void conv_fp16_3(const float* __restrict__ x0, const float* __restrict__ x1,
                            const float* __restrict__ x2,
                            __half* __restrict__ o0, __half* __restrict__ o1,
                            __half* __restrict__ o2) {
    int i = blockIdx.x * blockDim.x + threadIdx.x;
    const float* x = blockIdx.y == 0 ? x0 : (blockIdx.y == 1 ? x1 : x2);
    __half* o = blockIdx.y == 0 ? o0 : (blockIdx.y == 1 ? o1 : o2);
    float4 v = ((const float4*)x)[i];
    ((uint2*)o)[i] = make_uint2(pkh2(v.x, v.y), pkh2(v.z, v.w));
}

// ---------------- fp16 1-term GEMM, fused Q+K+V (grid.z = 3) ----------------
#define G1TILE 16384
#define G1STG  (2 * G1TILE)
#define G1SMEM (3 * G1STG)   // 96KB, 2 CTAs/SM

__global__ __launch_bounds__(256, 2)
void gemm_qkv(const __half* __restrict__ Aq, const __half* __restrict__ Ak,
              const __half* __restrict__ Av, const __half* __restrict__ W,
              __half* __restrict__ Cq, __half* __restrict__ Ck, __half* __restrict__ Cv) {
    extern __shared__ char smraw[];
    const uint32_t sb = smem_u32(smraw);
    const int z = blockIdx.z;
    const __half* A  = z == 0 ? Aq : (z == 1 ? Ak : Av);
    const __half* Bw = W + (size_t)z * D_ * D_;
    __half* Co = z == 0 ? Cq : (z == 1 ? Ck : Cv);
    const float scale = z == 0 ? QSCALE : 1.0f;

    const int tid = threadIdx.x;
    const int wid = tid >> 5, lane = tid & 31;
    const int bm = blockIdx.y * 128;
    const int bn = blockIdx.x * 128;
    const int warp_m = (wid & 1) * 64;
    const int warp_n = (wid >> 1) * 32;

    uint32_t soff[4];
    const __half *pA[4], *pB[4];
    #pragma unroll
    for (int i = 0; i < 4; ++i) {
        int lin = i * 256 + tid;
        int row = lin >> 3, c = lin & 7;
        soff[i] = FOFF(row, c);
        pA[i] = A  + (size_t)(bm + row) * D_ + c * 8;
        pB[i] = Bw + (size_t)(bn + row) * D_ + c * 8;
    }
    auto prefetch = [&](int t) {
        uint32_t stg = sb + (t % 3) * G1STG;
        int kofs = t * 64;
        #pragma unroll
        for (int i = 0; i < 4; ++i) {
            cpasync16(stg + soff[i],          pA[i] + kofs);
            cpasync16(stg + G1TILE + soff[i], pB[i] + kofs);
        }
    };
    prefetch(0); cp_commit();
    prefetch(1); cp_commit();

    const int arow = warp_m + (lane & 15);
    const int brow = warp_n + (lane & 7);
    float acc[4][4][4] = {};

    const int NT = D_ / 64;   // 16
    for (int t = 0; t < NT; ++t) {
        if (t == NT - 1) cp_wait<0>(); else cp_wait<1>();
        __syncthreads();
        if (t + 2 < NT) { prefetch(t + 2); cp_commit(); }
        uint32_t stg = sb + (t % 3) * G1STG;

        #pragma unroll
        for (int kk = 0; kk < 4; ++kk) {
            uint32_t ao = FOFF(arow, kk * 2 + (lane >> 4));
            uint32_t bo = FOFF(brow, kk * 2 + ((lane >> 3) & 1));
            uint32_t a4[4][4], b2[4][2];
            #pragma unroll
            for (int mb = 0; mb < 4; ++mb)
                ldsm_x4(a4[mb], stg + ao + mb * 2048);
            #pragma unroll
            for (int nb = 0; nb < 4; ++nb)
                ldsm_x2(b2[nb], stg + G1TILE + bo + nb * 1024);
            #pragma unroll
            for (int mb = 0; mb < 4; ++mb)
                #pragma unroll
                for (int nb = 0; nb < 4; ++nb)
                    mma16816h(acc[mb][nb], a4[mb], b2[nb]);
        }
    }

    const int tm = bm + warp_m + (lane >> 2);
    const int tn = bn + warp_n + (lane & 3) * 2;
    #pragma unroll
    for (int mb = 0; mb < 4; ++mb)
        #pragma unroll
        for (int nb = 0; nb < 4; ++nb) {
            int n = tn + nb * 8;
            int h = n >> 6, dk = n & 63;
            #pragma unroll
            for (int hh = 0; hh < 2; ++hh) {
                int row = tm + mb * 16 + hh * 8;
                int b = row >> 11, s = row & 2047;
                size_t idx = (((size_t)b * H_ + h) * S_ + s) * 64 + dk;
                *(uint32_t*)(Co + idx) = pkh2(acc[mb][nb][hh * 2] * scale,
                                              acc[mb][nb][hh * 2 + 1] * scale);
            }
        }
}

// ---------------- fp16 2-term GEMM for Wo (2-stage, 2 CTAs/SM) ----------------
#define WTILE 16384
#define WSTG  (3 * WTILE)      // Ah, Al, B = 48KB
#define WSMEM (2 * WSTG)       // 96KB

__global__ __launch_bounds__(256, 2)
void gemm_wo(const __half* __restrict__ Ah, const __half* __restrict__ Al,
             const __half* __restrict__ Bw, float* __restrict__ Cf) {
    extern __shared__ char smraw[];
    const uint32_t sb = smem_u32(smraw);
    const int tid = threadIdx.x;
    const int wid = tid >> 5, lane = tid & 31;
    const int bm = blockIdx.y * 128;
    const int bn = blockIdx.x * 128;
    const int warp_m = (wid & 1) * 64;
    const int warp_n = (wid >> 1) * 32;

    uint32_t soff[4];
    const __half *pA[4], *pAl[4], *pB[4];
    #pragma unroll
    for (int i = 0; i < 4; ++i) {
        int lin = i * 256 + tid;
        int row = lin >> 3, c = lin & 7;
        soff[i] = FOFF(row, c);
        pA[i]  = Ah + (size_t)(bm + row) * D_ + c * 8;
        pAl[i] = Al + (size_t)(bm + row) * D_ + c * 8;
        pB[i]  = Bw + (size_t)(bn + row) * D_ + c * 8;
    }
    auto prefetch = [&](int t) {
        uint32_t stg = sb + (t & 1) * WSTG;
        int kofs = t * 64;
        #pragma unroll
        for (int i = 0; i < 4; ++i) {
            cpasync16(stg + soff[i],             pA[i]  + kofs);
            cpasync16(stg + WTILE + soff[i],     pAl[i] + kofs);
            cpasync16(stg + 2 * WTILE + soff[i], pB[i]  + kofs);
        }
    };
    prefetch(0); cp_commit();

    const int arow = warp_m + (lane & 15);
    const int brow = warp_n + (lane & 7);
    float acc[4][4][4] = {};

    const int NT = D_ / 64;   // 16
    for (int t = 0; t < NT; ++t) {
        cp_wait<0>();
        __syncthreads();
        if (t + 1 < NT) { prefetch(t + 1); cp_commit(); }
        uint32_t stg = sb + (t & 1) * WSTG;

        #pragma unroll
        for (int kk = 0; kk < 4; ++kk) {
            uint32_t ao = FOFF(arow, kk * 2 + (lane >> 4));
            uint32_t bo = FOFF(brow, kk * 2 + ((lane >> 3) & 1));
            uint32_t ah4[4][4], al4[4][4], b2[4][2];
            #pragma unroll
            for (int mb = 0; mb < 4; ++mb) {
                ldsm_x4(ah4[mb], stg + ao + mb * 2048);
                ldsm_x4(al4[mb], stg + WTILE + ao + mb * 2048);
            }
            #pragma unroll
            for (int nb = 0; nb < 4; ++nb)
                ldsm_x2(b2[nb], stg + 2 * WTILE + bo + nb * 1024);
            #pragma unroll
            for (int mb = 0; mb < 4; ++mb)
                #pragma unroll
                for (int nb = 0; nb < 4; ++nb)
                    mma16816h(acc[mb][nb], ah4[mb], b2[nb]);
            #pragma unroll
            for (int mb = 0; mb < 4; ++mb)
                #pragma unroll
                for (int nb = 0; nb < 4; ++nb)
                    mma16816h(acc[mb][nb], al4[mb], b2[nb]);
        }
        __syncthreads();
    }

    const int tm = bm + warp_m + (lane >> 2);
    const int tn = bn + warp_n + (lane & 3) * 2;
    #pragma unroll
    for (int mb = 0; mb < 4; ++mb)
        #pragma unroll
        for (int nb = 0; nb < 4; ++nb) {
            float* c0 = Cf + (size_t)(tm + mb * 16) * D_ + tn + nb * 8;
            *(float2*)c0 = make_float2(acc[mb][nb][0], acc[mb][nb][1]);
            float* c1 = c0 + 8 * D_;
            *(float2*)c1 = make_float2(acc[mb][nb][2], acc[mb][nb][3]);
        }
}

// ---------------- flash attention fp16 (issue-minimized softmax) ----------------
// smem: Q 16K + 3 KV stages of 16K (K 8K, V 8K) = 64K -> 2 CTAs/SM
#define KVSTG 16384
#define FLASH_SMEM (16384 + 3 * KVSTG)

__global__ __launch_bounds__(256, 2)
void flash_fp16(const __half* __restrict__ qf, const __half* __restrict__ kf,
                const __half* __restrict__ vf,
                __half* __restrict__ aoh, __half* __restrict__ aol) {
    extern __shared__ char smraw[];
    const uint32_t sb = smem_u32(smraw);
    const int tid = threadIdx.x;
    const int wid = tid >> 5, lane = tid & 31;
    const int bh = blockIdx.y;
    const int s0 = blockIdx.x * 128;

    const size_t hb = (size_t)bh * S_ * 64;
    const __half* qp = qf + hb + (size_t)s0 * 64;
    const __half* kp = kf + hb;
    const __half* vp = vf + hb;

    #pragma unroll
    for (int i = 0; i < 4; ++i) {
        int lin = i * 256 + tid;
        int r = lin >> 3, c = lin & 7;
        cpasync16(sb + FOFF(r, c), qp + r * 64 + c * 8);
    }
    auto kvload = [&](int t) {
        uint32_t stg = sb + 16384 + (t % 3) * KVSTG;
        size_t tofs = (size_t)(t * 64) * 64;
        #pragma unroll
        for (int i = 0; i < 2; ++i) {
            int lin = i * 256 + tid;
            int r = lin >> 3, c = lin & 7;
            uint32_t o = FOFF(r, c);
            size_t g = tofs + r * 64 + c * 8;
            cpasync16(stg + o,        kp + g);
            cpasync16(stg + 8192 + o, vp + g);
        }
    };
    kvload(0); cp_commit();
    kvload(1); cp_commit();

    const int warp_m = wid * 16;
    uint32_t qfr[4][4];
    float Oacc[8][4] = {};
    float lacc[4] = {};                      // row sums via ones-MMA (replicated over quad)
    float m0 = -1e30f, m1 = -1e30f;
    const uint32_t ones2[2] = {0x3C003C00u, 0x3C003C00u};   // fp16 (1,1),(1,1)

    const int NT = S_ / 64;   // 32
    for (int t = 0; t < NT; ++t) {
        if (t == NT - 1) cp_wait<0>(); else cp_wait<1>();
        __syncthreads();
        if (t + 2 < NT) { kvload(t + 2); cp_commit(); }
        uint32_t stg = sb + 16384 + (t % 3) * KVSTG;

        if (t == 0) {
            #pragma unroll
            for (int kb = 0; kb < 4; ++kb) {
                int r = warp_m + (lane & 15);
                int c = kb * 2 + (lane >> 4);
                ldsm_x4(qfr[kb], sb + FOFF(r, c));
            }
        }

        // ---- S = Q K^T (fp16, 1 term), log2 domain ----
        float sacc[8][4] = {};
        #pragma unroll
        for (int kb = 0; kb < 4; ++kb) {
            #pragma unroll
            for (int nbp = 0; nbp < 4; ++nbp) {
                int r = nbp * 16 + ((lane >> 4) << 3) + (lane & 7);
                int c = kb * 2 + ((lane >> 3) & 1);
                uint32_t khf[4];
                ldsm_x4(khf, stg + FOFF(r, c));
                mma16816h(sacc[2 * nbp],     qfr[kb], khf);
                mma16816h(sacc[2 * nbp + 1], qfr[kb], khf + 2);
            }
        }

        // ---- row max ----
        float mx0 = -1e30f, mx1 = -1e30f;
        #pragma unroll
        for (int nb = 0; nb < 8; ++nb) {
            mx0 = fmaxf(mx0, fmaxf(sacc[nb][0], sacc[nb][1]));
            mx1 = fmaxf(mx1, fmaxf(sacc[nb][2], sacc[nb][3]));
        }
        mx0 = fmaxf(mx0, __shfl_xor_sync(0xffffffffu, mx0, 1));
        mx0 = fmaxf(mx0, __shfl_xor_sync(0xffffffffu, mx0, 2));
        mx1 = fmaxf(mx1, __shfl_xor_sync(0xffffffffu, mx1, 1));
        mx1 = fmaxf(mx1, __shfl_xor_sync(0xffffffffu, mx1, 2));
        float mn0 = fmaxf(m0, mx0), mn1 = fmaxf(m1, mx1);

        // ---- rescale O/l only when max advanced (warp vote) ----
        if (__any_sync(0xffffffffu, (mn0 > m0) | (mn1 > m1))) {
            float c0 = fexp2(m0 - mn0), c1 = fexp2(m1 - mn1);
            #pragma unroll
            for (int nb = 0; nb < 8; ++nb) {
                Oacc[nb][0] *= c0; Oacc[nb][1] *= c0;
                Oacc[nb][2] *= c1; Oacc[nb][3] *= c1;
            }
            lacc[0] *= c0; lacc[1] *= c0;
            lacc[2] *= c1; lacc[3] *= c1;
            m0 = mn0; m1 = mn1;
        }

        // ---- per-kb: fused exp2+pack (f16x2) -> ones-MMA row sums -> PV ----
        #pragma unroll
        for (int kb = 0; kb < 4; ++kb) {
            uint32_t ph[4];
            ph[0] = hexp2_2(sacc[2 * kb][0] - m0,     sacc[2 * kb][1] - m0);
            ph[1] = hexp2_2(sacc[2 * kb][2] - m1,     sacc[2 * kb][3] - m1);
            ph[2] = hexp2_2(sacc[2 * kb + 1][0] - m0, sacc[2 * kb + 1][1] - m0);
            ph[3] = hexp2_2(sacc[2 * kb + 1][2] - m1, sacc[2 * kb + 1][3] - m1);
            mma16816h(lacc, ph, ones2);   // l += row-sum of P (tensor-core)
            #pragma unroll
            for (int nbp = 0; nbp < 4; ++nbp) {
                int r = kb * 16 + (((lane >> 3) & 1) << 3) + (lane & 7);
                int c = nbp * 2 + (lane >> 4);
                uint32_t vfr[4];
                ldsm_x4_t(vfr, stg + 8192 + FOFF(r, c));
                mma16816h(Oacc[2 * nbp],     ph, vfr);
                mma16816h(Oacc[2 * nbp + 1], ph, vfr + 2);
            }
        }
    }

    // ---- epilogue: normalize, split to fp16 hi/lo for Wo GEMM ----
    // lacc[0]/lacc[2] hold full row sums (replicated across the quad's columns)
    float inv0 = 1.f / lacc[0], inv1 = 1.f / lacc[2];
    int b = bh >> 4, h = bh & 15;
    int r0 = s0 + warp_m + (lane >> 2);
    size_t base0 = ((size_t)b * S_ + r0) * D_ + h * 64 + (lane & 3) * 2;
    size_t base1 = base0 + 8 * D_;
    #pragma unroll
    for (int nb = 0; nb < 8; ++nb) {
        uint32_t hi, lo;
        split2h(Oacc[nb][0] * inv0, Oacc[nb][1] * inv0, hi, lo);
        *(uint32_t*)(aoh + base0 + nb * 8) = hi;
        *(uint32_t*)(aol + base0 + nb * 8) = lo;
        split2h(Oacc[nb][2] * inv1, Oacc[nb][3] * inv1, hi, lo);
        *(uint32_t*)(aoh + base1 + nb * 8) = hi;
        *(uint32_t*)(aol + base1 + nb * 8) = lo;
    }
}

// ---------------- launch ----------------
extern "C" void kernel_launch(void* const* d_in, const int* in_sizes, int n_in,
                              void* d_out, int out_size) {
    const float* query = (const float*)d_in[0];
    const float* key   = (const float*)d_in[1];
    const float* value = (const float*)d_in[2];
    const float* Wq    = (const float*)d_in[3];
    const float* Wk    = (const float*)d_in[4];
    const float* Wv    = (const float*)d_in[5];
    const float* Wo    = (const float*)d_in[6];
    float* out = (float*)d_out;

    __half *afq, *afk, *afv, *w16, *wo16, *qf, *kf, *vf, *aoh, *aol;
    cudaGetSymbolAddress((void**)&afq,  g_afq);
    cudaGetSymbolAddress((void**)&afk,  g_afk);
    cudaGetSymbolAddress((void**)&afv,  g_afv);
    cudaGetSymbolAddress((void**)&w16,  g_w16);
    cudaGetSymbolAddress((void**)&wo16, g_wo16);
    cudaGetSymbolAddress((void**)&qf,   g_qf);
    cudaGetSymbolAddress((void**)&kf,   g_kf);
    cudaGetSymbolAddress((void**)&vf,   g_vf);
    cudaGetSymbolAddress((void**)&aoh,  g_aoh);
    cudaGetSymbolAddress((void**)&aol,  g_aol);

    cudaFuncSetAttribute((const void*)gemm_qkv, cudaFuncAttributeMaxDynamicSharedMemorySize, G1SMEM);
    cudaFuncSetAttribute((const void*)gemm_wo, cudaFuncAttributeMaxDynamicSharedMemorySize, WSMEM);
    cudaFuncSetAttribute((const void*)flash_fp16, cudaFuncAttributeMaxDynamicSharedMemorySize, FLASH_SMEM);

    rearrange_w<<<(D_ * D_ + 255) / 256, 256>>>(Wq, Wk, Wv, Wo);

    int cvtBlocks = (M_ * D_ / 4) / 256;

    conv_fp16_3<<<dim3(cvtBlocks, 3), 256>>>(query, key, value, afq, afk, afv);
    gemm_qkv<<<dim3(8, 128, 3), 256, G1SMEM>>>(afq, afk, afv, w16, qf, kf, vf);

    flash_fp16<<<dim3(S_ / 128, B_ * H_), 256, FLASH_SMEM>>>(qf, kf, vf, aoh, aol);

    gemm_wo<<<dim3(8, 128), 256, WSMEM>>>(aoh, aol, wo16, out);
}